// round 5
// baseline (speedup 1.0000x reference)
#include <cuda_runtime.h>
#include <cuda_bf16.h>

// Problem constants
#define NN_NODES 4096
#define NN_EDGES 8192
#define DIM_V    512
#define DIM_OUT  512
#define DIM_E    128

// ---------------- scratch (device globals; no allocation allowed) ----------------
__device__ float g_e_scale[NN_EDGES];
__device__ float g_HW[(size_t)NN_NODES * DIM_OUT];                //  8 MB fp32
__device__ __nv_bfloat16 g_Ah[(size_t)NN_NODES * NN_EDGES];       // 64 MB
__device__ __nv_bfloat16 g_Al[(size_t)NN_NODES * NN_EDGES];       // 64 MB
__device__ __nv_bfloat16 g_Bh[(size_t)NN_NODES * NN_EDGES];       // 64 MB
__device__ __nv_bfloat16 g_Bl[(size_t)NN_NODES * NN_EDGES];       // 64 MB
__device__ __nv_bfloat16 g_Ch[(size_t)NN_NODES * NN_NODES];       // 32 MB (A_comb hi)
__device__ __nv_bfloat16 g_Cl[(size_t)NN_NODES * NN_NODES];       // 32 MB (A_comb lo)
__device__ __nv_bfloat16 g_HWth[(size_t)DIM_OUT * NN_NODES];      //  4 MB (HW^T hi)
__device__ __nv_bfloat16 g_HWtl[(size_t)DIM_OUT * NN_NODES];      //  4 MB (HW^T lo)

// ---------------- PTX helpers (non-'a' features only) ----------------
__device__ __forceinline__ unsigned smem_u32(const void* p) {
    unsigned a;
    asm("{ .reg .u64 t; cvta.to.shared.u64 t, %1; cvt.u32.u64 %0, t; }" : "=r"(a) : "l"(p));
    return a;
}
#define CP_ASYNC16(dst, src) \
    asm volatile("cp.async.cg.shared.global [%0], [%1], 16;" :: "r"(dst), "l"(src) : "memory")
#define CP_COMMIT() asm volatile("cp.async.commit_group;" ::: "memory")
#define CP_WAIT(n)  asm volatile("cp.async.wait_group %0;" :: "n"(n) : "memory")

#define LDSM4(r, addr) \
    asm volatile("ldmatrix.sync.aligned.m8n8.x4.shared.b16 {%0,%1,%2,%3}, [%4];" \
                 : "=r"((r)[0]), "=r"((r)[1]), "=r"((r)[2]), "=r"((r)[3]) : "r"(addr))

#define MMA_BF16(acc, A, B) \
    asm volatile("mma.sync.aligned.m16n8k16.row.col.f32.bf16.bf16.f32 " \
                 "{%0,%1,%2,%3},{%4,%5,%6,%7},{%8,%9},{%0,%1,%2,%3};" \
                 : "+f"((acc)[0]), "+f"((acc)[1]), "+f"((acc)[2]), "+f"((acc)[3]) \
                 : "r"((A)[0]), "r"((A)[1]), "r"((A)[2]), "r"((A)[3]), \
                   "r"((B)[0]), "r"((B)[1]))

// ---------------- packed f32x2 helpers (SIMT GEMM) ----------------
__device__ __forceinline__ void ffma2(unsigned long long& d,
                                      unsigned long long a,
                                      unsigned long long b) {
    asm("fma.rn.f32x2 %0, %1, %2, %0;" : "+l"(d) : "l"(a), "l"(b));
}
__device__ __forceinline__ unsigned long long pack2(float x, float y) {
    unsigned long long r;
    asm("mov.b64 %0, {%1, %2};" : "=l"(r) : "f"(x), "f"(y));
    return r;
}
__device__ __forceinline__ float2 unpack2(unsigned long long v) {
    float2 f;
    asm("mov.b64 {%0, %1}, %2;" : "=f"(f.x), "=f"(f.y) : "l"(v));
    return f;
}
__device__ __forceinline__ unsigned pack_bf16(float x, float y) {
    return (unsigned)__bfloat16_as_ushort(__float2bfloat16(x)) |
           ((unsigned)__bfloat16_as_ushort(__float2bfloat16(y)) << 16);
}

// ---------------- K0: e_scale[e] = dot(H_e[e,:], p) ----------------
__global__ void escale_kernel(const float* __restrict__ He,
                              const float* __restrict__ p) {
    int row  = blockIdx.x * 8 + threadIdx.y;
    int lane = threadIdx.x;
    float4 h  = ((const float4*)(He + (size_t)row * DIM_E))[lane];
    float4 pv = ((const float4*)p)[lane];
    float v = h.x * pv.x + h.y * pv.y + h.z * pv.z + h.w * pv.w;
    #pragma unroll
    for (int o = 16; o; o >>= 1) v += __shfl_xor_sync(0xffffffffu, v, o);
    if (lane == 0) g_e_scale[row] = v;
}

// ---------------- K-split: T -> (Bh,Bl), T*e -> (Ah,Al) bf16 hi/lo ----------------
__global__ __launch_bounds__(256) void split_kernel(const float* __restrict__ T) {
    size_t i = ((size_t)blockIdx.x * 256 + threadIdx.x) * 4;
    unsigned col = (unsigned)(i & (NN_EDGES - 1));
    float4 t = *(const float4*)(T + i);
    float4 e = *(const float4*)(g_e_scale + col);

    float b[4] = {t.x, t.y, t.z, t.w};
    float a[4] = {t.x * e.x, t.y * e.y, t.z * e.z, t.w * e.w};

    unsigned long long bh = 0, bl = 0, ah = 0, al = 0;
    #pragma unroll
    for (int k = 0; k < 4; ++k) {
        __nv_bfloat16 h = __float2bfloat16(b[k]);
        __nv_bfloat16 l = __float2bfloat16(b[k] - __bfloat162float(h));
        bh |= (unsigned long long)__bfloat16_as_ushort(h) << (16 * k);
        bl |= (unsigned long long)__bfloat16_as_ushort(l) << (16 * k);
        h = __float2bfloat16(a[k]);
        l = __float2bfloat16(a[k] - __bfloat162float(h));
        ah |= (unsigned long long)__bfloat16_as_ushort(h) << (16 * k);
        al |= (unsigned long long)__bfloat16_as_ushort(l) << (16 * k);
    }
    *(unsigned long long*)(g_Bh + i) = bh;
    *(unsigned long long*)(g_Bl + i) = bl;
    *(unsigned long long*)(g_Ah + i) = ah;
    *(unsigned long long*)(g_Al + i) = al;
}

// ---------------- shared mma mainloop (split-bf16, 3 products) ----------------
// CTA tile 128x128, K-chunk 32, double-buffered cp.async, ldmatrix frag loads.
// SMEM rows padded to 80B -> every ldmatrix phase hits all 32 banks once.
#define ROWB 80u
#define TILEB (128u * ROWB)          // 10240 B
#define STAGEB (4u * TILEB)          // 40960 B
#define SMEM_G1 (2u * STAGEB)        // 81920 B
#define OFF_AH(s) ((unsigned)(s) * STAGEB)
#define OFF_AL(s) (OFF_AH(s) + TILEB)
#define OFF_BH(s) (OFF_AH(s) + 2u * TILEB)
#define OFF_BL(s) (OFF_AH(s) + 3u * TILEB)

template<int LD, int NCH>
__device__ __forceinline__ void mma_mainloop(
    const __nv_bfloat16* __restrict__ Ah, const __nv_bfloat16* __restrict__ Al,
    const __nv_bfloat16* __restrict__ Bh, const __nv_bfloat16* __restrict__ Bl,
    int iBase, int jBase, unsigned sb, float (&acc)[2][8][4]) {

    const int tid  = threadIdx.x;
    const int warp = tid >> 5;
    const int lane = tid & 31;
    const int wM = (warp >> 1) * 32;
    const int wN = (warp & 1) * 64;

    #pragma unroll
    for (int mt = 0; mt < 2; ++mt)
        #pragma unroll
        for (int nt = 0; nt < 8; ++nt)
            #pragma unroll
            for (int q = 0; q < 4; ++q) acc[mt][nt][q] = 0.0f;

    // lane-dependent ldmatrix address components
    const unsigned rowA = (unsigned)(lane & 15);
    const unsigned hiA  = (unsigned)((lane >> 4) * 16);
    const unsigned nB   = (unsigned)((lane & 7) + ((lane >> 4) << 3));
    const unsigned hiB  = (unsigned)(((lane >> 3) & 1) * 16);

    auto fill = [&](int chunk, int stg) {
        const unsigned kb = (unsigned)chunk * 32u;
        #pragma unroll
        for (int i = 0; i < 2; ++i) {
            int c = tid + i * 256;
            int row = c >> 2, seg = c & 3;              // 4x 16B segments per 64B row
            unsigned so = (unsigned)row * ROWB + (unsigned)seg * 16u;
            size_t ga = (size_t)(iBase + row) * LD + kb + seg * 8;
            size_t gb = (size_t)(jBase + row) * LD + kb + seg * 8;
            CP_ASYNC16(sb + OFF_AH(stg) + so, (const char*)(Ah + ga));
            CP_ASYNC16(sb + OFF_AL(stg) + so, (const char*)(Al + ga));
            CP_ASYNC16(sb + OFF_BH(stg) + so, (const char*)(Bh + gb));
            CP_ASYNC16(sb + OFF_BL(stg) + so, (const char*)(Bl + gb));
        }
        CP_COMMIT();
    };

    fill(0, 0);

    for (int c = 0; c < NCH; ++c) {
        const int s = c & 1;
        if (c + 1 < NCH) { fill(c + 1, s ^ 1); CP_WAIT(1); }
        else             { CP_WAIT(0); }
        __syncthreads();

        const unsigned aAH = sb + OFF_AH(s);
        const unsigned aAL = sb + OFF_AL(s);
        const unsigned aBH = sb + OFF_BH(s);
        const unsigned aBL = sb + OFF_BL(s);

        #pragma unroll
        for (int ks = 0; ks < 2; ++ks) {
            const unsigned kbyte = (unsigned)ks * 32u;
            unsigned ah[2][4], al[2][4];
            #pragma unroll
            for (int mt = 0; mt < 2; ++mt) {
                unsigned ra = (unsigned)(wM + mt * 16) + rowA;
                unsigned off = ra * ROWB + kbyte + hiA;
                LDSM4(ah[mt], aAH + off);
                LDSM4(al[mt], aAL + off);
            }
            #pragma unroll
            for (int ntp = 0; ntp < 4; ++ntp) {
                unsigned bh[4], bl[4];
                unsigned rb = (unsigned)(wN + ntp * 16) + nB;
                unsigned off = rb * ROWB + kbyte + hiB;
                LDSM4(bh, aBH + off);
                LDSM4(bl, aBL + off);
                #pragma unroll
                for (int mt = 0; mt < 2; ++mt)
                    #pragma unroll
                    for (int h = 0; h < 2; ++h) {
                        const int nt = ntp * 2 + h;
                        MMA_BF16(acc[mt][nt], ah[mt], bh + h * 2);
                        MMA_BF16(acc[mt][nt], ah[mt], bl + h * 2);
                        MMA_BF16(acc[mt][nt], al[mt], bh + h * 2);
                    }
            }
        }
        __syncthreads();
    }
}

// ---------------- K2: GEMM1 + fused epilogue -> split bf16 A_comb ----------------
__global__ __launch_bounds__(256, 2) void gemm1_mma_kernel(const float* __restrict__ adj_v) {
    extern __shared__ char sm[];
    const unsigned sb = smem_u32(sm);
    const int warp = threadIdx.x >> 5;
    const int lane = threadIdx.x & 31;
    const int g = lane >> 2, t = lane & 3;
    const int iBase = blockIdx.y * 128;
    const int jBase = blockIdx.x * 128;
    const int wM = (warp >> 1) * 32;
    const int wN = (warp & 1) * 64;

    float acc[2][8][4];
    mma_mainloop<NN_EDGES, NN_EDGES / 32>(g_Ah, g_Al, g_Bh, g_Bl, iBase, jBase, sb, acc);

    // epilogue: A_comb = (i==j) ? adj : 0.5*adj*(S+1); store bf16 hi/lo
    #pragma unroll
    for (int mt = 0; mt < 2; ++mt) {
        int gi0 = iBase + wM + mt * 16 + g;            // rows gi0 and gi0+8
        const float* adj0 = adj_v + (size_t)gi0 * NN_NODES;
        const float* adj1 = adj0 + 8u * NN_NODES;
        size_t r0 = (size_t)gi0 * NN_NODES;
        size_t r1 = r0 + 8u * NN_NODES;
        #pragma unroll
        for (int nt = 0; nt < 8; ++nt) {
            int gj = jBase + wN + nt * 8 + t * 2;
            float2 a0 = *(const float2*)(adj0 + gj);
            float2 a1 = *(const float2*)(adj1 + gj);
            float o00 = (gi0 == gj)         ? a0.x : 0.5f * a0.x * (acc[mt][nt][0] + 1.0f);
            float o01 = (gi0 == gj + 1)     ? a0.y : 0.5f * a0.y * (acc[mt][nt][1] + 1.0f);
            float o10 = (gi0 + 8 == gj)     ? a1.x : 0.5f * a1.x * (acc[mt][nt][2] + 1.0f);
            float o11 = (gi0 + 8 == gj + 1) ? a1.y : 0.5f * a1.y * (acc[mt][nt][3] + 1.0f);

            __nv_bfloat16 h00 = __float2bfloat16(o00), h01 = __float2bfloat16(o01);
            __nv_bfloat16 h10 = __float2bfloat16(o10), h11 = __float2bfloat16(o11);
            *(unsigned*)(g_Ch + r0 + gj) =
                (unsigned)__bfloat16_as_ushort(h00) | ((unsigned)__bfloat16_as_ushort(h01) << 16);
            *(unsigned*)(g_Ch + r1 + gj) =
                (unsigned)__bfloat16_as_ushort(h10) | ((unsigned)__bfloat16_as_ushort(h11) << 16);
            *(unsigned*)(g_Cl + r0 + gj) =
                pack_bf16(o00 - __bfloat162float(h00), o01 - __bfloat162float(h01));
            *(unsigned*)(g_Cl + r1 + gj) =
                pack_bf16(o10 - __bfloat162float(h10), o11 - __bfloat162float(h11));
        }
    }
}

// ---------------- K3: ret = A_comb @ HW + bias (tensorized) ----------------
__global__ __launch_bounds__(256, 2) void gemm_out_mma_kernel(
    const float* __restrict__ bias, float* __restrict__ out) {
    extern __shared__ char sm[];
    const unsigned sb = smem_u32(sm);
    const int warp = threadIdx.x >> 5;
    const int lane = threadIdx.x & 31;
    const int g = lane >> 2, t = lane & 3;
    const int iBase = blockIdx.y * 128;
    const int jBase = blockIdx.x * 128;
    const int wM = (warp >> 1) * 32;
    const int wN = (warp & 1) * 64;

    float acc[2][8][4];
    mma_mainloop<NN_NODES, NN_NODES / 32>(g_Ch, g_Cl, g_HWth, g_HWtl, iBase, jBase, sb, acc);

    #pragma unroll
    for (int mt = 0; mt < 2; ++mt) {
        int gi0 = iBase + wM + mt * 16 + g;
        float* d0 = out + (size_t)gi0 * DIM_OUT;
        float* d1 = d0 + 8u * DIM_OUT;
        #pragma unroll
        for (int nt = 0; nt < 8; ++nt) {
            int gj = jBase + wN + nt * 8 + t * 2;
            float2 bs = *(const float2*)(bias + gj);
            float2 o0 = make_float2(acc[mt][nt][0] + bs.x, acc[mt][nt][1] + bs.y);
            float2 o1 = make_float2(acc[mt][nt][2] + bs.x, acc[mt][nt][3] + bs.y);
            *(float2*)(d0 + gj) = o0;
            *(float2*)(d1 + gj) = o1;
        }
    }
}

// ---------------- SIMT NN GEMM for HW = H_v @ W ----------------
__global__ __launch_bounds__(256, 2) void gemm_hw_kernel(
    const float* __restrict__ A, const float* __restrict__ B) {
    __shared__ __align__(16) float As[2][8][128];
    __shared__ __align__(16) float Bs[2][8][128];

    const int Nn = DIM_OUT, K = DIM_V;
    const int tid = threadIdx.x;
    const int iBase = blockIdx.y * 128;
    const int jBase = blockIdx.x * 128;

    const int lrow = tid >> 1;
    const int kq   = (tid & 1) * 4;
    const float* Aptr = A + (size_t)(iBase + lrow) * K + kq;
    const int bk = tid >> 5;
    const int bn = (tid & 31) * 4;
    const float* Bptr = B + (size_t)bk * Nn + jBase + bn;

    unsigned long long acc[8][4];
    #pragma unroll
    for (int r = 0; r < 8; ++r)
        #pragma unroll
        for (int c = 0; c < 4; ++c) acc[r][c] = 0ull;

    {
        float4 a = *(const float4*)Aptr;
        float4 b = *(const float4*)Bptr;
        As[0][kq + 0][lrow] = a.x; As[0][kq + 1][lrow] = a.y;
        As[0][kq + 2][lrow] = a.z; As[0][kq + 3][lrow] = a.w;
        *(float4*)&Bs[0][bk][bn] = b;
    }
    __syncthreads();

    const int tx = (tid & 15) * 8;
    const int ty = (tid >> 4) * 8;
    int buf = 0;
    const int KT = K / 8;

    for (int kt = 0; kt < KT; ++kt) {
        float4 aN, bN;
        if (kt + 1 < KT) {
            aN = *(const float4*)(Aptr + (size_t)(kt + 1) * 8);
            bN = *(const float4*)(Bptr + (size_t)(kt + 1) * 8 * Nn);
        }
        #pragma unroll
        for (int kk = 0; kk < 8; ++kk) {
            float4 a0 = *(const float4*)&As[buf][kk][ty];
            float4 a1 = *(const float4*)&As[buf][kk][ty + 4];
            ulonglong2 b0 = *(const ulonglong2*)&Bs[buf][kk][tx];
            ulonglong2 b1 = *(const ulonglong2*)&Bs[buf][kk][tx + 4];
            float av[8] = {a0.x, a0.y, a0.z, a0.w, a1.x, a1.y, a1.z, a1.w};
            unsigned long long bv[4] = {b0.x, b0.y, b1.x, b1.y};
            #pragma unroll
            for (int r = 0; r < 8; ++r) {
                unsigned long long aa = pack2(av[r], av[r]);
                #pragma unroll
                for (int c = 0; c < 4; ++c) ffma2(acc[r][c], aa, bv[c]);
            }
        }
        if (kt + 1 < KT) {
            int nb = buf ^ 1;
            As[nb][kq + 0][lrow] = aN.x; As[nb][kq + 1][lrow] = aN.y;
            As[nb][kq + 2][lrow] = aN.z; As[nb][kq + 3][lrow] = aN.w;
            *(float4*)&Bs[nb][bk][bn] = bN;
            __syncthreads();
            buf = nb;
        }
    }

    #pragma unroll
    for (int r = 0; r < 8; ++r) {
        int gi = iBase + ty + r;
        float* dst = g_HW + (size_t)gi * Nn;
        #pragma unroll
        for (int c = 0; c < 4; ++c) {
            int gj = jBase + tx + c * 2;
            float2 v = unpack2(acc[r][c]);
            *(float2*)&dst[gj] = v;
        }
    }
}

// ---------------- transpose + split: HW [4096,512] -> HW^T hi/lo [512,4096] ----------------
__global__ void hw_transpose_split_kernel() {
    __shared__ float tile[32][33];
    const int tx = threadIdx.x, ty = threadIdx.y;
    const int nb = blockIdx.x * 32;     // n tile base (0..511)
    const int kb = blockIdx.y * 32;     // k tile base (0..4095)
    #pragma unroll
    for (int i = 0; i < 4; ++i) {
        int k = kb + ty + i * 8;
        tile[ty + i * 8][tx] = g_HW[(size_t)k * DIM_OUT + nb + tx];
    }
    __syncthreads();
    #pragma unroll
    for (int i = 0; i < 4; ++i) {
        int n = nb + ty + i * 8;
        int k = kb + tx;
        float v = tile[tx][ty + i * 8];
        __nv_bfloat16 h = __float2bfloat16(v);
        g_HWth[(size_t)n * NN_NODES + k] = h;
        g_HWtl[(size_t)n * NN_NODES + k] = __float2bfloat16(v - __bfloat162float(h));
    }
}

extern "C" void kernel_launch(void* const* d_in, const int* in_sizes, int n_in,
                              void* d_out, int out_size) {
    const float* H_v    = (const float*)d_in[0];
    const float* H_e    = (const float*)d_in[1];
    const float* adj_v  = (const float*)d_in[3];
    const float* T      = (const float*)d_in[4];
    const float* weight = (const float*)d_in[5];
    const float* p      = (const float*)d_in[6];
    const float* bias   = (const float*)d_in[7];
    float* out = (float*)d_out;
    (void)in_sizes; (void)n_in;

    cudaFuncSetAttribute(gemm1_mma_kernel,
                         cudaFuncAttributeMaxDynamicSharedMemorySize, SMEM_G1);
    cudaFuncSetAttribute(gemm_out_mma_kernel,
                         cudaFuncAttributeMaxDynamicSharedMemorySize, SMEM_G1);

    // K0: edge scaling vector
    escale_kernel<<<NN_EDGES / 8, dim3(32, 8)>>>(H_e, p);

    // K-split: bf16 hi/lo operand prep (depends on K0)
    split_kernel<<<(NN_NODES * NN_EDGES) / (256 * 4), 256>>>(T);

    // K1: HW = H_v @ W, then transpose+split for the tensorized output GEMM
    gemm_hw_kernel<<<dim3(DIM_OUT / 128, NN_NODES / 128), 256>>>(H_v, weight);
    hw_transpose_split_kernel<<<dim3(DIM_OUT / 32, NN_NODES / 32), dim3(32, 8)>>>();

    // K2: dominant GEMM (split-bf16 mma, ldmatrix) + fused A_comb split-store
    gemm1_mma_kernel<<<dim3(NN_NODES / 128, NN_NODES / 128), 256, SMEM_G1>>>(adj_v);

    // K3: ret = A_comb @ HW + bias (tensorized)
    gemm_out_mma_kernel<<<dim3(DIM_OUT / 128, NN_NODES / 128), 256, SMEM_G1>>>(bias, out);

    const size_t ret_elems = (size_t)NN_NODES * DIM_OUT;
    const size_t he_elems  = (size_t)NN_EDGES * DIM_E;
    if ((size_t)out_size >= ret_elems + he_elems) {
        cudaMemcpyAsync(out + ret_elems, H_e, he_elems * sizeof(float),
                        cudaMemcpyDeviceToDevice);
    }
}

// round 6
// speedup vs baseline: 1.1713x; 1.1713x over previous
#include <cuda_runtime.h>
#include <cuda_bf16.h>

// Problem constants
#define NN_NODES 4096
#define NN_EDGES 8192
#define DIM_V    512
#define DIM_OUT  512
#define DIM_E    128

// ---------------- scratch (device globals; no allocation allowed) ----------------
__device__ float g_e_scale[NN_EDGES];
__device__ float g_Acomb[(size_t)NN_NODES * NN_NODES];            // 64 MB fp32
__device__ float g_HW[(size_t)NN_NODES * DIM_OUT];                //  8 MB fp32
__device__ __nv_bfloat16 g_Ah[(size_t)NN_NODES * NN_EDGES];       // 64 MB
__device__ __nv_bfloat16 g_Al[(size_t)NN_NODES * NN_EDGES];       // 64 MB
__device__ __nv_bfloat16 g_Bh[(size_t)NN_NODES * NN_EDGES];       // 64 MB
__device__ __nv_bfloat16 g_Bl[(size_t)NN_NODES * NN_EDGES];       // 64 MB
__device__ __nv_bfloat16 g_Ch[(size_t)NN_NODES * NN_NODES];       // 32 MB (A_comb hi)
__device__ __nv_bfloat16 g_Cl[(size_t)NN_NODES * NN_NODES];       // 32 MB (A_comb lo)
__device__ __nv_bfloat16 g_HWth[(size_t)DIM_OUT * NN_NODES];      //  4 MB (HW^T hi)
__device__ __nv_bfloat16 g_HWtl[(size_t)DIM_OUT * NN_NODES];      //  4 MB (HW^T lo)

// ---------------- PTX helpers (non-'a' features only) ----------------
__device__ __forceinline__ unsigned smem_u32(const void* p) {
    unsigned a;
    asm("{ .reg .u64 t; cvta.to.shared.u64 t, %1; cvt.u32.u64 %0, t; }" : "=r"(a) : "l"(p));
    return a;
}
#define CP_ASYNC8(dst, src) \
    asm volatile("cp.async.ca.shared.global [%0], [%1], 8;" :: "r"(dst), "l"(src) : "memory")
#define CP_COMMIT() asm volatile("cp.async.commit_group;" ::: "memory")
#define CP_WAIT(n)  asm volatile("cp.async.wait_group %0;" :: "n"(n) : "memory")

#define MMA_BF16(acc, A, B) \
    asm volatile("mma.sync.aligned.m16n8k16.row.col.f32.bf16.bf16.f32 " \
                 "{%0,%1,%2,%3},{%4,%5,%6,%7},{%8,%9},{%0,%1,%2,%3};" \
                 : "+f"((acc)[0]), "+f"((acc)[1]), "+f"((acc)[2]), "+f"((acc)[3]) \
                 : "r"((A)[0]), "r"((A)[1]), "r"((A)[2]), "r"((A)[3]), \
                   "r"((B)[0]), "r"((B)[1]))

// ---------------- packed f32x2 helpers (SIMT GEMM) ----------------
__device__ __forceinline__ void ffma2(unsigned long long& d,
                                      unsigned long long a,
                                      unsigned long long b) {
    asm("fma.rn.f32x2 %0, %1, %2, %0;" : "+l"(d) : "l"(a), "l"(b));
}
__device__ __forceinline__ unsigned long long pack2(float x, float y) {
    unsigned long long r;
    asm("mov.b64 %0, {%1, %2};" : "=l"(r) : "f"(x), "f"(y));
    return r;
}
__device__ __forceinline__ float2 unpack2(unsigned long long v) {
    float2 f;
    asm("mov.b64 {%0, %1}, %2;" : "=f"(f.x), "=f"(f.y) : "l"(v));
    return f;
}
__device__ __forceinline__ unsigned pack_bf16(float x, float y) {
    return (unsigned)__bfloat16_as_ushort(__float2bfloat16(x)) |
           ((unsigned)__bfloat16_as_ushort(__float2bfloat16(y)) << 16);
}

// ---------------- K0: e_scale[e] = dot(H_e[e,:], p) ----------------
__global__ void escale_kernel(const float* __restrict__ He,
                              const float* __restrict__ p) {
    int row  = blockIdx.x * 8 + threadIdx.y;
    int lane = threadIdx.x;
    float4 h  = ((const float4*)(He + (size_t)row * DIM_E))[lane];
    float4 pv = ((const float4*)p)[lane];
    float v = h.x * pv.x + h.y * pv.y + h.z * pv.z + h.w * pv.w;
    #pragma unroll
    for (int o = 16; o; o >>= 1) v += __shfl_xor_sync(0xffffffffu, v, o);
    if (lane == 0) g_e_scale[row] = v;
}

// ---------------- K-split: T -> (Bh,Bl), T*e -> (Ah,Al) bf16 hi/lo ----------------
__global__ __launch_bounds__(256) void split_kernel(const float* __restrict__ T) {
    size_t i = ((size_t)blockIdx.x * 256 + threadIdx.x) * 4;
    unsigned col = (unsigned)(i & (NN_EDGES - 1));
    float4 t = *(const float4*)(T + i);
    float4 e = *(const float4*)(g_e_scale + col);

    float b[4] = {t.x, t.y, t.z, t.w};
    float a[4] = {t.x * e.x, t.y * e.y, t.z * e.z, t.w * e.w};

    unsigned long long bh = 0, bl = 0, ah = 0, al = 0;
    #pragma unroll
    for (int k = 0; k < 4; ++k) {
        __nv_bfloat16 h = __float2bfloat16(b[k]);
        __nv_bfloat16 l = __float2bfloat16(b[k] - __bfloat162float(h));
        bh |= (unsigned long long)__bfloat16_as_ushort(h) << (16 * k);
        bl |= (unsigned long long)__bfloat16_as_ushort(l) << (16 * k);
        h = __float2bfloat16(a[k]);
        l = __float2bfloat16(a[k] - __bfloat162float(h));
        ah |= (unsigned long long)__bfloat16_as_ushort(h) << (16 * k);
        al |= (unsigned long long)__bfloat16_as_ushort(l) << (16 * k);
    }
    *(unsigned long long*)(g_Bh + i) = bh;
    *(unsigned long long*)(g_Bl + i) = bl;
    *(unsigned long long*)(g_Ah + i) = ah;
    *(unsigned long long*)(g_Al + i) = al;
}

// ---------------- shared mma mainloop (R4-proven: scalar LDS, 72B rows) ----------------
// CTA tile 128x128, K-chunk 32, double-buffered cp.async (8B, .ca).
#define ROWB 72u                     // bytes per smem row (64 data + 8 pad)
#define TILEB (128u * ROWB)          // 9216 B per tile
#define STAGEB (4u * TILEB)          // 36864 B per stage (Ah,Al,Bh,Bl)
#define SMEM_G1 (2u * STAGEB)        // 73728 B
#define OFF_AH(s) ((unsigned)(s) * STAGEB)
#define OFF_AL(s) (OFF_AH(s) + TILEB)
#define OFF_BH(s) (OFF_AH(s) + 2u * TILEB)
#define OFF_BL(s) (OFF_AH(s) + 3u * TILEB)

template<int LD, int NCH>
__device__ __forceinline__ void mma_mainloop(
    const __nv_bfloat16* __restrict__ Ahp, const __nv_bfloat16* __restrict__ Alp,
    const __nv_bfloat16* __restrict__ Bhp, const __nv_bfloat16* __restrict__ Blp,
    int iBase, int jBase, char* sm, unsigned sb, float (&acc)[2][8][4]) {

    const int tid  = threadIdx.x;
    const int warp = tid >> 5;
    const int lane = tid & 31;
    const int g = lane >> 2, t = lane & 3;
    const int wM = (warp >> 1) * 32;
    const int wN = (warp & 1) * 64;

    #pragma unroll
    for (int mt = 0; mt < 2; ++mt)
        #pragma unroll
        for (int nt = 0; nt < 8; ++nt)
            #pragma unroll
            for (int q = 0; q < 4; ++q) acc[mt][nt][q] = 0.0f;

    auto fill = [&](int chunk, int stg) {
        const unsigned kb = (unsigned)chunk * 32u;
        #pragma unroll
        for (int i = 0; i < 4; ++i) {
            int c = tid + i * 256;
            int row = c >> 3, sub = c & 7;          // 8x 8B segments per 64B row
            unsigned so = (unsigned)row * ROWB + (unsigned)sub * 8u;
            size_t ga = (size_t)(iBase + row) * LD + kb + sub * 4;
            size_t gb = (size_t)(jBase + row) * LD + kb + sub * 4;
            CP_ASYNC8(sb + OFF_AH(stg) + so, (const char*)(Ahp + ga));
            CP_ASYNC8(sb + OFF_AL(stg) + so, (const char*)(Alp + ga));
            CP_ASYNC8(sb + OFF_BH(stg) + so, (const char*)(Bhp + gb));
            CP_ASYNC8(sb + OFF_BL(stg) + so, (const char*)(Blp + gb));
        }
        CP_COMMIT();
    };

    fill(0, 0);

    for (int c = 0; c < NCH; ++c) {
        const int s = c & 1;
        if (c + 1 < NCH) { fill(c + 1, s ^ 1); CP_WAIT(1); }
        else             { CP_WAIT(0); }
        __syncthreads();

        const char* pAH = sm + OFF_AH(s);
        const char* pAL = sm + OFF_AL(s);
        const char* pBH = sm + OFF_BH(s);
        const char* pBL = sm + OFF_BL(s);

        #pragma unroll
        for (int ks = 0; ks < 2; ++ks) {
            unsigned ah[2][4], al[2][4], bh[8][2], bl[8][2];
            const unsigned colb = (unsigned)(ks * 32 + t * 4);
            #pragma unroll
            for (int mt = 0; mt < 2; ++mt) {
                unsigned o0 = (unsigned)(wM + mt * 16 + g) * ROWB + colb;
                unsigned o1 = o0 + 8u * ROWB;
                ah[mt][0] = *(const unsigned*)(pAH + o0);
                ah[mt][1] = *(const unsigned*)(pAH + o1);
                ah[mt][2] = *(const unsigned*)(pAH + o0 + 16u);
                ah[mt][3] = *(const unsigned*)(pAH + o1 + 16u);
                al[mt][0] = *(const unsigned*)(pAL + o0);
                al[mt][1] = *(const unsigned*)(pAL + o1);
                al[mt][2] = *(const unsigned*)(pAL + o0 + 16u);
                al[mt][3] = *(const unsigned*)(pAL + o1 + 16u);
            }
            #pragma unroll
            for (int nt = 0; nt < 8; ++nt) {
                unsigned ob = (unsigned)(wN + nt * 8 + g) * ROWB + colb;
                bh[nt][0] = *(const unsigned*)(pBH + ob);
                bh[nt][1] = *(const unsigned*)(pBH + ob + 16u);
                bl[nt][0] = *(const unsigned*)(pBL + ob);
                bl[nt][1] = *(const unsigned*)(pBL + ob + 16u);
            }
            #pragma unroll
            for (int mt = 0; mt < 2; ++mt)
                #pragma unroll
                for (int nt = 0; nt < 8; ++nt) {
                    MMA_BF16(acc[mt][nt], ah[mt], bh[nt]);
                    MMA_BF16(acc[mt][nt], ah[mt], bl[nt]);
                    MMA_BF16(acc[mt][nt], al[mt], bh[nt]);
                }
        }
        __syncthreads();
    }
}

// ---------------- K2: GEMM1 + fused epilogue (EXACT R4 structure) ----------------
__global__ __launch_bounds__(256) void gemm1_mma_kernel(const float* __restrict__ adj_v) {
    extern __shared__ char sm[];
    const unsigned sb = smem_u32(sm);
    const int warp = threadIdx.x >> 5;
    const int lane = threadIdx.x & 31;
    const int g = lane >> 2, t = lane & 3;
    const int iBase = blockIdx.y * 128;
    const int jBase = blockIdx.x * 128;
    const int wM = (warp >> 1) * 32;
    const int wN = (warp & 1) * 64;

    float acc[2][8][4];
    mma_mainloop<NN_EDGES, NN_EDGES / 32>(g_Ah, g_Al, g_Bh, g_Bl, iBase, jBase, sm, sb, acc);

    // epilogue: A_comb = (i==j) ? adj : 0.5*adj*(S+1)  (fp32, as in R4)
    #pragma unroll
    for (int mt = 0; mt < 2; ++mt) {
        int gi0 = iBase + wM + mt * 16 + g;        // rows gi0 and gi0+8
        const float* adj0 = adj_v + (size_t)gi0 * NN_NODES;
        const float* adj1 = adj0 + 8u * NN_NODES;
        float* d0 = g_Acomb + (size_t)gi0 * NN_NODES;
        float* d1 = d0 + 8u * NN_NODES;
        #pragma unroll
        for (int nt = 0; nt < 8; ++nt) {
            int gj = jBase + wN + nt * 8 + t * 2;
            float2 a0 = *(const float2*)(adj0 + gj);
            float2 a1 = *(const float2*)(adj1 + gj);
            float2 o0, o1;
            o0.x = (gi0 == gj)         ? a0.x : 0.5f * a0.x * (acc[mt][nt][0] + 1.0f);
            o0.y = (gi0 == gj + 1)     ? a0.y : 0.5f * a0.y * (acc[mt][nt][1] + 1.0f);
            o1.x = (gi0 + 8 == gj)     ? a1.x : 0.5f * a1.x * (acc[mt][nt][2] + 1.0f);
            o1.y = (gi0 + 8 == gj + 1) ? a1.y : 0.5f * a1.y * (acc[mt][nt][3] + 1.0f);
            *(float2*)(d0 + gj) = o0;
            *(float2*)(d1 + gj) = o1;
        }
    }
}

// ---------------- A_comb fp32 -> bf16 hi/lo split ----------------
__global__ __launch_bounds__(256) void acomb_split_kernel() {
    size_t i = ((size_t)blockIdx.x * 256 + threadIdx.x) * 4;
    float4 v = *(const float4*)(g_Acomb + i);
    float x[4] = {v.x, v.y, v.z, v.w};
    unsigned long long ch = 0, cl = 0;
    #pragma unroll
    for (int k = 0; k < 4; ++k) {
        __nv_bfloat16 h = __float2bfloat16(x[k]);
        __nv_bfloat16 l = __float2bfloat16(x[k] - __bfloat162float(h));
        ch |= (unsigned long long)__bfloat16_as_ushort(h) << (16 * k);
        cl |= (unsigned long long)__bfloat16_as_ushort(l) << (16 * k);
    }
    *(unsigned long long*)(g_Ch + i) = ch;
    *(unsigned long long*)(g_Cl + i) = cl;
}

// ---------------- K3: ret = A_comb @ HW + bias (tensorized, R4-style loop) ----------------
__global__ __launch_bounds__(256) void gemm_out_mma_kernel(
    const float* __restrict__ bias, float* __restrict__ out) {
    extern __shared__ char sm[];
    const unsigned sb = smem_u32(sm);
    const int warp = threadIdx.x >> 5;
    const int lane = threadIdx.x & 31;
    const int g = lane >> 2, t = lane & 3;
    const int iBase = blockIdx.y * 128;
    const int jBase = blockIdx.x * 128;
    const int wM = (warp >> 1) * 32;
    const int wN = (warp & 1) * 64;

    float acc[2][8][4];
    mma_mainloop<NN_NODES, NN_NODES / 32>(g_Ch, g_Cl, g_HWth, g_HWtl, iBase, jBase, sm, sb, acc);

    #pragma unroll
    for (int mt = 0; mt < 2; ++mt) {
        int gi0 = iBase + wM + mt * 16 + g;
        float* d0 = out + (size_t)gi0 * DIM_OUT;
        float* d1 = d0 + 8u * DIM_OUT;
        #pragma unroll
        for (int nt = 0; nt < 8; ++nt) {
            int gj = jBase + wN + nt * 8 + t * 2;
            float2 bs = *(const float2*)(bias + gj);
            *(float2*)(d0 + gj) = make_float2(acc[mt][nt][0] + bs.x, acc[mt][nt][1] + bs.y);
            *(float2*)(d1 + gj) = make_float2(acc[mt][nt][2] + bs.x, acc[mt][nt][3] + bs.y);
        }
    }
}

// ---------------- SIMT GEMM for HW = H_v @ W ----------------
__global__ __launch_bounds__(256, 2) void gemm_hw_kernel(
    const float* __restrict__ A, const float* __restrict__ B) {
    __shared__ __align__(16) float As[2][8][128];
    __shared__ __align__(16) float Bs[2][8][128];

    const int Nn = DIM_OUT, K = DIM_V;
    const int tid = threadIdx.x;
    const int iBase = blockIdx.y * 128;
    const int jBase = blockIdx.x * 128;

    const int lrow = tid >> 1;
    const int kq   = (tid & 1) * 4;
    const float* Aptr = A + (size_t)(iBase + lrow) * K + kq;
    const int bk = tid >> 5;
    const int bn = (tid & 31) * 4;
    const float* Bptr = B + (size_t)bk * Nn + jBase + bn;

    unsigned long long acc[8][4];
    #pragma unroll
    for (int r = 0; r < 8; ++r)
        #pragma unroll
        for (int c = 0; c < 4; ++c) acc[r][c] = 0ull;

    {
        float4 a = *(const float4*)Aptr;
        float4 b = *(const float4*)Bptr;
        As[0][kq + 0][lrow] = a.x; As[0][kq + 1][lrow] = a.y;
        As[0][kq + 2][lrow] = a.z; As[0][kq + 3][lrow] = a.w;
        *(float4*)&Bs[0][bk][bn] = b;
    }
    __syncthreads();

    const int tx = (tid & 15) * 8;
    const int ty = (tid >> 4) * 8;
    int buf = 0;
    const int KT = K / 8;

    for (int kt = 0; kt < KT; ++kt) {
        float4 aN, bN;
        if (kt + 1 < KT) {
            aN = *(const float4*)(Aptr + (size_t)(kt + 1) * 8);
            bN = *(const float4*)(Bptr + (size_t)(kt + 1) * 8 * Nn);
        }
        #pragma unroll
        for (int kk = 0; kk < 8; ++kk) {
            float4 a0 = *(const float4*)&As[buf][kk][ty];
            float4 a1 = *(const float4*)&As[buf][kk][ty + 4];
            ulonglong2 b0 = *(const ulonglong2*)&Bs[buf][kk][tx];
            ulonglong2 b1 = *(const ulonglong2*)&Bs[buf][kk][tx + 4];
            float av[8] = {a0.x, a0.y, a0.z, a0.w, a1.x, a1.y, a1.z, a1.w};
            unsigned long long bv[4] = {b0.x, b0.y, b1.x, b1.y};
            #pragma unroll
            for (int r = 0; r < 8; ++r) {
                unsigned long long aa = pack2(av[r], av[r]);
                #pragma unroll
                for (int c = 0; c < 4; ++c) ffma2(acc[r][c], aa, bv[c]);
            }
        }
        if (kt + 1 < KT) {
            int nb = buf ^ 1;
            As[nb][kq + 0][lrow] = aN.x; As[nb][kq + 1][lrow] = aN.y;
            As[nb][kq + 2][lrow] = aN.z; As[nb][kq + 3][lrow] = aN.w;
            *(float4*)&Bs[nb][bk][bn] = bN;
            __syncthreads();
            buf = nb;
        }
    }

    #pragma unroll
    for (int r = 0; r < 8; ++r) {
        int gi = iBase + ty + r;
        float* dst = g_HW + (size_t)gi * Nn;
        #pragma unroll
        for (int c = 0; c < 4; ++c) {
            int gj = jBase + tx + c * 2;
            float2 v = unpack2(acc[r][c]);
            *(float2*)&dst[gj] = v;
        }
    }
}

// ---------------- transpose + split: HW [4096,512] -> HW^T hi/lo [512,4096] ----------------
__global__ void hw_transpose_split_kernel() {
    __shared__ float tile[32][33];
    const int tx = threadIdx.x, ty = threadIdx.y;
    const int nb = blockIdx.x * 32;
    const int kb = blockIdx.y * 32;
    #pragma unroll
    for (int i = 0; i < 4; ++i) {
        int k = kb + ty + i * 8;
        tile[ty + i * 8][tx] = g_HW[(size_t)k * DIM_OUT + nb + tx];
    }
    __syncthreads();
    #pragma unroll
    for (int i = 0; i < 4; ++i) {
        int n = nb + ty + i * 8;
        int k = kb + tx;
        float v = tile[tx][ty + i * 8];
        __nv_bfloat16 h = __float2bfloat16(v);
        g_HWth[(size_t)n * NN_NODES + k] = h;
        g_HWtl[(size_t)n * NN_NODES + k] = __float2bfloat16(v - __bfloat162float(h));
    }
}

extern "C" void kernel_launch(void* const* d_in, const int* in_sizes, int n_in,
                              void* d_out, int out_size) {
    const float* H_v    = (const float*)d_in[0];
    const float* H_e    = (const float*)d_in[1];
    const float* adj_v  = (const float*)d_in[3];
    const float* T      = (const float*)d_in[4];
    const float* weight = (const float*)d_in[5];
    const float* p      = (const float*)d_in[6];
    const float* bias   = (const float*)d_in[7];
    float* out = (float*)d_out;
    (void)in_sizes; (void)n_in;

    cudaFuncSetAttribute(gemm1_mma_kernel,
                         cudaFuncAttributeMaxDynamicSharedMemorySize, SMEM_G1);
    cudaFuncSetAttribute(gemm_out_mma_kernel,
                         cudaFuncAttributeMaxDynamicSharedMemorySize, SMEM_G1);

    // K0: edge scaling vector
    escale_kernel<<<NN_EDGES / 8, dim3(32, 8)>>>(H_e, p);

    // K-split: bf16 hi/lo operand prep (depends on K0)
    split_kernel<<<(NN_NODES * NN_EDGES) / (256 * 4), 256>>>(T);

    // K1: HW = H_v @ W, then transpose+split for the tensorized output GEMM
    gemm_hw_kernel<<<dim3(DIM_OUT / 128, NN_NODES / 128), 256>>>(H_v, weight);
    hw_transpose_split_kernel<<<dim3(DIM_OUT / 32, NN_NODES / 32), dim3(32, 8)>>>();

    // K2: dominant GEMM (R4-proven mainloop) + fp32 A_comb epilogue
    gemm1_mma_kernel<<<dim3(NN_NODES / 128, NN_NODES / 128), 256, SMEM_G1>>>(adj_v);

    // A_comb -> bf16 hi/lo for the tensorized output GEMM
    acomb_split_kernel<<<(size_t)NN_NODES * NN_NODES / (256 * 4), 256>>>();

    // K3: ret = A_comb @ HW + bias (tensorized)
    gemm_out_mma_kernel<<<dim3(DIM_OUT / 128, NN_NODES / 128), 256, SMEM_G1>>>(bias, out);

    const size_t ret_elems = (size_t)NN_NODES * DIM_OUT;
    const size_t he_elems  = (size_t)NN_EDGES * DIM_E;
    if ((size_t)out_size >= ret_elems + he_elems) {
        cudaMemcpyAsync(out + ret_elems, H_e, he_elems * sizeof(float),
                        cudaMemcpyDeviceToDevice);
    }
}

// round 7
// speedup vs baseline: 1.8597x; 1.5877x over previous
#include <cuda_runtime.h>
#include <cuda_bf16.h>

// Problem constants
#define NN_NODES 4096
#define NN_EDGES 8192
#define DIM_V    512
#define DIM_OUT  512
#define DIM_E    128

// ---------------- scratch (device globals; no allocation allowed) ----------------
__device__ float g_e_scale[NN_EDGES];
__device__ float g_Acomb[(size_t)NN_NODES * NN_NODES];            // 64 MB fp32
__device__ float g_HW[(size_t)NN_NODES * DIM_OUT];                //  8 MB fp32
__device__ __nv_bfloat16 g_Ah[(size_t)NN_NODES * NN_EDGES];       // 64 MB
__device__ __nv_bfloat16 g_Al[(size_t)NN_NODES * NN_EDGES];       // 64 MB
__device__ __nv_bfloat16 g_Bh[(size_t)NN_NODES * NN_EDGES];       // 64 MB
__device__ __nv_bfloat16 g_Bl[(size_t)NN_NODES * NN_EDGES];       // 64 MB
__device__ __nv_bfloat16 g_Ch[(size_t)NN_NODES * NN_NODES];       // 32 MB (A_comb hi)
__device__ __nv_bfloat16 g_Cl[(size_t)NN_NODES * NN_NODES];       // 32 MB (A_comb lo)
__device__ __nv_bfloat16 g_HWth[(size_t)DIM_OUT * NN_NODES];      //  4 MB (HW^T hi)
__device__ __nv_bfloat16 g_HWtl[(size_t)DIM_OUT * NN_NODES];      //  4 MB (HW^T lo)

// ---------------- PTX helpers (non-'a' features only) ----------------
__device__ __forceinline__ unsigned smem_u32(const void* p) {
    unsigned a;
    asm("{ .reg .u64 t; cvta.to.shared.u64 t, %1; cvt.u32.u64 %0, t; }" : "=r"(a) : "l"(p));
    return a;
}
#define CP_ASYNC8(dst, src) \
    asm volatile("cp.async.ca.shared.global [%0], [%1], 8;" :: "r"(dst), "l"(src) : "memory")
#define CP_COMMIT() asm volatile("cp.async.commit_group;" ::: "memory")
#define CP_WAIT(n)  asm volatile("cp.async.wait_group %0;" :: "n"(n) : "memory")

#define MMA_BF16(acc, A, B) \
    asm volatile("mma.sync.aligned.m16n8k16.row.col.f32.bf16.bf16.f32 " \
                 "{%0,%1,%2,%3},{%4,%5,%6,%7},{%8,%9},{%0,%1,%2,%3};" \
                 : "+f"((acc)[0]), "+f"((acc)[1]), "+f"((acc)[2]), "+f"((acc)[3]) \
                 : "r"((A)[0]), "r"((A)[1]), "r"((A)[2]), "r"((A)[3]), \
                   "r"((B)[0]), "r"((B)[1]))

// ---------------- packed f32x2 helpers (SIMT GEMM) ----------------
__device__ __forceinline__ void ffma2(unsigned long long& d,
                                      unsigned long long a,
                                      unsigned long long b) {
    asm("fma.rn.f32x2 %0, %1, %2, %0;" : "+l"(d) : "l"(a), "l"(b));
}
__device__ __forceinline__ unsigned long long pack2(float x, float y) {
    unsigned long long r;
    asm("mov.b64 %0, {%1, %2};" : "=l"(r) : "f"(x), "f"(y));
    return r;
}
__device__ __forceinline__ float2 unpack2(unsigned long long v) {
    float2 f;
    asm("mov.b64 {%0, %1}, %2;" : "=f"(f.x), "=f"(f.y) : "l"(v));
    return f;
}

// ---------------- K0: e_scale[e] = dot(H_e[e,:], p) ----------------
__global__ void escale_kernel(const float* __restrict__ He,
                              const float* __restrict__ p) {
    int row  = blockIdx.x * 8 + threadIdx.y;
    int lane = threadIdx.x;
    float4 h  = ((const float4*)(He + (size_t)row * DIM_E))[lane];
    float4 pv = ((const float4*)p)[lane];
    float v = h.x * pv.x + h.y * pv.y + h.z * pv.z + h.w * pv.w;
    #pragma unroll
    for (int o = 16; o; o >>= 1) v += __shfl_xor_sync(0xffffffffu, v, o);
    if (lane == 0) g_e_scale[row] = v;
}

// ---------------- K-split: T -> (Bh,Bl), T*e -> (Ah,Al) bf16 hi/lo ----------------
__global__ __launch_bounds__(256) void split_kernel(const float* __restrict__ T) {
    size_t i = ((size_t)blockIdx.x * 256 + threadIdx.x) * 4;
    unsigned col = (unsigned)(i & (NN_EDGES - 1));
    float4 t = *(const float4*)(T + i);
    float4 e = *(const float4*)(g_e_scale + col);

    float b[4] = {t.x, t.y, t.z, t.w};
    float a[4] = {t.x * e.x, t.y * e.y, t.z * e.z, t.w * e.w};

    unsigned long long bh = 0, bl = 0, ah = 0, al = 0;
    #pragma unroll
    for (int k = 0; k < 4; ++k) {
        __nv_bfloat16 h = __float2bfloat16(b[k]);
        __nv_bfloat16 l = __float2bfloat16(b[k] - __bfloat162float(h));
        bh |= (unsigned long long)__bfloat16_as_ushort(h) << (16 * k);
        bl |= (unsigned long long)__bfloat16_as_ushort(l) << (16 * k);
        h = __float2bfloat16(a[k]);
        l = __float2bfloat16(a[k] - __bfloat162float(h));
        ah |= (unsigned long long)__bfloat16_as_ushort(h) << (16 * k);
        al |= (unsigned long long)__bfloat16_as_ushort(l) << (16 * k);
    }
    *(unsigned long long*)(g_Bh + i) = bh;
    *(unsigned long long*)(g_Bl + i) = bl;
    *(unsigned long long*)(g_Ah + i) = ah;
    *(unsigned long long*)(g_Al + i) = al;
}

// ---------------- shared mma mainloop (R4-proven: scalar LDS, 72B rows) ----------------
#define ROWB 72u                     // bytes per smem row (64 data + 8 pad)
#define TILEB (128u * ROWB)          // 9216 B per tile
#define STAGEB (4u * TILEB)          // 36864 B per stage (Ah,Al,Bh,Bl)
#define SMEM_G1 (2u * STAGEB)        // 73728 B
#define OFF_AH(s) ((unsigned)(s) * STAGEB)
#define OFF_AL(s) (OFF_AH(s) + TILEB)
#define OFF_BH(s) (OFF_AH(s) + 2u * TILEB)
#define OFF_BL(s) (OFF_AH(s) + 3u * TILEB)

template<int LD, int NCH>
__device__ __forceinline__ void mma_mainloop(
    const __nv_bfloat16* __restrict__ Ahp, const __nv_bfloat16* __restrict__ Alp,
    const __nv_bfloat16* __restrict__ Bhp, const __nv_bfloat16* __restrict__ Blp,
    int iBase, int jBase, char* sm, unsigned sb, float (&acc)[2][8][4]) {

    const int tid  = threadIdx.x;
    const int warp = tid >> 5;
    const int lane = tid & 31;
    const int g = lane >> 2, t = lane & 3;
    const int wM = (warp >> 1) * 32;
    const int wN = (warp & 1) * 64;

    #pragma unroll
    for (int mt = 0; mt < 2; ++mt)
        #pragma unroll
        for (int nt = 0; nt < 8; ++nt)
            #pragma unroll
            for (int q = 0; q < 4; ++q) acc[mt][nt][q] = 0.0f;

    auto fill = [&](int chunk, int stg) {
        const unsigned kb = (unsigned)chunk * 32u;
        #pragma unroll
        for (int i = 0; i < 4; ++i) {
            int c = tid + i * 256;
            int row = c >> 3, sub = c & 7;
            unsigned so = (unsigned)row * ROWB + (unsigned)sub * 8u;
            size_t ga = (size_t)(iBase + row) * LD + kb + sub * 4;
            size_t gb = (size_t)(jBase + row) * LD + kb + sub * 4;
            CP_ASYNC8(sb + OFF_AH(stg) + so, (const char*)(Ahp + ga));
            CP_ASYNC8(sb + OFF_AL(stg) + so, (const char*)(Alp + ga));
            CP_ASYNC8(sb + OFF_BH(stg) + so, (const char*)(Bhp + gb));
            CP_ASYNC8(sb + OFF_BL(stg) + so, (const char*)(Blp + gb));
        }
        CP_COMMIT();
    };

    fill(0, 0);

    for (int c = 0; c < NCH; ++c) {
        const int s = c & 1;
        if (c + 1 < NCH) { fill(c + 1, s ^ 1); CP_WAIT(1); }
        else             { CP_WAIT(0); }
        __syncthreads();

        const char* pAH = sm + OFF_AH(s);
        const char* pAL = sm + OFF_AL(s);
        const char* pBH = sm + OFF_BH(s);
        const char* pBL = sm + OFF_BL(s);

        #pragma unroll
        for (int ks = 0; ks < 2; ++ks) {
            unsigned ah[2][4], al[2][4], bh[8][2], bl[8][2];
            const unsigned colb = (unsigned)(ks * 32 + t * 4);
            #pragma unroll
            for (int mt = 0; mt < 2; ++mt) {
                unsigned o0 = (unsigned)(wM + mt * 16 + g) * ROWB + colb;
                unsigned o1 = o0 + 8u * ROWB;
                ah[mt][0] = *(const unsigned*)(pAH + o0);
                ah[mt][1] = *(const unsigned*)(pAH + o1);
                ah[mt][2] = *(const unsigned*)(pAH + o0 + 16u);
                ah[mt][3] = *(const unsigned*)(pAH + o1 + 16u);
                al[mt][0] = *(const unsigned*)(pAL + o0);
                al[mt][1] = *(const unsigned*)(pAL + o1);
                al[mt][2] = *(const unsigned*)(pAL + o0 + 16u);
                al[mt][3] = *(const unsigned*)(pAL + o1 + 16u);
            }
            #pragma unroll
            for (int nt = 0; nt < 8; ++nt) {
                unsigned ob = (unsigned)(wN + nt * 8 + g) * ROWB + colb;
                bh[nt][0] = *(const unsigned*)(pBH + ob);
                bh[nt][1] = *(const unsigned*)(pBH + ob + 16u);
                bl[nt][0] = *(const unsigned*)(pBL + ob);
                bl[nt][1] = *(const unsigned*)(pBL + ob + 16u);
            }
            #pragma unroll
            for (int mt = 0; mt < 2; ++mt)
                #pragma unroll
                for (int nt = 0; nt < 8; ++nt) {
                    MMA_BF16(acc[mt][nt], ah[mt], bh[nt]);
                    MMA_BF16(acc[mt][nt], ah[mt], bl[nt]);
                    MMA_BF16(acc[mt][nt], al[mt], bh[nt]);
                }
        }
        __syncthreads();
    }
}

// ---------------- K2: GEMM1 over UPPER-TRIANGULAR blocks (S symmetric) ----------------
#define TS_LDC 132   // floats per staged row (128 + 4 pad); 132*4=528 B, 16B-aligned rows

__global__ __launch_bounds__(256) void gemm1_mma_kernel(const float* __restrict__ adj_v) {
    extern __shared__ char sm[];
    const unsigned sb = smem_u32(sm);
    const int tid  = threadIdx.x;
    const int warp = tid >> 5;
    const int lane = tid & 31;
    const int g = lane >> 2, t = lane & 3;
    const int wM = (warp >> 1) * 32;
    const int wN = (warp & 1) * 64;

    // triangular block mapping: bid -> (bi <= bj), 32x32 block grid, 528 blocks
    const int rbid = 527 - (int)blockIdx.x;
    int u = (int)((sqrtf(8.0f * (float)rbid + 1.0f) - 1.0f) * 0.5f);
    while ((u + 1) * (u + 2) / 2 <= rbid) ++u;
    while (u * (u + 1) / 2 > rbid) --u;
    const int bi = 31 - u;
    const int bj = 31 - (rbid - u * (u + 1) / 2);
    const int iBase = bi * 128;
    const int jBase = bj * 128;

    float acc[2][8][4];
    mma_mainloop<NN_EDGES, NN_EDGES / 32>(g_Ah, g_Al, g_Bh, g_Bl, iBase, jBase, sm, sb, acc);

    // direct epilogue: A_comb[i,j] = (i==j) ? adj : 0.5*adj*(S+1)
    #pragma unroll
    for (int mt = 0; mt < 2; ++mt) {
        int gi0 = iBase + wM + mt * 16 + g;
        const float* adj0 = adj_v + (size_t)gi0 * NN_NODES;
        const float* adj1 = adj0 + 8u * NN_NODES;
        float* d0 = g_Acomb + (size_t)gi0 * NN_NODES;
        float* d1 = d0 + 8u * NN_NODES;
        #pragma unroll
        for (int nt = 0; nt < 8; ++nt) {
            int gj = jBase + wN + nt * 8 + t * 2;
            float2 a0 = *(const float2*)(adj0 + gj);
            float2 a1 = *(const float2*)(adj1 + gj);
            float2 o0, o1;
            o0.x = (gi0 == gj)         ? a0.x : 0.5f * a0.x * (acc[mt][nt][0] + 1.0f);
            o0.y = (gi0 == gj + 1)     ? a0.y : 0.5f * a0.y * (acc[mt][nt][1] + 1.0f);
            o1.x = (gi0 + 8 == gj)     ? a1.x : 0.5f * a1.x * (acc[mt][nt][2] + 1.0f);
            o1.y = (gi0 + 8 == gj + 1) ? a1.y : 0.5f * a1.y * (acc[mt][nt][3] + 1.0f);
            *(float2*)(d0 + gj) = o0;
            *(float2*)(d1 + gj) = o1;
        }
    }

    // mirrored epilogue (bi != bj): A_comb[j,i] = 0.5*adj[j,i]*(S[i,j]+1)
    if (bi != bj) {
        float* TS = (float*)sm;   // reuse stage smem; mainloop ended with __syncthreads
        #pragma unroll
        for (int mt = 0; mt < 2; ++mt) {
            int ii = wM + mt * 16 + g;
            #pragma unroll
            for (int nt = 0; nt < 8; ++nt) {
                int jj = wN + nt * 8 + t * 2;
                TS[(jj)     * TS_LDC + ii]     = acc[mt][nt][0];
                TS[(jj + 1) * TS_LDC + ii]     = acc[mt][nt][1];
                TS[(jj)     * TS_LDC + ii + 8] = acc[mt][nt][2];
                TS[(jj + 1) * TS_LDC + ii + 8] = acc[mt][nt][3];
            }
        }
        __syncthreads();

        const int jj  = tid >> 1;            // row of mirrored block (0..127)
        const int iiB = (tid & 1) * 64;      // half of the 128 cols
        const int gj  = jBase + jj;
        const float* adjRow = adj_v + (size_t)gj * NN_NODES + iBase + iiB;
        float* dst = g_Acomb + (size_t)gj * NN_NODES + iBase + iiB;
        const float* tsRow = TS + jj * TS_LDC + iiB;
        #pragma unroll
        for (int q = 0; q < 16; ++q) {
            float4 a = *(const float4*)(adjRow + q * 4);
            float4 s = *(const float4*)(tsRow + q * 4);
            float4 o;
            o.x = 0.5f * a.x * (s.x + 1.0f);
            o.y = 0.5f * a.y * (s.y + 1.0f);
            o.z = 0.5f * a.z * (s.z + 1.0f);
            o.w = 0.5f * a.w * (s.w + 1.0f);
            *(float4*)(dst + q * 4) = o;
        }
    }
}

// ---------------- A_comb fp32 -> bf16 hi/lo split ----------------
__global__ __launch_bounds__(256) void acomb_split_kernel() {
    size_t i = ((size_t)blockIdx.x * 256 + threadIdx.x) * 4;
    float4 v = *(const float4*)(g_Acomb + i);
    float x[4] = {v.x, v.y, v.z, v.w};
    unsigned long long ch = 0, cl = 0;
    #pragma unroll
    for (int k = 0; k < 4; ++k) {
        __nv_bfloat16 h = __float2bfloat16(x[k]);
        __nv_bfloat16 l = __float2bfloat16(x[k] - __bfloat162float(h));
        ch |= (unsigned long long)__bfloat16_as_ushort(h) << (16 * k);
        cl |= (unsigned long long)__bfloat16_as_ushort(l) << (16 * k);
    }
    *(unsigned long long*)(g_Ch + i) = ch;
    *(unsigned long long*)(g_Cl + i) = cl;
}

// ---------------- K3: ret = A_comb @ HW + bias (tensorized) ----------------
__global__ __launch_bounds__(256) void gemm_out_mma_kernel(
    const float* __restrict__ bias, float* __restrict__ out) {
    extern __shared__ char sm[];
    const unsigned sb = smem_u32(sm);
    const int warp = threadIdx.x >> 5;
    const int lane = threadIdx.x & 31;
    const int g = lane >> 2, t = lane & 3;
    const int iBase = blockIdx.y * 128;
    const int jBase = blockIdx.x * 128;
    const int wM = (warp >> 1) * 32;
    const int wN = (warp & 1) * 64;

    float acc[2][8][4];
    mma_mainloop<NN_NODES, NN_NODES / 32>(g_Ch, g_Cl, g_HWth, g_HWtl, iBase, jBase, sm, sb, acc);

    #pragma unroll
    for (int mt = 0; mt < 2; ++mt) {
        int gi0 = iBase + wM + mt * 16 + g;
        float* d0 = out + (size_t)gi0 * DIM_OUT;
        float* d1 = d0 + 8u * DIM_OUT;
        #pragma unroll
        for (int nt = 0; nt < 8; ++nt) {
            int gj = jBase + wN + nt * 8 + t * 2;
            float2 bs = *(const float2*)(bias + gj);
            *(float2*)(d0 + gj) = make_float2(acc[mt][nt][0] + bs.x, acc[mt][nt][1] + bs.y);
            *(float2*)(d1 + gj) = make_float2(acc[mt][nt][2] + bs.x, acc[mt][nt][3] + bs.y);
        }
    }
}

// ---------------- SIMT GEMM for HW = H_v @ W ----------------
__global__ __launch_bounds__(256, 2) void gemm_hw_kernel(
    const float* __restrict__ A, const float* __restrict__ B) {
    __shared__ __align__(16) float As[2][8][128];
    __shared__ __align__(16) float Bs[2][8][128];

    const int Nn = DIM_OUT, K = DIM_V;
    const int tid = threadIdx.x;
    const int iBase = blockIdx.y * 128;
    const int jBase = blockIdx.x * 128;

    const int lrow = tid >> 1;
    const int kq   = (tid & 1) * 4;
    const float* Aptr = A + (size_t)(iBase + lrow) * K + kq;
    const int bk = tid >> 5;
    const int bn = (tid & 31) * 4;
    const float* Bptr = B + (size_t)bk * Nn + jBase + bn;

    unsigned long long acc[8][4];
    #pragma unroll
    for (int r = 0; r < 8; ++r)
        #pragma unroll
        for (int c = 0; c < 4; ++c) acc[r][c] = 0ull;

    {
        float4 a = *(const float4*)Aptr;
        float4 b = *(const float4*)Bptr;
        As[0][kq + 0][lrow] = a.x; As[0][kq + 1][lrow] = a.y;
        As[0][kq + 2][lrow] = a.z; As[0][kq + 3][lrow] = a.w;
        *(float4*)&Bs[0][bk][bn] = b;
    }
    __syncthreads();

    const int tx = (tid & 15) * 8;
    const int ty = (tid >> 4) * 8;
    int buf = 0;
    const int KT = K / 8;

    for (int kt = 0; kt < KT; ++kt) {
        float4 aN, bN;
        if (kt + 1 < KT) {
            aN = *(const float4*)(Aptr + (size_t)(kt + 1) * 8);
            bN = *(const float4*)(Bptr + (size_t)(kt + 1) * 8 * Nn);
        }
        #pragma unroll
        for (int kk = 0; kk < 8; ++kk) {
            float4 a0 = *(const float4*)&As[buf][kk][ty];
            float4 a1 = *(const float4*)&As[buf][kk][ty + 4];
            ulonglong2 b0 = *(const ulonglong2*)&Bs[buf][kk][tx];
            ulonglong2 b1 = *(const ulonglong2*)&Bs[buf][kk][tx + 4];
            float av[8] = {a0.x, a0.y, a0.z, a0.w, a1.x, a1.y, a1.z, a1.w};
            unsigned long long bv[4] = {b0.x, b0.y, b1.x, b1.y};
            #pragma unroll
            for (int r = 0; r < 8; ++r) {
                unsigned long long aa = pack2(av[r], av[r]);
                #pragma unroll
                for (int c = 0; c < 4; ++c) ffma2(acc[r][c], aa, bv[c]);
            }
        }
        if (kt + 1 < KT) {
            int nb = buf ^ 1;
            As[nb][kq + 0][lrow] = aN.x; As[nb][kq + 1][lrow] = aN.y;
            As[nb][kq + 2][lrow] = aN.z; As[nb][kq + 3][lrow] = aN.w;
            *(float4*)&Bs[nb][bk][bn] = bN;
            __syncthreads();
            buf = nb;
        }
    }

    #pragma unroll
    for (int r = 0; r < 8; ++r) {
        int gi = iBase + ty + r;
        float* dst = g_HW + (size_t)gi * Nn;
        #pragma unroll
        for (int c = 0; c < 4; ++c) {
            int gj = jBase + tx + c * 2;
            float2 v = unpack2(acc[r][c]);
            *(float2*)&dst[gj] = v;
        }
    }
}

// ---------------- transpose + split: HW [4096,512] -> HW^T hi/lo [512,4096] ----------------
__global__ void hw_transpose_split_kernel() {
    __shared__ float tile[32][33];
    const int tx = threadIdx.x, ty = threadIdx.y;
    const int nb = blockIdx.x * 32;
    const int kb = blockIdx.y * 32;
    #pragma unroll
    for (int i = 0; i < 4; ++i) {
        int k = kb + ty + i * 8;
        tile[ty + i * 8][tx] = g_HW[(size_t)k * DIM_OUT + nb + tx];
    }
    __syncthreads();
    #pragma unroll
    for (int i = 0; i < 4; ++i) {
        int n = nb + ty + i * 8;
        int k = kb + tx;
        float v = tile[tx][ty + i * 8];
        __nv_bfloat16 h = __float2bfloat16(v);
        g_HWth[(size_t)n * NN_NODES + k] = h;
        g_HWtl[(size_t)n * NN_NODES + k] = __float2bfloat16(v - __bfloat162float(h));
    }
}

extern "C" void kernel_launch(void* const* d_in, const int* in_sizes, int n_in,
                              void* d_out, int out_size) {
    const float* H_v    = (const float*)d_in[0];
    const float* H_e    = (const float*)d_in[1];
    const float* adj_v  = (const float*)d_in[3];
    const float* T      = (const float*)d_in[4];
    const float* weight = (const float*)d_in[5];
    const float* p      = (const float*)d_in[6];
    const float* bias   = (const float*)d_in[7];
    float* out = (float*)d_out;
    (void)in_sizes; (void)n_in;

    cudaFuncSetAttribute(gemm1_mma_kernel,
                         cudaFuncAttributeMaxDynamicSharedMemorySize, SMEM_G1);
    cudaFuncSetAttribute(gemm_out_mma_kernel,
                         cudaFuncAttributeMaxDynamicSharedMemorySize, SMEM_G1);

    // K0: edge scaling vector
    escale_kernel<<<NN_EDGES / 8, dim3(32, 8)>>>(H_e, p);

    // K-split: bf16 hi/lo operand prep (depends on K0)
    split_kernel<<<(NN_NODES * NN_EDGES) / (256 * 4), 256>>>(T);

    // K1: HW = H_v @ W, then transpose+split for the tensorized output GEMM
    gemm_hw_kernel<<<dim3(DIM_OUT / 128, NN_NODES / 128), 256>>>(H_v, weight);
    hw_transpose_split_kernel<<<dim3(DIM_OUT / 32, NN_NODES / 32), dim3(32, 8)>>>();

    // K2: dominant GEMM — upper-triangular blocks only (S symmetric), mirrored epilogue
    gemm1_mma_kernel<<<528, 256, SMEM_G1>>>(adj_v);

    // A_comb -> bf16 hi/lo for the tensorized output GEMM
    acomb_split_kernel<<<(size_t)NN_NODES * NN_NODES / (256 * 4), 256>>>();

    // K3: ret = A_comb @ HW + bias (tensorized)
    gemm_out_mma_kernel<<<dim3(DIM_OUT / 128, NN_NODES / 128), 256, SMEM_G1>>>(bias, out);

    const size_t ret_elems = (size_t)NN_NODES * DIM_OUT;
    const size_t he_elems  = (size_t)NN_EDGES * DIM_E;
    if ((size_t)out_size >= ret_elems + he_elems) {
        cudaMemcpyAsync(out + ret_elems, H_e, he_elems * sizeof(float),
                        cudaMemcpyDeviceToDevice);
    }
}

// round 8
// speedup vs baseline: 1.9508x; 1.0490x over previous
#include <cuda_runtime.h>
#include <cuda_bf16.h>

// Problem constants
#define NN_NODES 4096
#define NN_EDGES 8192
#define DIM_V    512
#define DIM_OUT  512
#define DIM_E    128

// ---------------- scratch (device globals; no allocation allowed) ----------------
__device__ float g_e_scale[NN_EDGES];
__device__ float g_Acomb[(size_t)NN_NODES * NN_NODES];            // 64 MB fp32
__device__ float g_HW[(size_t)NN_NODES * DIM_OUT];                //  8 MB fp32
__device__ __nv_bfloat16 g_Ah[(size_t)NN_NODES * NN_EDGES];       // 64 MB
__device__ __nv_bfloat16 g_Al[(size_t)NN_NODES * NN_EDGES];       // 64 MB
__device__ __nv_bfloat16 g_Bh[(size_t)NN_NODES * NN_EDGES];       // 64 MB
__device__ __nv_bfloat16 g_Bl[(size_t)NN_NODES * NN_EDGES];       // 64 MB
__device__ __nv_bfloat16 g_Ch[(size_t)NN_NODES * NN_NODES];       // 32 MB (A_comb hi)
__device__ __nv_bfloat16 g_Cl[(size_t)NN_NODES * NN_NODES];       // 32 MB (A_comb lo)
__device__ __nv_bfloat16 g_HWth[(size_t)DIM_OUT * NN_NODES];      //  4 MB (HW^T hi)
__device__ __nv_bfloat16 g_HWtl[(size_t)DIM_OUT * NN_NODES];      //  4 MB (HW^T lo)

// ---------------- PTX helpers (non-'a' features only) ----------------
__device__ __forceinline__ unsigned smem_u32(const void* p) {
    unsigned a;
    asm("{ .reg .u64 t; cvta.to.shared.u64 t, %1; cvt.u32.u64 %0, t; }" : "=r"(a) : "l"(p));
    return a;
}
#define CP_ASYNC8(dst, src) \
    asm volatile("cp.async.ca.shared.global [%0], [%1], 8;" :: "r"(dst), "l"(src) : "memory")
#define CP_COMMIT() asm volatile("cp.async.commit_group;" ::: "memory")
#define CP_WAIT(n)  asm volatile("cp.async.wait_group %0;" :: "n"(n) : "memory")

#define MMA_BF16(acc, A, B) \
    asm volatile("mma.sync.aligned.m16n8k16.row.col.f32.bf16.bf16.f32 " \
                 "{%0,%1,%2,%3},{%4,%5,%6,%7},{%8,%9},{%0,%1,%2,%3};" \
                 : "+f"((acc)[0]), "+f"((acc)[1]), "+f"((acc)[2]), "+f"((acc)[3]) \
                 : "r"((A)[0]), "r"((A)[1]), "r"((A)[2]), "r"((A)[3]), \
                   "r"((B)[0]), "r"((B)[1]))

// ---------------- packed f32x2 helpers (SIMT GEMM) ----------------
__device__ __forceinline__ void ffma2(unsigned long long& d,
                                      unsigned long long a,
                                      unsigned long long b) {
    asm("fma.rn.f32x2 %0, %1, %2, %0;" : "+l"(d) : "l"(a), "l"(b));
}
__device__ __forceinline__ unsigned long long pack2(float x, float y) {
    unsigned long long r;
    asm("mov.b64 %0, {%1, %2};" : "=l"(r) : "f"(x), "f"(y));
    return r;
}
__device__ __forceinline__ float2 unpack2(unsigned long long v) {
    float2 f;
    asm("mov.b64 {%0, %1}, %2;" : "=f"(f.x), "=f"(f.y) : "l"(v));
    return f;
}

// ---------------- K0: e_scale[e] = dot(H_e[e,:], p) ----------------
__global__ void escale_kernel(const float* __restrict__ He,
                              const float* __restrict__ p) {
    int row  = blockIdx.x * 8 + threadIdx.y;
    int lane = threadIdx.x;
    float4 h  = ((const float4*)(He + (size_t)row * DIM_E))[lane];
    float4 pv = ((const float4*)p)[lane];
    float v = h.x * pv.x + h.y * pv.y + h.z * pv.z + h.w * pv.w;
    #pragma unroll
    for (int o = 16; o; o >>= 1) v += __shfl_xor_sync(0xffffffffu, v, o);
    if (lane == 0) g_e_scale[row] = v;
}

// ---------------- K-split: T -> (Bh,Bl), T*e -> (Ah,Al) bf16 hi/lo ----------------
__global__ __launch_bounds__(256) void split_kernel(const float* __restrict__ T) {
    size_t i = ((size_t)blockIdx.x * 256 + threadIdx.x) * 4;
    unsigned col = (unsigned)(i & (NN_EDGES - 1));
    float4 t = *(const float4*)(T + i);
    float4 e = *(const float4*)(g_e_scale + col);

    float b[4] = {t.x, t.y, t.z, t.w};
    float a[4] = {t.x * e.x, t.y * e.y, t.z * e.z, t.w * e.w};

    unsigned long long bh = 0, bl = 0, ah = 0, al = 0;
    #pragma unroll
    for (int k = 0; k < 4; ++k) {
        __nv_bfloat16 h = __float2bfloat16(b[k]);
        __nv_bfloat16 l = __float2bfloat16(b[k] - __bfloat162float(h));
        bh |= (unsigned long long)__bfloat16_as_ushort(h) << (16 * k);
        bl |= (unsigned long long)__bfloat16_as_ushort(l) << (16 * k);
        h = __float2bfloat16(a[k]);
        l = __float2bfloat16(a[k] - __bfloat162float(h));
        ah |= (unsigned long long)__bfloat16_as_ushort(h) << (16 * k);
        al |= (unsigned long long)__bfloat16_as_ushort(l) << (16 * k);
    }
    *(unsigned long long*)(g_Bh + i) = bh;
    *(unsigned long long*)(g_Bl + i) = bl;
    *(unsigned long long*)(g_Ah + i) = ah;
    *(unsigned long long*)(g_Al + i) = al;
}

// ================= K2: GEMM1, CTA tile 256x128, warp tile 64x64 =================
// Triangular over 256-row super-blocks; S symmetric; mirrored epilogue per half.
#define ROWB 72u
#define A_ROWS 256
#define B_ROWS 128
#define ATILEB (A_ROWS * ROWB)            // 18432
#define BTILEB (B_ROWS * ROWB)            //  9216
#define STAGEB2 (2u * ATILEB + 2u * BTILEB)   // 55296
#define SMEM_G1 (2u * STAGEB2)                // 110592
#define OFF2_AH(s) ((unsigned)(s) * STAGEB2)
#define OFF2_AL(s) (OFF2_AH(s) + ATILEB)
#define OFF2_BH(s) (OFF2_AH(s) + 2u * ATILEB)
#define OFF2_BL(s) (OFF2_AH(s) + 2u * ATILEB + BTILEB)
#define NCH_G1 (NN_EDGES / 32)            // 256
#define TS_LDC 132

__global__ __launch_bounds__(256) void gemm1_mma_kernel(const float* __restrict__ adj_v) {
    extern __shared__ char sm[];
    const unsigned sb = smem_u32(sm);
    const int tid  = threadIdx.x;
    const int warp = tid >> 5;
    const int lane = tid & 31;
    const int g = lane >> 2, t = lane & 3;
    const int wM = (warp >> 1) * 64;      // 4 warps over 256 M-rows
    const int wN = (warp & 1) * 64;       // 2 warps over 128 N-cols

    // bid -> (BI, bj): BI = 256-row super-block (0..15), bj = 128-col block >= 2*BI
    int r = (int)blockIdx.x, BI = 0;
    while (r >= 32 - 2 * BI) { r -= 32 - 2 * BI; ++BI; }
    const int bj = 2 * BI + r;
    const int iBase = BI * 256;
    const int jBase = bj * 128;

    float acc[4][8][4];
    #pragma unroll
    for (int mt = 0; mt < 4; ++mt)
        #pragma unroll
        for (int nt = 0; nt < 8; ++nt)
            #pragma unroll
            for (int q = 0; q < 4; ++q) acc[mt][nt][q] = 0.0f;

    auto fill = [&](int chunk, int stg) {
        const unsigned kb = (unsigned)chunk * 32u;
        #pragma unroll
        for (int i = 0; i < 8; ++i) {                 // A: 256 rows x 8 segs
            int c = tid + i * 256;
            int row = c >> 3, sub = c & 7;
            unsigned so = (unsigned)row * ROWB + (unsigned)sub * 8u;
            size_t ga = (size_t)(iBase + row) * NN_EDGES + kb + sub * 4;
            CP_ASYNC8(sb + OFF2_AH(stg) + so, (const char*)(g_Ah + ga));
            CP_ASYNC8(sb + OFF2_AL(stg) + so, (const char*)(g_Al + ga));
        }
        #pragma unroll
        for (int i = 0; i < 4; ++i) {                 // B: 128 rows x 8 segs
            int c = tid + i * 256;
            int row = c >> 3, sub = c & 7;
            unsigned so = (unsigned)row * ROWB + (unsigned)sub * 8u;
            size_t gb = (size_t)(jBase + row) * NN_EDGES + kb + sub * 4;
            CP_ASYNC8(sb + OFF2_BH(stg) + so, (const char*)(g_Bh + gb));
            CP_ASYNC8(sb + OFF2_BL(stg) + so, (const char*)(g_Bl + gb));
        }
        CP_COMMIT();
    };

    fill(0, 0);

    for (int c = 0; c < NCH_G1; ++c) {
        const int s = c & 1;
        if (c + 1 < NCH_G1) { fill(c + 1, s ^ 1); CP_WAIT(1); }
        else                { CP_WAIT(0); }
        __syncthreads();

        const char* pAH = sm + OFF2_AH(s);
        const char* pAL = sm + OFF2_AL(s);
        const char* pBH = sm + OFF2_BH(s);
        const char* pBL = sm + OFF2_BL(s);

        #pragma unroll
        for (int ks = 0; ks < 2; ++ks) {
            const unsigned colb = (unsigned)(ks * 32 + t * 4);
            unsigned ah[4][4], al[4][4];
            #pragma unroll
            for (int mt = 0; mt < 4; ++mt) {
                unsigned o0 = (unsigned)(wM + mt * 16 + g) * ROWB + colb;
                unsigned o1 = o0 + 8u * ROWB;
                ah[mt][0] = *(const unsigned*)(pAH + o0);
                ah[mt][1] = *(const unsigned*)(pAH + o1);
                ah[mt][2] = *(const unsigned*)(pAH + o0 + 16u);
                ah[mt][3] = *(const unsigned*)(pAH + o1 + 16u);
                al[mt][0] = *(const unsigned*)(pAL + o0);
                al[mt][1] = *(const unsigned*)(pAL + o1);
                al[mt][2] = *(const unsigned*)(pAL + o0 + 16u);
                al[mt][3] = *(const unsigned*)(pAL + o1 + 16u);
            }
            #pragma unroll
            for (int nt = 0; nt < 8; ++nt) {
                unsigned bh[2], bl[2];
                unsigned ob = (unsigned)(wN + nt * 8 + g) * ROWB + colb;
                bh[0] = *(const unsigned*)(pBH + ob);
                bh[1] = *(const unsigned*)(pBH + ob + 16u);
                bl[0] = *(const unsigned*)(pBL + ob);
                bl[1] = *(const unsigned*)(pBL + ob + 16u);
                #pragma unroll
                for (int mt = 0; mt < 4; ++mt) {
                    MMA_BF16(acc[mt][nt], ah[mt], bh);
                    MMA_BF16(acc[mt][nt], ah[mt], bl);
                    MMA_BF16(acc[mt][nt], al[mt], bh);
                }
            }
        }
        __syncthreads();
    }

    // -------- direct epilogue: A_comb[i,j] for halves on/above diagonal --------
    #pragma unroll
    for (int mt = 0; mt < 4; ++mt) {
        const int roff = wM + mt * 16 + g;       // 0..255
        const int h = roff >> 7;                 // row half
        if (h == 1 && bj == 2 * BI) continue;    // below diagonal: skip
        const int gi0 = iBase + roff;
        const float* adj0 = adj_v + (size_t)gi0 * NN_NODES;
        const float* adj1 = adj0 + 8u * NN_NODES;
        float* d0 = g_Acomb + (size_t)gi0 * NN_NODES;
        float* d1 = d0 + 8u * NN_NODES;
        #pragma unroll
        for (int nt = 0; nt < 8; ++nt) {
            int gj = jBase + wN + nt * 8 + t * 2;
            float2 a0 = *(const float2*)(adj0 + gj);
            float2 a1 = *(const float2*)(adj1 + gj);
            float2 o0, o1;
            o0.x = (gi0 == gj)         ? a0.x : 0.5f * a0.x * (acc[mt][nt][0] + 1.0f);
            o0.y = (gi0 == gj + 1)     ? a0.y : 0.5f * a0.y * (acc[mt][nt][1] + 1.0f);
            o1.x = (gi0 + 8 == gj)     ? a1.x : 0.5f * a1.x * (acc[mt][nt][2] + 1.0f);
            o1.y = (gi0 + 8 == gj + 1) ? a1.y : 0.5f * a1.y * (acc[mt][nt][3] + 1.0f);
            *(float2*)(d0 + gj) = o0;
            *(float2*)(d1 + gj) = o1;
        }
    }

    // -------- mirrored epilogue per row-half h with 2*BI+h < bj --------
    float* TS = (float*)sm;
    #pragma unroll
    for (int h = 0; h < 2; ++h) {
        if (2 * BI + h >= bj) continue;          // uniform across CTA
        __syncthreads();
        if ((wM >> 7) == h) {                    // warps owning this half stage S
            const int ibase_loc = wM & 127;
            #pragma unroll
            for (int mt = 0; mt < 4; ++mt) {
                int ii = ibase_loc + mt * 16 + g;
                #pragma unroll
                for (int nt = 0; nt < 8; ++nt) {
                    int jj = wN + nt * 8 + t * 2;
                    TS[(jj)     * TS_LDC + ii]     = acc[mt][nt][0];
                    TS[(jj + 1) * TS_LDC + ii]     = acc[mt][nt][1];
                    TS[(jj)     * TS_LDC + ii + 8] = acc[mt][nt][2];
                    TS[(jj + 1) * TS_LDC + ii + 8] = acc[mt][nt][3];
                }
            }
        }
        __syncthreads();

        const int jj  = tid >> 1;
        const int iiB = (tid & 1) * 64;
        const int gj  = jBase + jj;
        const int giB = iBase + h * 128 + iiB;
        const float* adjRow = adj_v + (size_t)gj * NN_NODES + giB;
        float* dst = g_Acomb + (size_t)gj * NN_NODES + giB;
        const float* tsRow = TS + jj * TS_LDC + iiB;
        #pragma unroll
        for (int q = 0; q < 16; ++q) {
            float4 a = *(const float4*)(adjRow + q * 4);
            float4 s4 = *(const float4*)(tsRow + q * 4);
            float4 o;
            o.x = 0.5f * a.x * (s4.x + 1.0f);
            o.y = 0.5f * a.y * (s4.y + 1.0f);
            o.z = 0.5f * a.z * (s4.z + 1.0f);
            o.w = 0.5f * a.w * (s4.w + 1.0f);
            *(float4*)(dst + q * 4) = o;
        }
    }
}

// ---------------- A_comb fp32 -> bf16 hi/lo split ----------------
__global__ __launch_bounds__(256) void acomb_split_kernel() {
    size_t i = ((size_t)blockIdx.x * 256 + threadIdx.x) * 4;
    float4 v = *(const float4*)(g_Acomb + i);
    float x[4] = {v.x, v.y, v.z, v.w};
    unsigned long long ch = 0, cl = 0;
    #pragma unroll
    for (int k = 0; k < 4; ++k) {
        __nv_bfloat16 h = __float2bfloat16(x[k]);
        __nv_bfloat16 l = __float2bfloat16(x[k] - __bfloat162float(h));
        ch |= (unsigned long long)__bfloat16_as_ushort(h) << (16 * k);
        cl |= (unsigned long long)__bfloat16_as_ushort(l) << (16 * k);
    }
    *(unsigned long long*)(g_Ch + i) = ch;
    *(unsigned long long*)(g_Cl + i) = cl;
}

// ---------------- R7-proven 128x128 mainloop (used by gemm_out) ----------------
#define OTILEB (128u * ROWB)              // 9216
#define OSTAGEB (4u * OTILEB)             // 36864
#define SMEM_GO (2u * OSTAGEB)            // 73728
#define OOFF_AH(s) ((unsigned)(s) * OSTAGEB)
#define OOFF_AL(s) (OOFF_AH(s) + OTILEB)
#define OOFF_BH(s) (OOFF_AH(s) + 2u * OTILEB)
#define OOFF_BL(s) (OOFF_AH(s) + 3u * OTILEB)

template<int LD, int NCH>
__device__ __forceinline__ void mma_mainloop(
    const __nv_bfloat16* __restrict__ Ahp, const __nv_bfloat16* __restrict__ Alp,
    const __nv_bfloat16* __restrict__ Bhp, const __nv_bfloat16* __restrict__ Blp,
    int iBase, int jBase, char* sm, unsigned sb, float (&acc)[2][8][4]) {

    const int tid  = threadIdx.x;
    const int warp = tid >> 5;
    const int lane = tid & 31;
    const int g = lane >> 2, t = lane & 3;
    const int wM = (warp >> 1) * 32;
    const int wN = (warp & 1) * 64;

    #pragma unroll
    for (int mt = 0; mt < 2; ++mt)
        #pragma unroll
        for (int nt = 0; nt < 8; ++nt)
            #pragma unroll
            for (int q = 0; q < 4; ++q) acc[mt][nt][q] = 0.0f;

    auto fill = [&](int chunk, int stg) {
        const unsigned kb = (unsigned)chunk * 32u;
        #pragma unroll
        for (int i = 0; i < 4; ++i) {
            int c = tid + i * 256;
            int row = c >> 3, sub = c & 7;
            unsigned so = (unsigned)row * ROWB + (unsigned)sub * 8u;
            size_t ga = (size_t)(iBase + row) * LD + kb + sub * 4;
            size_t gb = (size_t)(jBase + row) * LD + kb + sub * 4;
            CP_ASYNC8(sb + OOFF_AH(stg) + so, (const char*)(Ahp + ga));
            CP_ASYNC8(sb + OOFF_AL(stg) + so, (const char*)(Alp + ga));
            CP_ASYNC8(sb + OOFF_BH(stg) + so, (const char*)(Bhp + gb));
            CP_ASYNC8(sb + OOFF_BL(stg) + so, (const char*)(Blp + gb));
        }
        CP_COMMIT();
    };

    fill(0, 0);

    for (int c = 0; c < NCH; ++c) {
        const int s = c & 1;
        if (c + 1 < NCH) { fill(c + 1, s ^ 1); CP_WAIT(1); }
        else             { CP_WAIT(0); }
        __syncthreads();

        const char* pAH = sm + OOFF_AH(s);
        const char* pAL = sm + OOFF_AL(s);
        const char* pBH = sm + OOFF_BH(s);
        const char* pBL = sm + OOFF_BL(s);

        #pragma unroll
        for (int ks = 0; ks < 2; ++ks) {
            unsigned ah[2][4], al[2][4], bh[8][2], bl[8][2];
            const unsigned colb = (unsigned)(ks * 32 + t * 4);
            #pragma unroll
            for (int mt = 0; mt < 2; ++mt) {
                unsigned o0 = (unsigned)(wM + mt * 16 + g) * ROWB + colb;
                unsigned o1 = o0 + 8u * ROWB;
                ah[mt][0] = *(const unsigned*)(pAH + o0);
                ah[mt][1] = *(const unsigned*)(pAH + o1);
                ah[mt][2] = *(const unsigned*)(pAH + o0 + 16u);
                ah[mt][3] = *(const unsigned*)(pAH + o1 + 16u);
                al[mt][0] = *(const unsigned*)(pAL + o0);
                al[mt][1] = *(const unsigned*)(pAL + o1);
                al[mt][2] = *(const unsigned*)(pAL + o0 + 16u);
                al[mt][3] = *(const unsigned*)(pAL + o1 + 16u);
            }
            #pragma unroll
            for (int nt = 0; nt < 8; ++nt) {
                unsigned ob = (unsigned)(wN + nt * 8 + g) * ROWB + colb;
                bh[nt][0] = *(const unsigned*)(pBH + ob);
                bh[nt][1] = *(const unsigned*)(pBH + ob + 16u);
                bl[nt][0] = *(const unsigned*)(pBL + ob);
                bl[nt][1] = *(const unsigned*)(pBL + ob + 16u);
            }
            #pragma unroll
            for (int mt = 0; mt < 2; ++mt)
                #pragma unroll
                for (int nt = 0; nt < 8; ++nt) {
                    MMA_BF16(acc[mt][nt], ah[mt], bh[nt]);
                    MMA_BF16(acc[mt][nt], ah[mt], bl[nt]);
                    MMA_BF16(acc[mt][nt], al[mt], bh[nt]);
                }
        }
        __syncthreads();
    }
}

// ---------------- K3: ret = A_comb @ HW + bias (tensorized) ----------------
__global__ __launch_bounds__(256) void gemm_out_mma_kernel(
    const float* __restrict__ bias, float* __restrict__ out) {
    extern __shared__ char sm[];
    const unsigned sb = smem_u32(sm);
    const int warp = threadIdx.x >> 5;
    const int lane = threadIdx.x & 31;
    const int g = lane >> 2, t = lane & 3;
    const int iBase = blockIdx.y * 128;
    const int jBase = blockIdx.x * 128;
    const int wM = (warp >> 1) * 32;
    const int wN = (warp & 1) * 64;

    float acc[2][8][4];
    mma_mainloop<NN_NODES, NN_NODES / 32>(g_Ch, g_Cl, g_HWth, g_HWtl, iBase, jBase, sm, sb, acc);

    #pragma unroll
    for (int mt = 0; mt < 2; ++mt) {
        int gi0 = iBase + wM + mt * 16 + g;
        float* d0 = out + (size_t)gi0 * DIM_OUT;
        float* d1 = d0 + 8u * DIM_OUT;
        #pragma unroll
        for (int nt = 0; nt < 8; ++nt) {
            int gj = jBase + wN + nt * 8 + t * 2;
            float2 bs = *(const float2*)(bias + gj);
            *(float2*)(d0 + gj) = make_float2(acc[mt][nt][0] + bs.x, acc[mt][nt][1] + bs.y);
            *(float2*)(d1 + gj) = make_float2(acc[mt][nt][2] + bs.x, acc[mt][nt][3] + bs.y);
        }
    }
}

// ---------------- SIMT GEMM for HW = H_v @ W ----------------
__global__ __launch_bounds__(256, 2) void gemm_hw_kernel(
    const float* __restrict__ A, const float* __restrict__ B) {
    __shared__ __align__(16) float As[2][8][128];
    __shared__ __align__(16) float Bs[2][8][128];

    const int Nn = DIM_OUT, K = DIM_V;
    const int tid = threadIdx.x;
    const int iBase = blockIdx.y * 128;
    const int jBase = blockIdx.x * 128;

    const int lrow = tid >> 1;
    const int kq   = (tid & 1) * 4;
    const float* Aptr = A + (size_t)(iBase + lrow) * K + kq;
    const int bk = tid >> 5;
    const int bn = (tid & 31) * 4;
    const float* Bptr = B + (size_t)bk * Nn + jBase + bn;

    unsigned long long acc[8][4];
    #pragma unroll
    for (int r = 0; r < 8; ++r)
        #pragma unroll
        for (int c = 0; c < 4; ++c) acc[r][c] = 0ull;

    {
        float4 a = *(const float4*)Aptr;
        float4 b = *(const float4*)Bptr;
        As[0][kq + 0][lrow] = a.x; As[0][kq + 1][lrow] = a.y;
        As[0][kq + 2][lrow] = a.z; As[0][kq + 3][lrow] = a.w;
        *(float4*)&Bs[0][bk][bn] = b;
    }
    __syncthreads();

    const int tx = (tid & 15) * 8;
    const int ty = (tid >> 4) * 8;
    int buf = 0;
    const int KT = K / 8;

    for (int kt = 0; kt < KT; ++kt) {
        float4 aN, bN;
        if (kt + 1 < KT) {
            aN = *(const float4*)(Aptr + (size_t)(kt + 1) * 8);
            bN = *(const float4*)(Bptr + (size_t)(kt + 1) * 8 * Nn);
        }
        #pragma unroll
        for (int kk = 0; kk < 8; ++kk) {
            float4 a0 = *(const float4*)&As[buf][kk][ty];
            float4 a1 = *(const float4*)&As[buf][kk][ty + 4];
            ulonglong2 b0 = *(const ulonglong2*)&Bs[buf][kk][tx];
            ulonglong2 b1 = *(const ulonglong2*)&Bs[buf][kk][tx + 4];
            float av[8] = {a0.x, a0.y, a0.z, a0.w, a1.x, a1.y, a1.z, a1.w};
            unsigned long long bv[4] = {b0.x, b0.y, b1.x, b1.y};
            #pragma unroll
            for (int r = 0; r < 8; ++r) {
                unsigned long long aa = pack2(av[r], av[r]);
                #pragma unroll
                for (int c = 0; c < 4; ++c) ffma2(acc[r][c], aa, bv[c]);
            }
        }
        if (kt + 1 < KT) {
            int nb = buf ^ 1;
            As[nb][kq + 0][lrow] = aN.x; As[nb][kq + 1][lrow] = aN.y;
            As[nb][kq + 2][lrow] = aN.z; As[nb][kq + 3][lrow] = aN.w;
            *(float4*)&Bs[nb][bk][bn] = bN;
            __syncthreads();
            buf = nb;
        }
    }

    #pragma unroll
    for (int r = 0; r < 8; ++r) {
        int gi = iBase + ty + r;
        float* dst = g_HW + (size_t)gi * Nn;
        #pragma unroll
        for (int c = 0; c < 4; ++c) {
            int gj = jBase + tx + c * 2;
            float2 v = unpack2(acc[r][c]);
            *(float2*)&dst[gj] = v;
        }
    }
}

// ---------------- transpose + split: HW [4096,512] -> HW^T hi/lo [512,4096] ----------------
__global__ void hw_transpose_split_kernel() {
    __shared__ float tile[32][33];
    const int tx = threadIdx.x, ty = threadIdx.y;
    const int nb = blockIdx.x * 32;
    const int kb = blockIdx.y * 32;
    #pragma unroll
    for (int i = 0; i < 4; ++i) {
        int k = kb + ty + i * 8;
        tile[ty + i * 8][tx] = g_HW[(size_t)k * DIM_OUT + nb + tx];
    }
    __syncthreads();
    #pragma unroll
    for (int i = 0; i < 4; ++i) {
        int n = nb + ty + i * 8;
        int k = kb + tx;
        float v = tile[tx][ty + i * 8];
        __nv_bfloat16 h = __float2bfloat16(v);
        g_HWth[(size_t)n * NN_NODES + k] = h;
        g_HWtl[(size_t)n * NN_NODES + k] = __float2bfloat16(v - __bfloat162float(h));
    }
}

extern "C" void kernel_launch(void* const* d_in, const int* in_sizes, int n_in,
                              void* d_out, int out_size) {
    const float* H_v    = (const float*)d_in[0];
    const float* H_e    = (const float*)d_in[1];
    const float* adj_v  = (const float*)d_in[3];
    const float* T      = (const float*)d_in[4];
    const float* weight = (const float*)d_in[5];
    const float* p      = (const float*)d_in[6];
    const float* bias   = (const float*)d_in[7];
    float* out = (float*)d_out;
    (void)in_sizes; (void)n_in;

    cudaFuncSetAttribute(gemm1_mma_kernel,
                         cudaFuncAttributeMaxDynamicSharedMemorySize, SMEM_G1);
    cudaFuncSetAttribute(gemm_out_mma_kernel,
                         cudaFuncAttributeMaxDynamicSharedMemorySize, SMEM_GO);

    // K0: edge scaling vector
    escale_kernel<<<NN_EDGES / 8, dim3(32, 8)>>>(H_e, p);

    // K-split: bf16 hi/lo operand prep (depends on K0)
    split_kernel<<<(NN_NODES * NN_EDGES) / (256 * 4), 256>>>(T);

    // K1: HW = H_v @ W, then transpose+split for the tensorized output GEMM
    gemm_hw_kernel<<<dim3(DIM_OUT / 128, NN_NODES / 128), 256>>>(H_v, weight);
    hw_transpose_split_kernel<<<dim3(DIM_OUT / 32, NN_NODES / 32), dim3(32, 8)>>>();

    // K2: dominant GEMM — 256x128 tiles, triangular super-blocks, mirrored epilogue
    gemm1_mma_kernel<<<272, 256, SMEM_G1>>>(adj_v);

    // A_comb -> bf16 hi/lo for the tensorized output GEMM
    acomb_split_kernel<<<(size_t)NN_NODES * NN_NODES / (256 * 4), 256>>>();

    // K3: ret = A_comb @ HW + bias (tensorized)
    gemm_out_mma_kernel<<<dim3(DIM_OUT / 128, NN_NODES / 128), 256, SMEM_GO>>>(bias, out);

    const size_t ret_elems = (size_t)NN_NODES * DIM_OUT;
    const size_t he_elems  = (size_t)NN_EDGES * DIM_E;
    if ((size_t)out_size >= ret_elems + he_elems) {
        cudaMemcpyAsync(out + ret_elems, H_e, he_elems * sizeof(float),
                        cudaMemcpyDeviceToDevice);
    }
}

// round 10
// speedup vs baseline: 2.7611x; 1.4154x over previous
#include <cuda_runtime.h>
#include <cuda_bf16.h>
#include <cuda_fp16.h>

// Problem constants
#define NN_NODES 4096
#define NN_EDGES 8192
#define DIM_V    512
#define DIM_OUT  512
#define DIM_E    128

// ---------------- scratch (device globals; no allocation allowed) ----------------
__device__ float g_e_scale[NN_EDGES];
__device__ float g_Acomb[(size_t)NN_NODES * NN_NODES];            // 64 MB fp32
__device__ float g_HW[(size_t)NN_NODES * DIM_OUT];                //  8 MB fp32
__device__ __half g_Ah[(size_t)NN_NODES * NN_EDGES];              // 64 MB (fp16 hi of T*e)
__device__ __half g_Bh[(size_t)NN_NODES * NN_EDGES];              // 64 MB (fp16 hi of T)
__device__ __half g_Bl[(size_t)NN_NODES * NN_EDGES];              // 64 MB (fp16 lo of T)
__device__ __nv_bfloat16 g_Ch[(size_t)NN_NODES * NN_NODES];       // 32 MB (A_comb hi)
__device__ __nv_bfloat16 g_Cl[(size_t)NN_NODES * NN_NODES];       // 32 MB (A_comb lo)
__device__ __nv_bfloat16 g_HWth[(size_t)DIM_OUT * NN_NODES];      //  4 MB (HW^T hi)
__device__ __nv_bfloat16 g_HWtl[(size_t)DIM_OUT * NN_NODES];      //  4 MB (HW^T lo)

// ---------------- PTX helpers (non-'a' features only) ----------------
__device__ __forceinline__ unsigned smem_u32(const void* p) {
    unsigned a;
    asm("{ .reg .u64 t; cvta.to.shared.u64 t, %1; cvt.u32.u64 %0, t; }" : "=r"(a) : "l"(p));
    return a;
}
#define CP_ASYNC8(dst, src) \
    asm volatile("cp.async.ca.shared.global [%0], [%1], 8;" :: "r"(dst), "l"(src) : "memory")
#define CP_COMMIT() asm volatile("cp.async.commit_group;" ::: "memory")
#define CP_WAIT(n)  asm volatile("cp.async.wait_group %0;" :: "n"(n) : "memory")

#define MMA_BF16(acc, A, B) \
    asm volatile("mma.sync.aligned.m16n8k16.row.col.f32.bf16.bf16.f32 " \
                 "{%0,%1,%2,%3},{%4,%5,%6,%7},{%8,%9},{%0,%1,%2,%3};" \
                 : "+f"((acc)[0]), "+f"((acc)[1]), "+f"((acc)[2]), "+f"((acc)[3]) \
                 : "r"((A)[0]), "r"((A)[1]), "r"((A)[2]), "r"((A)[3]), \
                   "r"((B)[0]), "r"((B)[1]))

#define MMA_FP16(acc, A, B) \
    asm volatile("mma.sync.aligned.m16n8k16.row.col.f32.f16.f16.f32 " \
                 "{%0,%1,%2,%3},{%4,%5,%6,%7},{%8,%9},{%0,%1,%2,%3};" \
                 : "+f"((acc)[0]), "+f"((acc)[1]), "+f"((acc)[2]), "+f"((acc)[3]) \
                 : "r"((A)[0]), "r"((A)[1]), "r"((A)[2]), "r"((A)[3]), \
                   "r"((B)[0]), "r"((B)[1]))

// ---------------- packed f32x2 helpers (SIMT GEMM) ----------------
__device__ __forceinline__ void ffma2(unsigned long long& d,
                                      unsigned long long a,
                                      unsigned long long b) {
    asm("fma.rn.f32x2 %0, %1, %2, %0;" : "+l"(d) : "l"(a), "l"(b));
}
__device__ __forceinline__ unsigned long long pack2(float x, float y) {
    unsigned long long r;
    asm("mov.b64 %0, {%1, %2};" : "=l"(r) : "f"(x), "f"(y));
    return r;
}
__device__ __forceinline__ float2 unpack2(unsigned long long v) {
    float2 f;
    asm("mov.b64 {%0, %1}, %2;" : "=f"(f.x), "=f"(f.y) : "l"(v));
    return f;
}

// ---------------- K0: e_scale[e] = dot(H_e[e,:], p) ----------------
__global__ void escale_kernel(const float* __restrict__ He,
                              const float* __restrict__ p) {
    int row  = blockIdx.x * 8 + threadIdx.y;
    int lane = threadIdx.x;
    float4 h  = ((const float4*)(He + (size_t)row * DIM_E))[lane];
    float4 pv = ((const float4*)p)[lane];
    float v = h.x * pv.x + h.y * pv.y + h.z * pv.z + h.w * pv.w;
    #pragma unroll
    for (int o = 16; o; o >>= 1) v += __shfl_xor_sync(0xffffffffu, v, o);
    if (lane == 0) g_e_scale[row] = v;
}

// ------- K-split: T -> fp16 (Bh,Bl);  T*e -> fp16 Ah (lo of A dropped) -------
__global__ __launch_bounds__(256) void split_kernel(const float* __restrict__ T) {
    size_t i = ((size_t)blockIdx.x * 256 + threadIdx.x) * 4;
    unsigned col = (unsigned)(i & (NN_EDGES - 1));
    float4 t = *(const float4*)(T + i);
    float4 e = *(const float4*)(g_e_scale + col);

    float b[4] = {t.x, t.y, t.z, t.w};
    float a[4] = {t.x * e.x, t.y * e.y, t.z * e.z, t.w * e.w};

    unsigned long long ah = 0, bh = 0, bl = 0;
    #pragma unroll
    for (int k = 0; k < 4; ++k) {
        __half hb = __float2half_rn(b[k]);
        __half lb = __float2half_rn(b[k] - __half2float(hb));
        __half ha = __float2half_rn(a[k]);
        bh |= (unsigned long long)__half_as_ushort(hb) << (16 * k);
        bl |= (unsigned long long)__half_as_ushort(lb) << (16 * k);
        ah |= (unsigned long long)__half_as_ushort(ha) << (16 * k);
    }
    *(unsigned long long*)(g_Bh + i) = bh;
    *(unsigned long long*)(g_Bl + i) = bl;
    *(unsigned long long*)(g_Ah + i) = ah;
}

// ========== K2: GEMM1 fp16 2-product, CTA tile 256x128, warp tile 64x64 ==========
#define ROWB 72u
#define A_ROWS 256
#define B_ROWS 128
#define ATILEB (A_ROWS * ROWB)                // 18432 (A hi only)
#define BTILEB (B_ROWS * ROWB)                //  9216
#define STAGEB2 (ATILEB + 2u * BTILEB)        // 36864
#define SMEM_G1 (2u * STAGEB2)                // 73728
#define OFF2_AH(s) ((unsigned)(s) * STAGEB2)
#define OFF2_BH(s) (OFF2_AH(s) + ATILEB)
#define OFF2_BL(s) (OFF2_AH(s) + ATILEB + BTILEB)
#define NCH_G1 (NN_EDGES / 32)                // 256
#define TS_LDC 132

__global__ __launch_bounds__(256) void gemm1_mma_kernel(const float* __restrict__ adj_v) {
    extern __shared__ char sm[];
    const unsigned sb = smem_u32(sm);
    const int tid  = threadIdx.x;
    const int warp = tid >> 5;
    const int lane = tid & 31;
    const int g = lane >> 2, t = lane & 3;
    const int wM = (warp >> 1) * 64;
    const int wN = (warp & 1) * 64;

    // bid -> (BI, bj): BI = 256-row super-block (0..15), bj = 128-col block >= 2*BI
    int r = (int)blockIdx.x, BI = 0;
    while (r >= 32 - 2 * BI) { r -= 32 - 2 * BI; ++BI; }
    const int bj = 2 * BI + r;
    const int iBase = BI * 256;
    const int jBase = bj * 128;

    float acc[4][8][4];
    #pragma unroll
    for (int mt = 0; mt < 4; ++mt)
        #pragma unroll
        for (int nt = 0; nt < 8; ++nt)
            #pragma unroll
            for (int q = 0; q < 4; ++q) acc[mt][nt][q] = 0.0f;

    auto fill = [&](int chunk, int stg) {
        const unsigned kb = (unsigned)chunk * 32u;
        #pragma unroll
        for (int i = 0; i < 8; ++i) {                 // A hi: 256 rows x 8 segs
            int c = tid + i * 256;
            int row = c >> 3, sub = c & 7;
            unsigned so = (unsigned)row * ROWB + (unsigned)sub * 8u;
            size_t ga = (size_t)(iBase + row) * NN_EDGES + kb + sub * 4;
            CP_ASYNC8(sb + OFF2_AH(stg) + so, (const char*)(g_Ah + ga));
        }
        #pragma unroll
        for (int i = 0; i < 4; ++i) {                 // B hi/lo: 128 rows x 8 segs
            int c = tid + i * 256;
            int row = c >> 3, sub = c & 7;
            unsigned so = (unsigned)row * ROWB + (unsigned)sub * 8u;
            size_t gb = (size_t)(jBase + row) * NN_EDGES + kb + sub * 4;
            CP_ASYNC8(sb + OFF2_BH(stg) + so, (const char*)(g_Bh + gb));
            CP_ASYNC8(sb + OFF2_BL(stg) + so, (const char*)(g_Bl + gb));
        }
        CP_COMMIT();
    };

    fill(0, 0);

    for (int c = 0; c < NCH_G1; ++c) {
        const int s = c & 1;
        if (c + 1 < NCH_G1) { fill(c + 1, s ^ 1); CP_WAIT(1); }
        else                { CP_WAIT(0); }
        __syncthreads();

        const char* pAH = sm + OFF2_AH(s);
        const char* pBH = sm + OFF2_BH(s);
        const char* pBL = sm + OFF2_BL(s);

        #pragma unroll
        for (int ks = 0; ks < 2; ++ks) {
            const unsigned colb = (unsigned)(ks * 32 + t * 4);
            unsigned ah[4][4];
            #pragma unroll
            for (int mt = 0; mt < 4; ++mt) {
                unsigned o0 = (unsigned)(wM + mt * 16 + g) * ROWB + colb;
                unsigned o1 = o0 + 8u * ROWB;
                ah[mt][0] = *(const unsigned*)(pAH + o0);
                ah[mt][1] = *(const unsigned*)(pAH + o1);
                ah[mt][2] = *(const unsigned*)(pAH + o0 + 16u);
                ah[mt][3] = *(const unsigned*)(pAH + o1 + 16u);
            }
            #pragma unroll
            for (int nt = 0; nt < 8; ++nt) {
                unsigned bh[2], bl[2];
                unsigned ob = (unsigned)(wN + nt * 8 + g) * ROWB + colb;
                bh[0] = *(const unsigned*)(pBH + ob);
                bh[1] = *(const unsigned*)(pBH + ob + 16u);
                bl[0] = *(const unsigned*)(pBL + ob);
                bl[1] = *(const unsigned*)(pBL + ob + 16u);
                #pragma unroll
                for (int mt = 0; mt < 4; ++mt) {
                    MMA_FP16(acc[mt][nt], ah[mt], bh);
                    MMA_FP16(acc[mt][nt], ah[mt], bl);
                }
            }
        }
        __syncthreads();
    }

    // -------- direct epilogue: A_comb[i,j] for halves on/above diagonal --------
    #pragma unroll
    for (int mt = 0; mt < 4; ++mt) {
        const int roff = wM + mt * 16 + g;
        const int h = roff >> 7;
        if (h == 1 && bj == 2 * BI) continue;
        const int gi0 = iBase + roff;
        const float* adj0 = adj_v + (size_t)gi0 * NN_NODES;
        const float* adj1 = adj0 + 8u * NN_NODES;
        float* d0 = g_Acomb + (size_t)gi0 * NN_NODES;
        float* d1 = d0 + 8u * NN_NODES;
        #pragma unroll
        for (int nt = 0; nt < 8; ++nt) {
            int gj = jBase + wN + nt * 8 + t * 2;
            float2 a0 = *(const float2*)(adj0 + gj);
            float2 a1 = *(const float2*)(adj1 + gj);
            float2 o0, o1;
            o0.x = (gi0 == gj)         ? a0.x : 0.5f * a0.x * (acc[mt][nt][0] + 1.0f);
            o0.y = (gi0 == gj + 1)     ? a0.y : 0.5f * a0.y * (acc[mt][nt][1] + 1.0f);
            o1.x = (gi0 + 8 == gj)     ? a1.x : 0.5f * a1.x * (acc[mt][nt][2] + 1.0f);
            o1.y = (gi0 + 8 == gj + 1) ? a1.y : 0.5f * a1.y * (acc[mt][nt][3] + 1.0f);
            *(float2*)(d0 + gj) = o0;
            *(float2*)(d1 + gj) = o1;
        }
    }

    // -------- mirrored epilogue per row-half h with 2*BI+h < bj --------
    float* TS = (float*)sm;
    #pragma unroll
    for (int h = 0; h < 2; ++h) {
        if (2 * BI + h >= bj) continue;
        __syncthreads();
        if ((wM >> 7) == h) {
            const int ibase_loc = wM & 127;
            #pragma unroll
            for (int mt = 0; mt < 4; ++mt) {
                int ii = ibase_loc + mt * 16 + g;
                #pragma unroll
                for (int nt = 0; nt < 8; ++nt) {
                    int jj = wN + nt * 8 + t * 2;
                    TS[(jj)     * TS_LDC + ii]     = acc[mt][nt][0];
                    TS[(jj + 1) * TS_LDC + ii]     = acc[mt][nt][1];
                    TS[(jj)     * TS_LDC + ii + 8] = acc[mt][nt][2];
                    TS[(jj + 1) * TS_LDC + ii + 8] = acc[mt][nt][3];
                }
            }
        }
        __syncthreads();

        const int jj  = tid >> 1;
        const int iiB = (tid & 1) * 64;
        const int gj  = jBase + jj;
        const int giB = iBase + h * 128 + iiB;
        const float* adjRow = adj_v + (size_t)gj * NN_NODES + giB;
        float* dst = g_Acomb + (size_t)gj * NN_NODES + giB;
        const float* tsRow = TS + jj * TS_LDC + iiB;
        #pragma unroll
        for (int q = 0; q < 16; ++q) {
            float4 a = *(const float4*)(adjRow + q * 4);
            float4 s4 = *(const float4*)(tsRow + q * 4);
            float4 o;
            o.x = 0.5f * a.x * (s4.x + 1.0f);
            o.y = 0.5f * a.y * (s4.y + 1.0f);
            o.z = 0.5f * a.z * (s4.z + 1.0f);
            o.w = 0.5f * a.w * (s4.w + 1.0f);
            *(float4*)(dst + q * 4) = o;
        }
    }
}

// ---------------- A_comb fp32 -> bf16 hi/lo split ----------------
__global__ __launch_bounds__(256) void acomb_split_kernel() {
    size_t i = ((size_t)blockIdx.x * 256 + threadIdx.x) * 4;
    float4 v = *(const float4*)(g_Acomb + i);
    float x[4] = {v.x, v.y, v.z, v.w};
    unsigned long long ch = 0, cl = 0;
    #pragma unroll
    for (int k = 0; k < 4; ++k) {
        __nv_bfloat16 h = __float2bfloat16(x[k]);
        __nv_bfloat16 l = __float2bfloat16(x[k] - __bfloat162float(h));
        ch |= (unsigned long long)__bfloat16_as_ushort(h) << (16 * k);
        cl |= (unsigned long long)__bfloat16_as_ushort(l) << (16 * k);
    }
    *(unsigned long long*)(g_Ch + i) = ch;
    *(unsigned long long*)(g_Cl + i) = cl;
}

// ---------------- bf16 3-product 128x128 mainloop (gemm_out) ----------------
#define OTILEB (128u * ROWB)              // 9216
#define OSTAGEB (4u * OTILEB)             // 36864
#define SMEM_GO (2u * OSTAGEB)            // 73728
#define OOFF_AH(s) ((unsigned)(s) * OSTAGEB)
#define OOFF_AL(s) (OOFF_AH(s) + OTILEB)
#define OOFF_BH(s) (OOFF_AH(s) + 2u * OTILEB)
#define OOFF_BL(s) (OOFF_AH(s) + 3u * OTILEB)

template<int LD, int NCH>
__device__ __forceinline__ void mma_mainloop(
    const __nv_bfloat16* __restrict__ Ahp, const __nv_bfloat16* __restrict__ Alp,
    const __nv_bfloat16* __restrict__ Bhp, const __nv_bfloat16* __restrict__ Blp,
    int iBase, int jBase, char* sm, unsigned sb, float (&acc)[2][8][4]) {

    const int tid  = threadIdx.x;
    const int warp = tid >> 5;
    const int lane = tid & 31;
    const int g = lane >> 2, t = lane & 3;
    const int wM = (warp >> 1) * 32;
    const int wN = (warp & 1) * 64;

    #pragma unroll
    for (int mt = 0; mt < 2; ++mt)
        #pragma unroll
        for (int nt = 0; nt < 8; ++nt)
            #pragma unroll
            for (int q = 0; q < 4; ++q) acc[mt][nt][q] = 0.0f;

    auto fill = [&](int chunk, int stg) {
        const unsigned kb = (unsigned)chunk * 32u;
        #pragma unroll
        for (int i = 0; i < 4; ++i) {
            int c = tid + i * 256;
            int row = c >> 3, sub = c & 7;
            unsigned so = (unsigned)row * ROWB + (unsigned)sub * 8u;
            size_t ga = (size_t)(iBase + row) * LD + kb + sub * 4;
            size_t gb = (size_t)(jBase + row) * LD + kb + sub * 4;
            CP_ASYNC8(sb + OOFF_AH(stg) + so, (const char*)(Ahp + ga));
            CP_ASYNC8(sb + OOFF_AL(stg) + so, (const char*)(Alp + ga));
            CP_ASYNC8(sb + OOFF_BH(stg) + so, (const char*)(Bhp + gb));
            CP_ASYNC8(sb + OOFF_BL(stg) + so, (const char*)(Blp + gb));
        }
        CP_COMMIT();
    };

    fill(0, 0);

    for (int c = 0; c < NCH; ++c) {
        const int s = c & 1;
        if (c + 1 < NCH) { fill(c + 1, s ^ 1); CP_WAIT(1); }
        else             { CP_WAIT(0); }
        __syncthreads();

        const char* pAH = sm + OOFF_AH(s);
        const char* pAL = sm + OOFF_AL(s);
        const char* pBH = sm + OOFF_BH(s);
        const char* pBL = sm + OOFF_BL(s);

        #pragma unroll
        for (int ks = 0; ks < 2; ++ks) {
            unsigned ah[2][4], al[2][4], bh[8][2], bl[8][2];
            const unsigned colb = (unsigned)(ks * 32 + t * 4);
            #pragma unroll
            for (int mt = 0; mt < 2; ++mt) {
                unsigned o0 = (unsigned)(wM + mt * 16 + g) * ROWB + colb;
                unsigned o1 = o0 + 8u * ROWB;
                ah[mt][0] = *(const unsigned*)(pAH + o0);
                ah[mt][1] = *(const unsigned*)(pAH + o1);
                ah[mt][2] = *(const unsigned*)(pAH + o0 + 16u);
                ah[mt][3] = *(const unsigned*)(pAH + o1 + 16u);
                al[mt][0] = *(const unsigned*)(pAL + o0);
                al[mt][1] = *(const unsigned*)(pAL + o1);
                al[mt][2] = *(const unsigned*)(pAL + o0 + 16u);
                al[mt][3] = *(const unsigned*)(pAL + o1 + 16u);
            }
            #pragma unroll
            for (int nt = 0; nt < 8; ++nt) {
                unsigned ob = (unsigned)(wN + nt * 8 + g) * ROWB + colb;
                bh[nt][0] = *(const unsigned*)(pBH + ob);
                bh[nt][1] = *(const unsigned*)(pBH + ob + 16u);
                bl[nt][0] = *(const unsigned*)(pBL + ob);
                bl[nt][1] = *(const unsigned*)(pBL + ob + 16u);
            }
            #pragma unroll
            for (int mt = 0; mt < 2; ++mt)
                #pragma unroll
                for (int nt = 0; nt < 8; ++nt) {
                    MMA_BF16(acc[mt][nt], ah[mt], bh[nt]);
                    MMA_BF16(acc[mt][nt], ah[mt], bl[nt]);
                    MMA_BF16(acc[mt][nt], al[mt], bh[nt]);
                }
        }
        __syncthreads();
    }
}

// ---------------- K3: ret = A_comb @ HW + bias (tensorized) ----------------
__global__ __launch_bounds__(256) void gemm_out_mma_kernel(
    const float* __restrict__ bias, float* __restrict__ out) {
    extern __shared__ char sm[];
    const unsigned sb = smem_u32(sm);
    const int warp = threadIdx.x >> 5;
    const int lane = threadIdx.x & 31;
    const int g = lane >> 2, t = lane & 3;
    const int iBase = blockIdx.y * 128;
    const int jBase = blockIdx.x * 128;
    const int wM = (warp >> 1) * 32;
    const int wN = (warp & 1) * 64;

    float acc[2][8][4];
    mma_mainloop<NN_NODES, NN_NODES / 32>(g_Ch, g_Cl, g_HWth, g_HWtl, iBase, jBase, sm, sb, acc);

    #pragma unroll
    for (int mt = 0; mt < 2; ++mt) {
        int gi0 = iBase + wM + mt * 16 + g;
        float* d0 = out + (size_t)gi0 * DIM_OUT;
        float* d1 = d0 + 8u * DIM_OUT;
        #pragma unroll
        for (int nt = 0; nt < 8; ++nt) {
            int gj = jBase + wN + nt * 8 + t * 2;
            float2 bs = *(const float2*)(bias + gj);
            *(float2*)(d0 + gj) = make_float2(acc[mt][nt][0] + bs.x, acc[mt][nt][1] + bs.y);
            *(float2*)(d1 + gj) = make_float2(acc[mt][nt][2] + bs.x, acc[mt][nt][3] + bs.y);
        }
    }
}

// ---------------- SIMT GEMM for HW = H_v @ W ----------------
__global__ __launch_bounds__(256, 2) void gemm_hw_kernel(
    const float* __restrict__ A, const float* __restrict__ B) {
    __shared__ __align__(16) float As[2][8][128];
    __shared__ __align__(16) float Bs[2][8][128];

    const int Nn = DIM_OUT, K = DIM_V;
    const int tid = threadIdx.x;
    const int iBase = blockIdx.y * 128;
    const int jBase = blockIdx.x * 128;

    const int lrow = tid >> 1;
    const int kq   = (tid & 1) * 4;
    const float* Aptr = A + (size_t)(iBase + lrow) * K + kq;
    const int bk = tid >> 5;
    const int bn = (tid & 31) * 4;
    const float* Bptr = B + (size_t)bk * Nn + jBase + bn;

    unsigned long long acc[8][4];
    #pragma unroll
    for (int r = 0; r < 8; ++r)
        #pragma unroll
        for (int c = 0; c < 4; ++c) acc[r][c] = 0ull;

    {
        float4 a = *(const float4*)Aptr;
        float4 b = *(const float4*)Bptr;
        As[0][kq + 0][lrow] = a.x; As[0][kq + 1][lrow] = a.y;
        As[0][kq + 2][lrow] = a.z; As[0][kq + 3][lrow] = a.w;
        *(float4*)&Bs[0][bk][bn] = b;
    }
    __syncthreads();

    const int tx = (tid & 15) * 8;
    const int ty = (tid >> 4) * 8;
    int buf = 0;
    const int KT = K / 8;

    for (int kt = 0; kt < KT; ++kt) {
        float4 aN, bN;
        if (kt + 1 < KT) {
            aN = *(const float4*)(Aptr + (size_t)(kt + 1) * 8);
            bN = *(const float4*)(Bptr + (size_t)(kt + 1) * 8 * Nn);
        }
        #pragma unroll
        for (int kk = 0; kk < 8; ++kk) {
            float4 a0 = *(const float4*)&As[buf][kk][ty];
            float4 a1 = *(const float4*)&As[buf][kk][ty + 4];
            ulonglong2 b0 = *(const ulonglong2*)&Bs[buf][kk][tx];
            ulonglong2 b1 = *(const ulonglong2*)&Bs[buf][kk][tx + 4];
            float av[8] = {a0.x, a0.y, a0.z, a0.w, a1.x, a1.y, a1.z, a1.w};
            unsigned long long bv[4] = {b0.x, b0.y, b1.x, b1.y};
            #pragma unroll
            for (int r = 0; r < 8; ++r) {
                unsigned long long aa = pack2(av[r], av[r]);
                #pragma unroll
                for (int c = 0; c < 4; ++c) ffma2(acc[r][c], aa, bv[c]);
            }
        }
        if (kt + 1 < KT) {
            int nb = buf ^ 1;
            As[nb][kq + 0][lrow] = aN.x; As[nb][kq + 1][lrow] = aN.y;
            As[nb][kq + 2][lrow] = aN.z; As[nb][kq + 3][lrow] = aN.w;
            *(float4*)&Bs[nb][bk][bn] = bN;
            __syncthreads();
            buf = nb;
        }
    }

    #pragma unroll
    for (int r = 0; r < 8; ++r) {
        int gi = iBase + ty + r;
        float* dst = g_HW + (size_t)gi * Nn;
        #pragma unroll
        for (int c = 0; c < 4; ++c) {
            int gj = jBase + tx + c * 2;
            float2 v = unpack2(acc[r][c]);
            *(float2*)&dst[gj] = v;
        }
    }
}

// ---------------- transpose + split: HW [4096,512] -> HW^T hi/lo [512,4096] ----------------
__global__ void hw_transpose_split_kernel() {
    __shared__ float tile[32][33];
    const int tx = threadIdx.x, ty = threadIdx.y;
    const int nb = blockIdx.x * 32;
    const int kb = blockIdx.y * 32;
    #pragma unroll
    for (int i = 0; i < 4; ++i) {
        int k = kb + ty + i * 8;
        tile[ty + i * 8][tx] = g_HW[(size_t)k * DIM_OUT + nb + tx];
    }
    __syncthreads();
    #pragma unroll
    for (int i = 0; i < 4; ++i) {
        int n = nb + ty + i * 8;
        int k = kb + tx;
        float v = tile[tx][ty + i * 8];
        __nv_bfloat16 h = __float2bfloat16(v);
        g_HWth[(size_t)n * NN_NODES + k] = h;
        g_HWtl[(size_t)n * NN_NODES + k] = __float2bfloat16(v - __bfloat162float(h));
    }
}

extern "C" void kernel_launch(void* const* d_in, const int* in_sizes, int n_in,
                              void* d_out, int out_size) {
    const float* H_v    = (const float*)d_in[0];
    const float* H_e    = (const float*)d_in[1];
    const float* adj_v  = (const float*)d_in[3];
    const float* T      = (const float*)d_in[4];
    const float* weight = (const float*)d_in[5];
    const float* p      = (const float*)d_in[6];
    const float* bias   = (const float*)d_in[7];
    float* out = (float*)d_out;
    (void)in_sizes; (void)n_in;

    cudaFuncSetAttribute(gemm1_mma_kernel,
                         cudaFuncAttributeMaxDynamicSharedMemorySize, SMEM_G1);
    cudaFuncSetAttribute(gemm_out_mma_kernel,
                         cudaFuncAttributeMaxDynamicSharedMemorySize, SMEM_GO);

    // K0: edge scaling vector
    escale_kernel<<<NN_EDGES / 8, dim3(32, 8)>>>(H_e, p);

    // K-split: fp16 operand prep (depends on K0)
    split_kernel<<<(NN_NODES * NN_EDGES) / (256 * 4), 256>>>(T);

    // K1: HW = H_v @ W
    gemm_hw_kernel<<<dim3(DIM_OUT / 128, NN_NODES / 128), 256>>>(H_v, weight);

    // K2 (4th launch — lands in the ncu profiling slot): dominant GEMM,
    // fp16 2-product, 256x128 tiles, triangular super-blocks, mirrored epilogue
    gemm1_mma_kernel<<<272, 256, SMEM_G1>>>(adj_v);

    // HW transpose+split for the tensorized output GEMM (indep of gemm1)
    hw_transpose_split_kernel<<<dim3(DIM_OUT / 32, NN_NODES / 32), dim3(32, 8)>>>();

    // A_comb -> bf16 hi/lo
    acomb_split_kernel<<<(size_t)NN_NODES * NN_NODES / (256 * 4), 256>>>();

    // K3: ret = A_comb @ HW + bias (tensorized)
    gemm_out_mma_kernel<<<dim3(DIM_OUT / 128, NN_NODES / 128), 256, SMEM_GO>>>(bias, out);

    const size_t ret_elems = (size_t)NN_NODES * DIM_OUT;
    const size_t he_elems  = (size_t)NN_EDGES * DIM_E;
    if ((size_t)out_size >= ret_elems + he_elems) {
        cudaMemcpyAsync(out + ret_elems, H_e, he_elems * sizeof(float),
                        cudaMemcpyDeviceToDevice);
    }
}

// round 11
// speedup vs baseline: 3.6756x; 1.3312x over previous
#include <cuda_runtime.h>
#include <cuda_bf16.h>
#include <cuda_fp16.h>

// Problem constants
#define NN_NODES 4096
#define NN_EDGES 8192
#define DIM_V    512
#define DIM_OUT  512
#define DIM_E    128

// ---------------- scratch (device globals; no allocation allowed) ----------------
__device__ float g_e_scale[NN_EDGES];
__device__ float g_Acomb[(size_t)NN_NODES * NN_NODES];            // 64 MB fp32
__device__ float g_HW[(size_t)NN_NODES * DIM_OUT];                //  8 MB fp32
__device__ __half g_Ah[(size_t)NN_NODES * NN_EDGES];              // 64 MB (fp16 of T*e)
__device__ __half g_Bh[(size_t)NN_NODES * NN_EDGES];              // 64 MB (fp16 of T)
__device__ __nv_bfloat16 g_Ch[(size_t)NN_NODES * NN_NODES];       // 32 MB (A_comb hi)
__device__ __nv_bfloat16 g_Cl[(size_t)NN_NODES * NN_NODES];       // 32 MB (A_comb lo)
__device__ __nv_bfloat16 g_HWth[(size_t)DIM_OUT * NN_NODES];      //  4 MB (HW^T hi)
__device__ __nv_bfloat16 g_HWtl[(size_t)DIM_OUT * NN_NODES];      //  4 MB (HW^T lo)

// ---------------- PTX helpers (non-'a' features only) ----------------
__device__ __forceinline__ unsigned smem_u32(const void* p) {
    unsigned a;
    asm("{ .reg .u64 t; cvta.to.shared.u64 t, %1; cvt.u32.u64 %0, t; }" : "=r"(a) : "l"(p));
    return a;
}
#define CP_ASYNC8(dst, src) \
    asm volatile("cp.async.ca.shared.global [%0], [%1], 8;" :: "r"(dst), "l"(src) : "memory")
#define CP_COMMIT() asm volatile("cp.async.commit_group;" ::: "memory")
#define CP_WAIT(n)  asm volatile("cp.async.wait_group %0;" :: "n"(n) : "memory")

#define MMA_BF16(acc, A, B) \
    asm volatile("mma.sync.aligned.m16n8k16.row.col.f32.bf16.bf16.f32 " \
                 "{%0,%1,%2,%3},{%4,%5,%6,%7},{%8,%9},{%0,%1,%2,%3};" \
                 : "+f"((acc)[0]), "+f"((acc)[1]), "+f"((acc)[2]), "+f"((acc)[3]) \
                 : "r"((A)[0]), "r"((A)[1]), "r"((A)[2]), "r"((A)[3]), \
                   "r"((B)[0]), "r"((B)[1]))

#define MMA_FP16(acc, A, B) \
    asm volatile("mma.sync.aligned.m16n8k16.row.col.f32.f16.f16.f32 " \
                 "{%0,%1,%2,%3},{%4,%5,%6,%7},{%8,%9},{%0,%1,%2,%3};" \
                 : "+f"((acc)[0]), "+f"((acc)[1]), "+f"((acc)[2]), "+f"((acc)[3]) \
                 : "r"((A)[0]), "r"((A)[1]), "r"((A)[2]), "r"((A)[3]), \
                   "r"((B)[0]), "r"((B)[1]))

// ---------------- packed f32x2 helpers (SIMT GEMM) ----------------
__device__ __forceinline__ void ffma2(unsigned long long& d,
                                      unsigned long long a,
                                      unsigned long long b) {
    asm("fma.rn.f32x2 %0, %1, %2, %0;" : "+l"(d) : "l"(a), "l"(b));
}
__device__ __forceinline__ unsigned long long pack2(float x, float y) {
    unsigned long long r;
    asm("mov.b64 %0, {%1, %2};" : "=l"(r) : "f"(x), "f"(y));
    return r;
}
__device__ __forceinline__ float2 unpack2(unsigned long long v) {
    float2 f;
    asm("mov.b64 {%0, %1}, %2;" : "=f"(f.x), "=f"(f.y) : "l"(v));
    return f;
}

// ---------------- K0: e_scale[e] = dot(H_e[e,:], p) ----------------
__global__ void escale_kernel(const float* __restrict__ He,
                              const float* __restrict__ p) {
    int row  = blockIdx.x * 8 + threadIdx.y;
    int lane = threadIdx.x;
    float4 h  = ((const float4*)(He + (size_t)row * DIM_E))[lane];
    float4 pv = ((const float4*)p)[lane];
    float v = h.x * pv.x + h.y * pv.y + h.z * pv.z + h.w * pv.w;
    #pragma unroll
    for (int o = 16; o; o >>= 1) v += __shfl_xor_sync(0xffffffffu, v, o);
    if (lane == 0) g_e_scale[row] = v;
}

// ------- K-split: T -> fp16 Bh;  T*e -> fp16 Ah (lo parts dropped) -------
__global__ __launch_bounds__(256) void split_kernel(const float* __restrict__ T) {
    size_t i = ((size_t)blockIdx.x * 256 + threadIdx.x) * 4;
    unsigned col = (unsigned)(i & (NN_EDGES - 1));
    float4 t = *(const float4*)(T + i);
    float4 e = *(const float4*)(g_e_scale + col);

    float b[4] = {t.x, t.y, t.z, t.w};
    float a[4] = {t.x * e.x, t.y * e.y, t.z * e.z, t.w * e.w};

    unsigned long long ah = 0, bh = 0;
    #pragma unroll
    for (int k = 0; k < 4; ++k) {
        bh |= (unsigned long long)__half_as_ushort(__float2half_rn(b[k])) << (16 * k);
        ah |= (unsigned long long)__half_as_ushort(__float2half_rn(a[k])) << (16 * k);
    }
    *(unsigned long long*)(g_Bh + i) = bh;
    *(unsigned long long*)(g_Ah + i) = ah;
}

// ========== K2: GEMM1 fp16 SINGLE product, CTA tile 256x128, warp tile 64x64 ==========
#define ROWB 72u
#define A_ROWS 256
#define B_ROWS 128
#define ATILEB (A_ROWS * ROWB)                // 18432
#define BTILEB (B_ROWS * ROWB)                //  9216
#define STAGEB2 (ATILEB + BTILEB)             // 27648
#define SMEM_G1 73728u                        // covers 2 stages (55296) AND TS (67584)
#define OFF2_AH(s) ((unsigned)(s) * STAGEB2)
#define OFF2_BH(s) (OFF2_AH(s) + ATILEB)
#define NCH_G1 (NN_EDGES / 32)                // 256
#define TS_LDC 132

__global__ __launch_bounds__(256) void gemm1_mma_kernel(const float* __restrict__ adj_v) {
    extern __shared__ char sm[];
    const unsigned sb = smem_u32(sm);
    const int tid  = threadIdx.x;
    const int warp = tid >> 5;
    const int lane = tid & 31;
    const int g = lane >> 2, t = lane & 3;
    const int wM = (warp >> 1) * 64;
    const int wN = (warp & 1) * 64;

    // bid -> (BI, bj): BI = 256-row super-block (0..15), bj = 128-col block >= 2*BI
    int r = (int)blockIdx.x, BI = 0;
    while (r >= 32 - 2 * BI) { r -= 32 - 2 * BI; ++BI; }
    const int bj = 2 * BI + r;
    const int iBase = BI * 256;
    const int jBase = bj * 128;

    float acc[4][8][4];
    #pragma unroll
    for (int mt = 0; mt < 4; ++mt)
        #pragma unroll
        for (int nt = 0; nt < 8; ++nt)
            #pragma unroll
            for (int q = 0; q < 4; ++q) acc[mt][nt][q] = 0.0f;

    auto fill = [&](int chunk, int stg) {
        const unsigned kb = (unsigned)chunk * 32u;
        #pragma unroll
        for (int i = 0; i < 8; ++i) {                 // A: 256 rows x 8 segs
            int c = tid + i * 256;
            int row = c >> 3, sub = c & 7;
            unsigned so = (unsigned)row * ROWB + (unsigned)sub * 8u;
            size_t ga = (size_t)(iBase + row) * NN_EDGES + kb + sub * 4;
            CP_ASYNC8(sb + OFF2_AH(stg) + so, (const char*)(g_Ah + ga));
        }
        #pragma unroll
        for (int i = 0; i < 4; ++i) {                 // B: 128 rows x 8 segs
            int c = tid + i * 256;
            int row = c >> 3, sub = c & 7;
            unsigned so = (unsigned)row * ROWB + (unsigned)sub * 8u;
            size_t gb = (size_t)(jBase + row) * NN_EDGES + kb + sub * 4;
            CP_ASYNC8(sb + OFF2_BH(stg) + so, (const char*)(g_Bh + gb));
        }
        CP_COMMIT();
    };

    fill(0, 0);

    for (int c = 0; c < NCH_G1; ++c) {
        const int s = c & 1;
        if (c + 1 < NCH_G1) { fill(c + 1, s ^ 1); CP_WAIT(1); }
        else                { CP_WAIT(0); }
        __syncthreads();

        const char* pAH = sm + OFF2_AH(s);
        const char* pBH = sm + OFF2_BH(s);

        #pragma unroll
        for (int ks = 0; ks < 2; ++ks) {
            const unsigned colb = (unsigned)(ks * 32 + t * 4);
            unsigned ah[4][4];
            #pragma unroll
            for (int mt = 0; mt < 4; ++mt) {
                unsigned o0 = (unsigned)(wM + mt * 16 + g) * ROWB + colb;
                unsigned o1 = o0 + 8u * ROWB;
                ah[mt][0] = *(const unsigned*)(pAH + o0);
                ah[mt][1] = *(const unsigned*)(pAH + o1);
                ah[mt][2] = *(const unsigned*)(pAH + o0 + 16u);
                ah[mt][3] = *(const unsigned*)(pAH + o1 + 16u);
            }
            #pragma unroll
            for (int nt = 0; nt < 8; ++nt) {
                unsigned bh[2];
                unsigned ob = (unsigned)(wN + nt * 8 + g) * ROWB + colb;
                bh[0] = *(const unsigned*)(pBH + ob);
                bh[1] = *(const unsigned*)(pBH + ob + 16u);
                #pragma unroll
                for (int mt = 0; mt < 4; ++mt) {
                    MMA_FP16(acc[mt][nt], ah[mt], bh);
                }
            }
        }
        __syncthreads();
    }

    // -------- direct epilogue: A_comb[i,j] for halves on/above diagonal --------
    #pragma unroll
    for (int mt = 0; mt < 4; ++mt) {
        const int roff = wM + mt * 16 + g;
        const int h = roff >> 7;
        if (h == 1 && bj == 2 * BI) continue;
        const int gi0 = iBase + roff;
        const float* adj0 = adj_v + (size_t)gi0 * NN_NODES;
        const float* adj1 = adj0 + 8u * NN_NODES;
        float* d0 = g_Acomb + (size_t)gi0 * NN_NODES;
        float* d1 = d0 + 8u * NN_NODES;
        #pragma unroll
        for (int nt = 0; nt < 8; ++nt) {
            int gj = jBase + wN + nt * 8 + t * 2;
            float2 a0 = *(const float2*)(adj0 + gj);
            float2 a1 = *(const float2*)(adj1 + gj);
            float2 o0, o1;
            o0.x = (gi0 == gj)         ? a0.x : 0.5f * a0.x * (acc[mt][nt][0] + 1.0f);
            o0.y = (gi0 == gj + 1)     ? a0.y : 0.5f * a0.y * (acc[mt][nt][1] + 1.0f);
            o1.x = (gi0 + 8 == gj)     ? a1.x : 0.5f * a1.x * (acc[mt][nt][2] + 1.0f);
            o1.y = (gi0 + 8 == gj + 1) ? a1.y : 0.5f * a1.y * (acc[mt][nt][3] + 1.0f);
            *(float2*)(d0 + gj) = o0;
            *(float2*)(d1 + gj) = o1;
        }
    }

    // -------- mirrored epilogue per row-half h with 2*BI+h < bj --------
    float* TS = (float*)sm;
    #pragma unroll
    for (int h = 0; h < 2; ++h) {
        if (2 * BI + h >= bj) continue;
        __syncthreads();
        if ((wM >> 7) == h) {
            const int ibase_loc = wM & 127;
            #pragma unroll
            for (int mt = 0; mt < 4; ++mt) {
                int ii = ibase_loc + mt * 16 + g;
                #pragma unroll
                for (int nt = 0; nt < 8; ++nt) {
                    int jj = wN + nt * 8 + t * 2;
                    TS[(jj)     * TS_LDC + ii]     = acc[mt][nt][0];
                    TS[(jj + 1) * TS_LDC + ii]     = acc[mt][nt][1];
                    TS[(jj)     * TS_LDC + ii + 8] = acc[mt][nt][2];
                    TS[(jj + 1) * TS_LDC + ii + 8] = acc[mt][nt][3];
                }
            }
        }
        __syncthreads();

        const int jj  = tid >> 1;
        const int iiB = (tid & 1) * 64;
        const int gj  = jBase + jj;
        const int giB = iBase + h * 128 + iiB;
        const float* adjRow = adj_v + (size_t)gj * NN_NODES + giB;
        float* dst = g_Acomb + (size_t)gj * NN_NODES + giB;
        const float* tsRow = TS + jj * TS_LDC + iiB;
        #pragma unroll
        for (int q = 0; q < 16; ++q) {
            float4 a = *(const float4*)(adjRow + q * 4);
            float4 s4 = *(const float4*)(tsRow + q * 4);
            float4 o;
            o.x = 0.5f * a.x * (s4.x + 1.0f);
            o.y = 0.5f * a.y * (s4.y + 1.0f);
            o.z = 0.5f * a.z * (s4.z + 1.0f);
            o.w = 0.5f * a.w * (s4.w + 1.0f);
            *(float4*)(dst + q * 4) = o;
        }
    }
}

// ---------------- A_comb fp32 -> bf16 hi/lo split ----------------
__global__ __launch_bounds__(256) void acomb_split_kernel() {
    size_t i = ((size_t)blockIdx.x * 256 + threadIdx.x) * 4;
    float4 v = *(const float4*)(g_Acomb + i);
    float x[4] = {v.x, v.y, v.z, v.w};
    unsigned long long ch = 0, cl = 0;
    #pragma unroll
    for (int k = 0; k < 4; ++k) {
        __nv_bfloat16 h = __float2bfloat16(x[k]);
        __nv_bfloat16 l = __float2bfloat16(x[k] - __bfloat162float(h));
        ch |= (unsigned long long)__bfloat16_as_ushort(h) << (16 * k);
        cl |= (unsigned long long)__bfloat16_as_ushort(l) << (16 * k);
    }
    *(unsigned long long*)(g_Ch + i) = ch;
    *(unsigned long long*)(g_Cl + i) = cl;
}

// ---------------- bf16 3-product 128x128 mainloop (gemm_out) ----------------
#define OTILEB (128u * ROWB)              // 9216
#define OSTAGEB (4u * OTILEB)             // 36864
#define SMEM_GO (2u * OSTAGEB)            // 73728
#define OOFF_AH(s) ((unsigned)(s) * OSTAGEB)
#define OOFF_AL(s) (OOFF_AH(s) + OTILEB)
#define OOFF_BH(s) (OOFF_AH(s) + 2u * OTILEB)
#define OOFF_BL(s) (OOFF_AH(s) + 3u * OTILEB)

template<int LD, int NCH>
__device__ __forceinline__ void mma_mainloop(
    const __nv_bfloat16* __restrict__ Ahp, const __nv_bfloat16* __restrict__ Alp,
    const __nv_bfloat16* __restrict__ Bhp, const __nv_bfloat16* __restrict__ Blp,
    int iBase, int jBase, char* sm, unsigned sb, float (&acc)[2][8][4]) {

    const int tid  = threadIdx.x;
    const int warp = tid >> 5;
    const int lane = tid & 31;
    const int g = lane >> 2, t = lane & 3;
    const int wM = (warp >> 1) * 32;
    const int wN = (warp & 1) * 64;

    #pragma unroll
    for (int mt = 0; mt < 2; ++mt)
        #pragma unroll
        for (int nt = 0; nt < 8; ++nt)
            #pragma unroll
            for (int q = 0; q < 4; ++q) acc[mt][nt][q] = 0.0f;

    auto fill = [&](int chunk, int stg) {
        const unsigned kb = (unsigned)chunk * 32u;
        #pragma unroll
        for (int i = 0; i < 4; ++i) {
            int c = tid + i * 256;
            int row = c >> 3, sub = c & 7;
            unsigned so = (unsigned)row * ROWB + (unsigned)sub * 8u;
            size_t ga = (size_t)(iBase + row) * LD + kb + sub * 4;
            size_t gb = (size_t)(jBase + row) * LD + kb + sub * 4;
            CP_ASYNC8(sb + OOFF_AH(stg) + so, (const char*)(Ahp + ga));
            CP_ASYNC8(sb + OOFF_AL(stg) + so, (const char*)(Alp + ga));
            CP_ASYNC8(sb + OOFF_BH(stg) + so, (const char*)(Bhp + gb));
            CP_ASYNC8(sb + OOFF_BL(stg) + so, (const char*)(Blp + gb));
        }
        CP_COMMIT();
    };

    fill(0, 0);

    for (int c = 0; c < NCH; ++c) {
        const int s = c & 1;
        if (c + 1 < NCH) { fill(c + 1, s ^ 1); CP_WAIT(1); }
        else             { CP_WAIT(0); }
        __syncthreads();

        const char* pAH = sm + OOFF_AH(s);
        const char* pAL = sm + OOFF_AL(s);
        const char* pBH = sm + OOFF_BH(s);
        const char* pBL = sm + OOFF_BL(s);

        #pragma unroll
        for (int ks = 0; ks < 2; ++ks) {
            unsigned ah[2][4], al[2][4], bh[8][2], bl[8][2];
            const unsigned colb = (unsigned)(ks * 32 + t * 4);
            #pragma unroll
            for (int mt = 0; mt < 2; ++mt) {
                unsigned o0 = (unsigned)(wM + mt * 16 + g) * ROWB + colb;
                unsigned o1 = o0 + 8u * ROWB;
                ah[mt][0] = *(const unsigned*)(pAH + o0);
                ah[mt][1] = *(const unsigned*)(pAH + o1);
                ah[mt][2] = *(const unsigned*)(pAH + o0 + 16u);
                ah[mt][3] = *(const unsigned*)(pAH + o1 + 16u);
                al[mt][0] = *(const unsigned*)(pAL + o0);
                al[mt][1] = *(const unsigned*)(pAL + o1);
                al[mt][2] = *(const unsigned*)(pAL + o0 + 16u);
                al[mt][3] = *(const unsigned*)(pAL + o1 + 16u);
            }
            #pragma unroll
            for (int nt = 0; nt < 8; ++nt) {
                unsigned ob = (unsigned)(wN + nt * 8 + g) * ROWB + colb;
                bh[nt][0] = *(const unsigned*)(pBH + ob);
                bh[nt][1] = *(const unsigned*)(pBH + ob + 16u);
                bl[nt][0] = *(const unsigned*)(pBL + ob);
                bl[nt][1] = *(const unsigned*)(pBL + ob + 16u);
            }
            #pragma unroll
            for (int mt = 0; mt < 2; ++mt)
                #pragma unroll
                for (int nt = 0; nt < 8; ++nt) {
                    MMA_BF16(acc[mt][nt], ah[mt], bh[nt]);
                    MMA_BF16(acc[mt][nt], ah[mt], bl[nt]);
                    MMA_BF16(acc[mt][nt], al[mt], bh[nt]);
                }
        }
        __syncthreads();
    }
}

// ---------------- K3: ret = A_comb @ HW + bias (tensorized) ----------------
__global__ __launch_bounds__(256) void gemm_out_mma_kernel(
    const float* __restrict__ bias, float* __restrict__ out) {
    extern __shared__ char sm[];
    const unsigned sb = smem_u32(sm);
    const int warp = threadIdx.x >> 5;
    const int lane = threadIdx.x & 31;
    const int g = lane >> 2, t = lane & 3;
    const int iBase = blockIdx.y * 128;
    const int jBase = blockIdx.x * 128;
    const int wM = (warp >> 1) * 32;
    const int wN = (warp & 1) * 64;

    float acc[2][8][4];
    mma_mainloop<NN_NODES, NN_NODES / 32>(g_Ch, g_Cl, g_HWth, g_HWtl, iBase, jBase, sm, sb, acc);

    #pragma unroll
    for (int mt = 0; mt < 2; ++mt) {
        int gi0 = iBase + wM + mt * 16 + g;
        float* d0 = out + (size_t)gi0 * DIM_OUT;
        float* d1 = d0 + 8u * DIM_OUT;
        #pragma unroll
        for (int nt = 0; nt < 8; ++nt) {
            int gj = jBase + wN + nt * 8 + t * 2;
            float2 bs = *(const float2*)(bias + gj);
            *(float2*)(d0 + gj) = make_float2(acc[mt][nt][0] + bs.x, acc[mt][nt][1] + bs.y);
            *(float2*)(d1 + gj) = make_float2(acc[mt][nt][2] + bs.x, acc[mt][nt][3] + bs.y);
        }
    }
}

// ---------------- SIMT GEMM for HW = H_v @ W ----------------
__global__ __launch_bounds__(256, 2) void gemm_hw_kernel(
    const float* __restrict__ A, const float* __restrict__ B) {
    __shared__ __align__(16) float As[2][8][128];
    __shared__ __align__(16) float Bs[2][8][128];

    const int Nn = DIM_OUT, K = DIM_V;
    const int tid = threadIdx.x;
    const int iBase = blockIdx.y * 128;
    const int jBase = blockIdx.x * 128;

    const int lrow = tid >> 1;
    const int kq   = (tid & 1) * 4;
    const float* Aptr = A + (size_t)(iBase + lrow) * K + kq;
    const int bk = tid >> 5;
    const int bn = (tid & 31) * 4;
    const float* Bptr = B + (size_t)bk * Nn + jBase + bn;

    unsigned long long acc[8][4];
    #pragma unroll
    for (int r = 0; r < 8; ++r)
        #pragma unroll
        for (int c = 0; c < 4; ++c) acc[r][c] = 0ull;

    {
        float4 a = *(const float4*)Aptr;
        float4 b = *(const float4*)Bptr;
        As[0][kq + 0][lrow] = a.x; As[0][kq + 1][lrow] = a.y;
        As[0][kq + 2][lrow] = a.z; As[0][kq + 3][lrow] = a.w;
        *(float4*)&Bs[0][bk][bn] = b;
    }
    __syncthreads();

    const int tx = (tid & 15) * 8;
    const int ty = (tid >> 4) * 8;
    int buf = 0;
    const int KT = K / 8;

    for (int kt = 0; kt < KT; ++kt) {
        float4 aN, bN;
        if (kt + 1 < KT) {
            aN = *(const float4*)(Aptr + (size_t)(kt + 1) * 8);
            bN = *(const float4*)(Bptr + (size_t)(kt + 1) * 8 * Nn);
        }
        #pragma unroll
        for (int kk = 0; kk < 8; ++kk) {
            float4 a0 = *(const float4*)&As[buf][kk][ty];
            float4 a1 = *(const float4*)&As[buf][kk][ty + 4];
            ulonglong2 b0 = *(const ulonglong2*)&Bs[buf][kk][tx];
            ulonglong2 b1 = *(const ulonglong2*)&Bs[buf][kk][tx + 4];
            float av[8] = {a0.x, a0.y, a0.z, a0.w, a1.x, a1.y, a1.z, a1.w};
            unsigned long long bv[4] = {b0.x, b0.y, b1.x, b1.y};
            #pragma unroll
            for (int r = 0; r < 8; ++r) {
                unsigned long long aa = pack2(av[r], av[r]);
                #pragma unroll
                for (int c = 0; c < 4; ++c) ffma2(acc[r][c], aa, bv[c]);
            }
        }
        if (kt + 1 < KT) {
            int nb = buf ^ 1;
            As[nb][kq + 0][lrow] = aN.x; As[nb][kq + 1][lrow] = aN.y;
            As[nb][kq + 2][lrow] = aN.z; As[nb][kq + 3][lrow] = aN.w;
            *(float4*)&Bs[nb][bk][bn] = bN;
            __syncthreads();
            buf = nb;
        }
    }

    #pragma unroll
    for (int r = 0; r < 8; ++r) {
        int gi = iBase + ty + r;
        float* dst = g_HW + (size_t)gi * Nn;
        #pragma unroll
        for (int c = 0; c < 4; ++c) {
            int gj = jBase + tx + c * 2;
            float2 v = unpack2(acc[r][c]);
            *(float2*)&dst[gj] = v;
        }
    }
}

// ---------------- transpose + split: HW [4096,512] -> HW^T hi/lo [512,4096] ----------------
__global__ void hw_transpose_split_kernel() {
    __shared__ float tile[32][33];
    const int tx = threadIdx.x, ty = threadIdx.y;
    const int nb = blockIdx.x * 32;
    const int kb = blockIdx.y * 32;
    #pragma unroll
    for (int i = 0; i < 4; ++i) {
        int k = kb + ty + i * 8;
        tile[ty + i * 8][tx] = g_HW[(size_t)k * DIM_OUT + nb + tx];
    }
    __syncthreads();
    #pragma unroll
    for (int i = 0; i < 4; ++i) {
        int n = nb + ty + i * 8;
        int k = kb + tx;
        float v = tile[tx][ty + i * 8];
        __nv_bfloat16 h = __float2bfloat16(v);
        g_HWth[(size_t)n * NN_NODES + k] = h;
        g_HWtl[(size_t)n * NN_NODES + k] = __float2bfloat16(v - __bfloat162float(h));
    }
}

extern "C" void kernel_launch(void* const* d_in, const int* in_sizes, int n_in,
                              void* d_out, int out_size) {
    const float* H_v    = (const float*)d_in[0];
    const float* H_e    = (const float*)d_in[1];
    const float* adj_v  = (const float*)d_in[3];
    const float* T      = (const float*)d_in[4];
    const float* weight = (const float*)d_in[5];
    const float* p      = (const float*)d_in[6];
    const float* bias   = (const float*)d_in[7];
    float* out = (float*)d_out;
    (void)in_sizes; (void)n_in;

    cudaFuncSetAttribute(gemm1_mma_kernel,
                         cudaFuncAttributeMaxDynamicSharedMemorySize, SMEM_G1);
    cudaFuncSetAttribute(gemm_out_mma_kernel,
                         cudaFuncAttributeMaxDynamicSharedMemorySize, SMEM_GO);

    // K0: edge scaling vector
    escale_kernel<<<NN_EDGES / 8, dim3(32, 8)>>>(H_e, p);

    // K-split: fp16 operand prep (depends on K0)
    split_kernel<<<(NN_NODES * NN_EDGES) / (256 * 4), 256>>>(T);

    // K1: HW = H_v @ W
    gemm_hw_kernel<<<dim3(DIM_OUT / 128, NN_NODES / 128), 256>>>(H_v, weight);

    // K2 (4th launch — ncu profiling slot): dominant GEMM, fp16 single-product,
    // 256x128 tiles, triangular super-blocks, mirrored epilogue
    gemm1_mma_kernel<<<272, 256, SMEM_G1>>>(adj_v);

    // HW transpose+split for the tensorized output GEMM (indep of gemm1)
    hw_transpose_split_kernel<<<dim3(DIM_OUT / 32, NN_NODES / 32), dim3(32, 8)>>>();

    // A_comb -> bf16 hi/lo
    acomb_split_kernel<<<(size_t)NN_NODES * NN_NODES / (256 * 4), 256>>>();

    // K3: ret = A_comb @ HW + bias (tensorized)
    gemm_out_mma_kernel<<<dim3(DIM_OUT / 128, NN_NODES / 128), 256, SMEM_GO>>>(bias, out);

    const size_t ret_elems = (size_t)NN_NODES * DIM_OUT;
    const size_t he_elems  = (size_t)NN_EDGES * DIM_E;
    if ((size_t)out_size >= ret_elems + he_elems) {
        cudaMemcpyAsync(out + ret_elems, H_e, he_elems * sizeof(float),
                        cudaMemcpyDeviceToDevice);
    }
}

// round 12
// speedup vs baseline: 4.5445x; 1.2364x over previous
#include <cuda_runtime.h>
#include <cuda_bf16.h>
#include <cuda_fp16.h>

// Problem constants
#define NN_NODES 4096
#define NN_EDGES 8192
#define DIM_V    512
#define DIM_OUT  512
#define DIM_E    128
#define KBLKS    (NN_EDGES / 16)   // 512 col-blocks of 16

// ---------------- scratch (device globals; no allocation allowed) ----------------
__device__ float g_e_scale[NN_EDGES];
__device__ float g_Acomb[(size_t)NN_NODES * NN_NODES];            // 64 MB fp32
__device__ float g_HW[(size_t)NN_NODES * DIM_OUT];                //  8 MB fp32
// fragment-permuted fp16 operands for gemm1 (mma.m16n8k16 order)
__device__ __half g_Ah[(size_t)NN_NODES * NN_EDGES];              // 64 MB
__device__ __half g_Bh[(size_t)NN_NODES * NN_EDGES];              // 64 MB
__device__ __half g_Cf[(size_t)NN_NODES * NN_NODES];              // 32 MB (A_comb fp16)
__device__ __half g_HWth[(size_t)DIM_OUT * NN_NODES];             //  4 MB (HW^T hi)
__device__ __half g_HWtl[(size_t)DIM_OUT * NN_NODES];             //  4 MB (HW^T lo)

// ---------------- PTX helpers (non-'a' features only) ----------------
__device__ __forceinline__ unsigned smem_u32(const void* p) {
    unsigned a;
    asm("{ .reg .u64 t; cvta.to.shared.u64 t, %1; cvt.u32.u64 %0, t; }" : "=r"(a) : "l"(p));
    return a;
}
#define CP_ASYNC8(dst, src) \
    asm volatile("cp.async.ca.shared.global [%0], [%1], 8;" :: "r"(dst), "l"(src) : "memory")
#define CP_ASYNC16(dst, src) \
    asm volatile("cp.async.cg.shared.global [%0], [%1], 16;" :: "r"(dst), "l"(src) : "memory")
#define CP_COMMIT() asm volatile("cp.async.commit_group;" ::: "memory")
#define CP_WAIT(n)  asm volatile("cp.async.wait_group %0;" :: "n"(n) : "memory")

#define MMA_FP16(acc, A, B) \
    asm volatile("mma.sync.aligned.m16n8k16.row.col.f32.f16.f16.f32 " \
                 "{%0,%1,%2,%3},{%4,%5,%6,%7},{%8,%9},{%0,%1,%2,%3};" \
                 : "+f"((acc)[0]), "+f"((acc)[1]), "+f"((acc)[2]), "+f"((acc)[3]) \
                 : "r"((A)[0]), "r"((A)[1]), "r"((A)[2]), "r"((A)[3]), \
                   "r"((B)[0]), "r"((B)[1]))

// ---------------- packed f32x2 helpers (SIMT GEMM) ----------------
__device__ __forceinline__ void ffma2(unsigned long long& d,
                                      unsigned long long a,
                                      unsigned long long b) {
    asm("fma.rn.f32x2 %0, %1, %2, %0;" : "+l"(d) : "l"(a), "l"(b));
}
__device__ __forceinline__ unsigned long long pack2(float x, float y) {
    unsigned long long r;
    asm("mov.b64 %0, {%1, %2};" : "=l"(r) : "f"(x), "f"(y));
    return r;
}
__device__ __forceinline__ float2 unpack2(unsigned long long v) {
    float2 f;
    asm("mov.b64 {%0, %1}, %2;" : "=f"(f.x), "=f"(f.y) : "l"(v));
    return f;
}
__device__ __forceinline__ unsigned packh2(__half x, __half y) {
    return (unsigned)__half_as_ushort(x) | ((unsigned)__half_as_ushort(y) << 16);
}

// ---------------- K0: e_scale[e] = dot(H_e[e,:], p) ----------------
__global__ void escale_kernel(const float* __restrict__ He,
                              const float* __restrict__ p) {
    int row  = blockIdx.x * 8 + threadIdx.y;
    int lane = threadIdx.x;
    float4 h  = ((const float4*)(He + (size_t)row * DIM_E))[lane];
    float4 pv = ((const float4*)p)[lane];
    float v = h.x * pv.x + h.y * pv.y + h.z * pv.z + h.w * pv.w;
    #pragma unroll
    for (int o = 16; o; o >>= 1) v += __shfl_xor_sync(0xffffffffu, v, o);
    if (lane == 0) g_e_scale[row] = v;
}

// ------- K-split: fragment-permuted fp16 operands for gemm1 -------
// A perm: block (row/16, col/16) of 512B; within: lane(g*4+t)*16 + (m+2*kh)*4 + klo*2
// B perm: block (row/8, col/16) of 256B; within: lane(g*4+t)*8 + kh*4 + klo*2
__global__ __launch_bounds__(256) void split_kernel(const float* __restrict__ T) {
    size_t i = ((size_t)blockIdx.x * 256 + threadIdx.x) * 4;
    int row = (int)(i >> 13);             // / 8192
    int c0  = (int)(i & (NN_EDGES - 1));
    float4 t = *(const float4*)(T + i);
    float4 e = *(const float4*)(g_e_scale + c0);

    __half ha0 = __float2half_rn(t.x * e.x), ha1 = __float2half_rn(t.y * e.y);
    __half ha2 = __float2half_rn(t.z * e.z), ha3 = __float2half_rn(t.w * e.w);
    __half hb0 = __float2half_rn(t.x), hb1 = __float2half_rn(t.y);
    __half hb2 = __float2half_rn(t.z), hb3 = __float2half_rn(t.w);

    const int col_blk = c0 >> 4;
    const int k_in = c0 & 15;
    const int kh = k_in >> 3;
    const int t0 = (k_in & 7) >> 1;       // elements 0,1 -> t0; 2,3 -> t0+1

    // A
    {
        int row_blk = row >> 4, r_in = row & 15;
        int g = r_in & 7, m = r_in >> 3;
        size_t base = ((size_t)row_blk * KBLKS + col_blk) * 512
                    + (unsigned)((g * 4 + t0) * 16 + (m + 2 * kh) * 4);
        *(unsigned*)((char*)g_Ah + base)      = packh2(ha0, ha1);
        *(unsigned*)((char*)g_Ah + base + 16) = packh2(ha2, ha3);
    }
    // B
    {
        int n_blk = row >> 3, gb = row & 7;
        size_t base = ((size_t)n_blk * KBLKS + col_blk) * 256
                    + (unsigned)((gb * 4 + t0) * 8 + kh * 4);
        *(unsigned*)((char*)g_Bh + base)     = packh2(hb0, hb1);
        *(unsigned*)((char*)g_Bh + base + 8) = packh2(hb2, hb3);
    }
}

// ========== K2: GEMM1 fp16 single product, permuted frags, 256x128 tiles ==========
#define A_TILE_B 16384u                  // 16 row-blks x 1024B (2 col-blks)
#define B_TILE_B 8192u                   // 16 n-blks x 512B
#define STAGEB2 (A_TILE_B + B_TILE_B)    // 24576
#define SMEM_G1 73728u                   // >= 2 stages (49152) and TS (67584)
#define OFF2_A(s) ((unsigned)(s) * STAGEB2)
#define OFF2_B(s) (OFF2_A(s) + A_TILE_B)
#define NCH_G1 (NN_EDGES / 32)           // 256
#define TS_LDC 132

__global__ __launch_bounds__(256) void gemm1_mma_kernel(const float* __restrict__ adj_v) {
    extern __shared__ char sm[];
    const unsigned sb = smem_u32(sm);
    const int tid  = threadIdx.x;
    const int warp = tid >> 5;
    const int lane = tid & 31;
    const int g = lane >> 2, t = lane & 3;
    const int wM = (warp >> 1) * 64;
    const int wN = (warp & 1) * 64;
    const int wM16 = (warp >> 1) * 4;    // A row-blk origin
    const int wN8  = (warp & 1) * 8;     // B n-blk origin

    // bid -> (BI, bj): BI = 256-row super-block (0..15), bj = 128-col block >= 2*BI
    int r = (int)blockIdx.x, BI = 0;
    while (r >= 32 - 2 * BI) { r -= 32 - 2 * BI; ++BI; }
    const int bj = 2 * BI + r;
    const int iBase = BI * 256;
    const int jBase = bj * 128;
    const int iBase16 = BI * 16;         // A row-blk base
    const int jBase8  = bj * 16;         // B n-blk base

    float acc[4][8][4];
    #pragma unroll
    for (int mt = 0; mt < 4; ++mt)
        #pragma unroll
        for (int nt = 0; nt < 8; ++nt)
            #pragma unroll
            for (int q = 0; q < 4; ++q) acc[mt][nt][q] = 0.0f;

    auto fill = [&](int chunk, int stg) {
        const int kb16 = chunk * 2;      // col-blk index of this 32-col chunk
        #pragma unroll
        for (int i = 0; i < 4; ++i) {    // A: 16 rb x 64 segs of 16B
            int c = tid + i * 256;
            int rb = c >> 6, seg = c & 63;
            const char* src = (const char*)g_Ah
                + ((size_t)(iBase16 + rb) * KBLKS + kb16) * 512 + seg * 16;
            CP_ASYNC16(sb + OFF2_A(stg) + rb * 1024u + seg * 16u, src);
        }
        #pragma unroll
        for (int i = 0; i < 2; ++i) {    // B: 16 nb x 32 segs of 16B
            int c = tid + i * 256;
            int nb = c >> 5, seg = c & 31;
            const char* src = (const char*)g_Bh
                + ((size_t)(jBase8 + nb) * KBLKS + kb16) * 256 + seg * 16;
            CP_ASYNC16(sb + OFF2_B(stg) + nb * 512u + seg * 16u, src);
        }
        CP_COMMIT();
    };

    fill(0, 0);

    for (int c = 0; c < NCH_G1; ++c) {
        const int s = c & 1;
        if (c + 1 < NCH_G1) { fill(c + 1, s ^ 1); CP_WAIT(1); }
        else                { CP_WAIT(0); }
        __syncthreads();

        const char* pA = sm + OFF2_A(s);
        const char* pB = sm + OFF2_B(s);

        #pragma unroll
        for (int ks = 0; ks < 2; ++ks) {
            unsigned ah[4][4];
            #pragma unroll
            for (int mt = 0; mt < 4; ++mt) {
                uint4 v = *(const uint4*)(pA + (wM16 + mt) * 1024 + ks * 512 + lane * 16);
                ah[mt][0] = v.x; ah[mt][1] = v.y; ah[mt][2] = v.z; ah[mt][3] = v.w;
            }
            #pragma unroll
            for (int nt = 0; nt < 8; ++nt) {
                uint2 bv = *(const uint2*)(pB + (wN8 + nt) * 512 + ks * 256 + lane * 8);
                unsigned bh[2] = {bv.x, bv.y};
                #pragma unroll
                for (int mt = 0; mt < 4; ++mt) {
                    MMA_FP16(acc[mt][nt], ah[mt], bh);
                }
            }
        }
        __syncthreads();
    }

    // -------- direct epilogue: A_comb[i,j] for halves on/above diagonal --------
    #pragma unroll
    for (int mt = 0; mt < 4; ++mt) {
        const int roff = wM + mt * 16 + g;
        const int h = roff >> 7;
        if (h == 1 && bj == 2 * BI) continue;
        const int gi0 = iBase + roff;
        const float* adj0 = adj_v + (size_t)gi0 * NN_NODES;
        const float* adj1 = adj0 + 8u * NN_NODES;
        float* d0 = g_Acomb + (size_t)gi0 * NN_NODES;
        float* d1 = d0 + 8u * NN_NODES;
        #pragma unroll
        for (int nt = 0; nt < 8; ++nt) {
            int gj = jBase + wN + nt * 8 + t * 2;
            float2 a0 = *(const float2*)(adj0 + gj);
            float2 a1 = *(const float2*)(adj1 + gj);
            float2 o0, o1;
            o0.x = (gi0 == gj)         ? a0.x : 0.5f * a0.x * (acc[mt][nt][0] + 1.0f);
            o0.y = (gi0 == gj + 1)     ? a0.y : 0.5f * a0.y * (acc[mt][nt][1] + 1.0f);
            o1.x = (gi0 + 8 == gj)     ? a1.x : 0.5f * a1.x * (acc[mt][nt][2] + 1.0f);
            o1.y = (gi0 + 8 == gj + 1) ? a1.y : 0.5f * a1.y * (acc[mt][nt][3] + 1.0f);
            *(float2*)(d0 + gj) = o0;
            *(float2*)(d1 + gj) = o1;
        }
    }

    // -------- mirrored epilogue per row-half h with 2*BI+h < bj --------
    float* TS = (float*)sm;
    #pragma unroll
    for (int h = 0; h < 2; ++h) {
        if (2 * BI + h >= bj) continue;
        __syncthreads();
        if ((wM >> 7) == h) {
            const int ibase_loc = wM & 127;
            #pragma unroll
            for (int mt = 0; mt < 4; ++mt) {
                int ii = ibase_loc + mt * 16 + g;
                #pragma unroll
                for (int nt = 0; nt < 8; ++nt) {
                    int jj = wN + nt * 8 + t * 2;
                    TS[(jj)     * TS_LDC + ii]     = acc[mt][nt][0];
                    TS[(jj + 1) * TS_LDC + ii]     = acc[mt][nt][1];
                    TS[(jj)     * TS_LDC + ii + 8] = acc[mt][nt][2];
                    TS[(jj + 1) * TS_LDC + ii + 8] = acc[mt][nt][3];
                }
            }
        }
        __syncthreads();

        const int jj  = tid >> 1;
        const int iiB = (tid & 1) * 64;
        const int gj  = jBase + jj;
        const int giB = iBase + h * 128 + iiB;
        const float* adjRow = adj_v + (size_t)gj * NN_NODES + giB;
        float* dst = g_Acomb + (size_t)gj * NN_NODES + giB;
        const float* tsRow = TS + jj * TS_LDC + iiB;
        #pragma unroll
        for (int q = 0; q < 16; ++q) {
            float4 a = *(const float4*)(adjRow + q * 4);
            float4 s4 = *(const float4*)(tsRow + q * 4);
            float4 o;
            o.x = 0.5f * a.x * (s4.x + 1.0f);
            o.y = 0.5f * a.y * (s4.y + 1.0f);
            o.z = 0.5f * a.z * (s4.z + 1.0f);
            o.w = 0.5f * a.w * (s4.w + 1.0f);
            *(float4*)(dst + q * 4) = o;
        }
    }
}

// ---------------- A_comb fp32 -> fp16 ----------------
__global__ __launch_bounds__(256) void acomb_split_kernel() {
    size_t i = ((size_t)blockIdx.x * 256 + threadIdx.x) * 4;
    float4 v = *(const float4*)(g_Acomb + i);
    unsigned long long cf =
          (unsigned long long)__half_as_ushort(__float2half_rn(v.x))
        | ((unsigned long long)__half_as_ushort(__float2half_rn(v.y)) << 16)
        | ((unsigned long long)__half_as_ushort(__float2half_rn(v.z)) << 32)
        | ((unsigned long long)__half_as_ushort(__float2half_rn(v.w)) << 48);
    *(unsigned long long*)(g_Cf + i) = cf;
}

// ---------------- K3: ret = A_comb @ HW + bias (fp16 2-product) ----------------
#define G3_ROWB 72u
#define G3_TILE (128u * G3_ROWB)          // 9216
#define G3_STAGE (3u * G3_TILE)           // 27648
#define SMEM_GO (2u * G3_STAGE)           // 55296
#define OFF3_A(s)  ((unsigned)(s) * G3_STAGE)
#define OFF3_BH(s) (OFF3_A(s) + G3_TILE)
#define OFF3_BL(s) (OFF3_A(s) + 2u * G3_TILE)

__global__ __launch_bounds__(256) void gemm_out_mma_kernel(
    const float* __restrict__ bias, float* __restrict__ out) {
    extern __shared__ char sm[];
    const unsigned sb = smem_u32(sm);
    const int tid  = threadIdx.x;
    const int warp = tid >> 5;
    const int lane = tid & 31;
    const int g = lane >> 2, t = lane & 3;
    const int iBase = blockIdx.y * 128;
    const int jBase = blockIdx.x * 128;
    const int wM = (warp >> 1) * 32;
    const int wN = (warp & 1) * 64;

    float acc[2][8][4];
    #pragma unroll
    for (int mt = 0; mt < 2; ++mt)
        #pragma unroll
        for (int nt = 0; nt < 8; ++nt)
            #pragma unroll
            for (int q = 0; q < 4; ++q) acc[mt][nt][q] = 0.0f;

    auto fill = [&](int chunk, int stg) {
        const unsigned kb = (unsigned)chunk * 32u;
        #pragma unroll
        for (int i = 0; i < 4; ++i) {
            int c = tid + i * 256;
            int row = c >> 3, sub = c & 7;
            unsigned so = (unsigned)row * G3_ROWB + (unsigned)sub * 8u;
            size_t ga = (size_t)(iBase + row) * NN_NODES + kb + sub * 4;
            size_t gb = (size_t)(jBase + row) * NN_NODES + kb + sub * 4;
            CP_ASYNC8(sb + OFF3_A(stg)  + so, (const char*)(g_Cf + ga));
            CP_ASYNC8(sb + OFF3_BH(stg) + so, (const char*)(g_HWth + gb));
            CP_ASYNC8(sb + OFF3_BL(stg) + so, (const char*)(g_HWtl + gb));
        }
        CP_COMMIT();
    };

    fill(0, 0);
    const int NCH = NN_NODES / 32;

    for (int c = 0; c < NCH; ++c) {
        const int s = c & 1;
        if (c + 1 < NCH) { fill(c + 1, s ^ 1); CP_WAIT(1); }
        else             { CP_WAIT(0); }
        __syncthreads();

        const char* pA  = sm + OFF3_A(s);
        const char* pBH = sm + OFF3_BH(s);
        const char* pBL = sm + OFF3_BL(s);

        #pragma unroll
        for (int ks = 0; ks < 2; ++ks) {
            unsigned ah[2][4], bh[8][2], bl[8][2];
            const unsigned colb = (unsigned)(ks * 32 + t * 4);
            #pragma unroll
            for (int mt = 0; mt < 2; ++mt) {
                unsigned o0 = (unsigned)(wM + mt * 16 + g) * G3_ROWB + colb;
                unsigned o1 = o0 + 8u * G3_ROWB;
                ah[mt][0] = *(const unsigned*)(pA + o0);
                ah[mt][1] = *(const unsigned*)(pA + o1);
                ah[mt][2] = *(const unsigned*)(pA + o0 + 16u);
                ah[mt][3] = *(const unsigned*)(pA + o1 + 16u);
            }
            #pragma unroll
            for (int nt = 0; nt < 8; ++nt) {
                unsigned ob = (unsigned)(wN + nt * 8 + g) * G3_ROWB + colb;
                bh[nt][0] = *(const unsigned*)(pBH + ob);
                bh[nt][1] = *(const unsigned*)(pBH + ob + 16u);
                bl[nt][0] = *(const unsigned*)(pBL + ob);
                bl[nt][1] = *(const unsigned*)(pBL + ob + 16u);
            }
            #pragma unroll
            for (int mt = 0; mt < 2; ++mt)
                #pragma unroll
                for (int nt = 0; nt < 8; ++nt) {
                    MMA_FP16(acc[mt][nt], ah[mt], bh[nt]);
                    MMA_FP16(acc[mt][nt], ah[mt], bl[nt]);
                }
        }
        __syncthreads();
    }

    #pragma unroll
    for (int mt = 0; mt < 2; ++mt) {
        int gi0 = iBase + wM + mt * 16 + g;
        float* d0 = out + (size_t)gi0 * DIM_OUT;
        float* d1 = d0 + 8u * DIM_OUT;
        #pragma unroll
        for (int nt = 0; nt < 8; ++nt) {
            int gj = jBase + wN + nt * 8 + t * 2;
            float2 bs = *(const float2*)(bias + gj);
            *(float2*)(d0 + gj) = make_float2(acc[mt][nt][0] + bs.x, acc[mt][nt][1] + bs.y);
            *(float2*)(d1 + gj) = make_float2(acc[mt][nt][2] + bs.x, acc[mt][nt][3] + bs.y);
        }
    }
}

// ---------------- SIMT GEMM for HW = H_v @ W ----------------
__global__ __launch_bounds__(256, 2) void gemm_hw_kernel(
    const float* __restrict__ A, const float* __restrict__ B) {
    __shared__ __align__(16) float As[2][8][128];
    __shared__ __align__(16) float Bs[2][8][128];

    const int Nn = DIM_OUT, K = DIM_V;
    const int tid = threadIdx.x;
    const int iBase = blockIdx.y * 128;
    const int jBase = blockIdx.x * 128;

    const int lrow = tid >> 1;
    const int kq   = (tid & 1) * 4;
    const float* Aptr = A + (size_t)(iBase + lrow) * K + kq;
    const int bk = tid >> 5;
    const int bn = (tid & 31) * 4;
    const float* Bptr = B + (size_t)bk * Nn + jBase + bn;

    unsigned long long acc[8][4];
    #pragma unroll
    for (int r = 0; r < 8; ++r)
        #pragma unroll
        for (int c = 0; c < 4; ++c) acc[r][c] = 0ull;

    {
        float4 a = *(const float4*)Aptr;
        float4 b = *(const float4*)Bptr;
        As[0][kq + 0][lrow] = a.x; As[0][kq + 1][lrow] = a.y;
        As[0][kq + 2][lrow] = a.z; As[0][kq + 3][lrow] = a.w;
        *(float4*)&Bs[0][bk][bn] = b;
    }
    __syncthreads();

    const int tx = (tid & 15) * 8;
    const int ty = (tid >> 4) * 8;
    int buf = 0;
    const int KT = K / 8;

    for (int kt = 0; kt < KT; ++kt) {
        float4 aN, bN;
        if (kt + 1 < KT) {
            aN = *(const float4*)(Aptr + (size_t)(kt + 1) * 8);
            bN = *(const float4*)(Bptr + (size_t)(kt + 1) * 8 * Nn);
        }
        #pragma unroll
        for (int kk = 0; kk < 8; ++kk) {
            float4 a0 = *(const float4*)&As[buf][kk][ty];
            float4 a1 = *(const float4*)&As[buf][kk][ty + 4];
            ulonglong2 b0 = *(const ulonglong2*)&Bs[buf][kk][tx];
            ulonglong2 b1 = *(const ulonglong2*)&Bs[buf][kk][tx + 4];
            float av[8] = {a0.x, a0.y, a0.z, a0.w, a1.x, a1.y, a1.z, a1.w};
            unsigned long long bv[4] = {b0.x, b0.y, b1.x, b1.y};
            #pragma unroll
            for (int r = 0; r < 8; ++r) {
                unsigned long long aa = pack2(av[r], av[r]);
                #pragma unroll
                for (int c = 0; c < 4; ++c) ffma2(acc[r][c], aa, bv[c]);
            }
        }
        if (kt + 1 < KT) {
            int nb = buf ^ 1;
            As[nb][kq + 0][lrow] = aN.x; As[nb][kq + 1][lrow] = aN.y;
            As[nb][kq + 2][lrow] = aN.z; As[nb][kq + 3][lrow] = aN.w;
            *(float4*)&Bs[nb][bk][bn] = bN;
            __syncthreads();
            buf = nb;
        }
    }

    #pragma unroll
    for (int r = 0; r < 8; ++r) {
        int gi = iBase + ty + r;
        float* dst = g_HW + (size_t)gi * Nn;
        #pragma unroll
        for (int c = 0; c < 4; ++c) {
            int gj = jBase + tx + c * 2;
            float2 v = unpack2(acc[r][c]);
            *(float2*)&dst[gj] = v;
        }
    }
}

// -------- transpose + split: HW [4096,512] -> HW^T fp16 hi/lo [512,4096] --------
__global__ void hw_transpose_split_kernel() {
    __shared__ float tile[32][33];
    const int tx = threadIdx.x, ty = threadIdx.y;
    const int nb = blockIdx.x * 32;
    const int kb = blockIdx.y * 32;
    #pragma unroll
    for (int i = 0; i < 4; ++i) {
        int k = kb + ty + i * 8;
        tile[ty + i * 8][tx] = g_HW[(size_t)k * DIM_OUT + nb + tx];
    }
    __syncthreads();
    #pragma unroll
    for (int i = 0; i < 4; ++i) {
        int n = nb + ty + i * 8;
        int k = kb + tx;
        float v = tile[tx][ty + i * 8];
        __half h = __float2half_rn(v);
        g_HWth[(size_t)n * NN_NODES + k] = h;
        g_HWtl[(size_t)n * NN_NODES + k] = __float2half_rn(v - __half2float(h));
    }
}

extern "C" void kernel_launch(void* const* d_in, const int* in_sizes, int n_in,
                              void* d_out, int out_size) {
    const float* H_v    = (const float*)d_in[0];
    const float* H_e    = (const float*)d_in[1];
    const float* adj_v  = (const float*)d_in[3];
    const float* T      = (const float*)d_in[4];
    const float* weight = (const float*)d_in[5];
    const float* p      = (const float*)d_in[6];
    const float* bias   = (const float*)d_in[7];
    float* out = (float*)d_out;
    (void)in_sizes; (void)n_in;

    cudaFuncSetAttribute(gemm1_mma_kernel,
                         cudaFuncAttributeMaxDynamicSharedMemorySize, SMEM_G1);
    cudaFuncSetAttribute(gemm_out_mma_kernel,
                         cudaFuncAttributeMaxDynamicSharedMemorySize, SMEM_GO);

    // K0: edge scaling vector
    escale_kernel<<<NN_EDGES / 8, dim3(32, 8)>>>(H_e, p);

    // K-split: fragment-permuted fp16 operand prep (depends on K0)
    split_kernel<<<(NN_NODES * NN_EDGES) / (256 * 4), 256>>>(T);

    // K1: HW = H_v @ W
    gemm_hw_kernel<<<dim3(DIM_OUT / 128, NN_NODES / 128), 256>>>(H_v, weight);

    // K2 (4th launch — ncu profiling slot): dominant GEMM, fp16 single-product,
    // permuted fragment loads, 256x128 tiles, triangular, mirrored epilogue
    gemm1_mma_kernel<<<272, 256, SMEM_G1>>>(adj_v);

    // HW transpose+split (indep of gemm1)
    hw_transpose_split_kernel<<<dim3(DIM_OUT / 32, NN_NODES / 32), dim3(32, 8)>>>();

    // A_comb -> fp16
    acomb_split_kernel<<<(size_t)NN_NODES * NN_NODES / (256 * 4), 256>>>();

    // K3: ret = A_comb @ HW + bias (fp16 2-product)
    gemm_out_mma_kernel<<<dim3(DIM_OUT / 128, NN_NODES / 128), 256, SMEM_GO>>>(bias, out);

    const size_t ret_elems = (size_t)NN_NODES * DIM_OUT;
    const size_t he_elems  = (size_t)NN_EDGES * DIM_E;
    if ((size_t)out_size >= ret_elems + he_elems) {
        cudaMemcpyAsync(out + ret_elems, H_e, he_elems * sizeof(float),
                        cudaMemcpyDeviceToDevice);
    }
}

// round 14
// speedup vs baseline: 5.0574x; 1.1129x over previous
#include <cuda_runtime.h>
#include <cuda_bf16.h>
#include <cuda_fp16.h>

// Problem constants
#define NN_NODES 4096
#define NN_EDGES 8192
#define DIM_V    512
#define DIM_OUT  512
#define DIM_E    128
#define KBLKS    (NN_EDGES / 16)   // 512 col-blocks of 16

// ---------------- scratch (device globals; no allocation allowed) ----------------
__device__ float g_e_scale[NN_EDGES];
__device__ float g_HW[(size_t)NN_NODES * DIM_OUT];                //  8 MB fp32
// fragment-permuted fp16 operands for gemm1 (mma.m16n8k16 order)
__device__ __half g_Ah[(size_t)NN_NODES * NN_EDGES];              // 64 MB
__device__ __half g_Bh[(size_t)NN_NODES * NN_EDGES];              // 64 MB
__device__ __half g_Cf[(size_t)NN_NODES * NN_NODES];              // 32 MB (A_comb fp16)
__device__ __half g_HWth[(size_t)DIM_OUT * NN_NODES];             //  4 MB (HW^T fp16)

// ---------------- PTX helpers (non-'a' features only) ----------------
__device__ __forceinline__ unsigned smem_u32(const void* p) {
    unsigned a;
    asm("{ .reg .u64 t; cvta.to.shared.u64 t, %1; cvt.u32.u64 %0, t; }" : "=r"(a) : "l"(p));
    return a;
}
#define CP_ASYNC8(dst, src) \
    asm volatile("cp.async.ca.shared.global [%0], [%1], 8;" :: "r"(dst), "l"(src) : "memory")
#define CP_ASYNC16(dst, src) \
    asm volatile("cp.async.cg.shared.global [%0], [%1], 16;" :: "r"(dst), "l"(src) : "memory")
#define CP_COMMIT() asm volatile("cp.async.commit_group;" ::: "memory")
#define CP_WAIT(n)  asm volatile("cp.async.wait_group %0;" :: "n"(n) : "memory")

#define MMA_FP16(acc, A, B) \
    asm volatile("mma.sync.aligned.m16n8k16.row.col.f32.f16.f16.f32 " \
                 "{%0,%1,%2,%3},{%4,%5,%6,%7},{%8,%9},{%0,%1,%2,%3};" \
                 : "+f"((acc)[0]), "+f"((acc)[1]), "+f"((acc)[2]), "+f"((acc)[3]) \
                 : "r"((A)[0]), "r"((A)[1]), "r"((A)[2]), "r"((A)[3]), \
                   "r"((B)[0]), "r"((B)[1]))

// ---------------- packed f32x2 helpers (SIMT GEMM) ----------------
__device__ __forceinline__ void ffma2(unsigned long long& d,
                                      unsigned long long a,
                                      unsigned long long b) {
    asm("fma.rn.f32x2 %0, %1, %2, %0;" : "+l"(d) : "l"(a), "l"(b));
}
__device__ __forceinline__ unsigned long long pack2(float x, float y) {
    unsigned long long r;
    asm("mov.b64 %0, {%1, %2};" : "=l"(r) : "f"(x), "f"(y));
    return r;
}
__device__ __forceinline__ float2 unpack2(unsigned long long v) {
    float2 f;
    asm("mov.b64 {%0, %1}, %2;" : "=f"(f.x), "=f"(f.y) : "l"(v));
    return f;
}
__device__ __forceinline__ unsigned packh2(__half x, __half y) {
    return (unsigned)__half_as_ushort(x) | ((unsigned)__half_as_ushort(y) << 16);
}
__device__ __forceinline__ unsigned packf2h(float x, float y) {
    return packh2(__float2half_rn(x), __float2half_rn(y));
}

// ---------------- K0: e_scale[e] = dot(H_e[e,:], p) ----------------
__global__ void escale_kernel(const float* __restrict__ He,
                              const float* __restrict__ p) {
    int row  = blockIdx.x * 8 + threadIdx.y;
    int lane = threadIdx.x;
    float4 h  = ((const float4*)(He + (size_t)row * DIM_E))[lane];
    float4 pv = ((const float4*)p)[lane];
    float v = h.x * pv.x + h.y * pv.y + h.z * pv.z + h.w * pv.w;
    #pragma unroll
    for (int o = 16; o; o >>= 1) v += __shfl_xor_sync(0xffffffffu, v, o);
    if (lane == 0) g_e_scale[row] = v;
}

// ------- K-split: fragment-permuted fp16 operands for gemm1 -------
__global__ __launch_bounds__(256) void split_kernel(const float* __restrict__ T) {
    size_t i = ((size_t)blockIdx.x * 256 + threadIdx.x) * 4;
    int row = (int)(i >> 13);
    int c0  = (int)(i & (NN_EDGES - 1));
    float4 t = *(const float4*)(T + i);
    float4 e = *(const float4*)(g_e_scale + c0);

    __half ha0 = __float2half_rn(t.x * e.x), ha1 = __float2half_rn(t.y * e.y);
    __half ha2 = __float2half_rn(t.z * e.z), ha3 = __float2half_rn(t.w * e.w);
    __half hb0 = __float2half_rn(t.x), hb1 = __float2half_rn(t.y);
    __half hb2 = __float2half_rn(t.z), hb3 = __float2half_rn(t.w);

    const int col_blk = c0 >> 4;
    const int k_in = c0 & 15;
    const int kh = k_in >> 3;
    const int t0 = (k_in & 7) >> 1;

    // A
    {
        int row_blk = row >> 4, r_in = row & 15;
        int g = r_in & 7, m = r_in >> 3;
        size_t base = ((size_t)row_blk * KBLKS + col_blk) * 512
                    + (unsigned)((g * 4 + t0) * 16 + (m + 2 * kh) * 4);
        *(unsigned*)((char*)g_Ah + base)      = packh2(ha0, ha1);
        *(unsigned*)((char*)g_Ah + base + 16) = packh2(ha2, ha3);
    }
    // B
    {
        int n_blk = row >> 3, gb = row & 7;
        size_t base = ((size_t)n_blk * KBLKS + col_blk) * 256
                    + (unsigned)((gb * 4 + t0) * 8 + kh * 4);
        *(unsigned*)((char*)g_Bh + base)     = packh2(hb0, hb1);
        *(unsigned*)((char*)g_Bh + base + 8) = packh2(hb2, hb3);
    }
}

// ========== K2: GEMM1 fp16 single product, permuted frags, 256x128 tiles ==========
#define A_TILE_B 16384u
#define B_TILE_B 8192u
#define STAGEB2 (A_TILE_B + B_TILE_B)    // 24576
#define SMEM_G1 73728u                   // >= 2 stages (49152) and TS (67584)
#define OFF2_A(s) ((unsigned)(s) * STAGEB2)
#define OFF2_B(s) (OFF2_A(s) + A_TILE_B)
#define NCH_G1 (NN_EDGES / 32)           // 256
#define TS_LDC 132

__global__ __launch_bounds__(256) void gemm1_mma_kernel(const float* __restrict__ adj_v) {
    extern __shared__ char sm[];
    const unsigned sb = smem_u32(sm);
    const int tid  = threadIdx.x;
    const int warp = tid >> 5;
    const int lane = tid & 31;
    const int g = lane >> 2, t = lane & 3;
    const int wM = (warp >> 1) * 64;
    const int wN = (warp & 1) * 64;
    const int wM16 = (warp >> 1) * 4;
    const int wN8  = (warp & 1) * 8;

    int r = (int)blockIdx.x, BI = 0;
    while (r >= 32 - 2 * BI) { r -= 32 - 2 * BI; ++BI; }
    const int bj = 2 * BI + r;
    const int iBase = BI * 256;
    const int jBase = bj * 128;
    const int iBase16 = BI * 16;
    const int jBase8  = bj * 16;

    float acc[4][8][4];
    #pragma unroll
    for (int mt = 0; mt < 4; ++mt)
        #pragma unroll
        for (int nt = 0; nt < 8; ++nt)
            #pragma unroll
            for (int q = 0; q < 4; ++q) acc[mt][nt][q] = 0.0f;

    auto fill = [&](int chunk, int stg) {
        const int kb16 = chunk * 2;
        #pragma unroll
        for (int i = 0; i < 4; ++i) {
            int c = tid + i * 256;
            int rb = c >> 6, seg = c & 63;
            const char* src = (const char*)g_Ah
                + ((size_t)(iBase16 + rb) * KBLKS + kb16) * 512 + seg * 16;
            CP_ASYNC16(sb + OFF2_A(stg) + rb * 1024u + seg * 16u, src);
        }
        #pragma unroll
        for (int i = 0; i < 2; ++i) {
            int c = tid + i * 256;
            int nb = c >> 5, seg = c & 31;
            const char* src = (const char*)g_Bh
                + ((size_t)(jBase8 + nb) * KBLKS + kb16) * 256 + seg * 16;
            CP_ASYNC16(sb + OFF2_B(stg) + nb * 512u + seg * 16u, src);
        }
        CP_COMMIT();
    };

    fill(0, 0);

    for (int c = 0; c < NCH_G1; ++c) {
        const int s = c & 1;
        if (c + 1 < NCH_G1) { fill(c + 1, s ^ 1); CP_WAIT(1); }
        else                { CP_WAIT(0); }
        __syncthreads();

        const char* pA = sm + OFF2_A(s);
        const char* pB = sm + OFF2_B(s);

        #pragma unroll
        for (int ks = 0; ks < 2; ++ks) {
            unsigned ah[4][4];
            #pragma unroll
            for (int mt = 0; mt < 4; ++mt) {
                uint4 v = *(const uint4*)(pA + (wM16 + mt) * 1024 + ks * 512 + lane * 16);
                ah[mt][0] = v.x; ah[mt][1] = v.y; ah[mt][2] = v.z; ah[mt][3] = v.w;
            }
            #pragma unroll
            for (int nt = 0; nt < 8; ++nt) {
                uint2 bv = *(const uint2*)(pB + (wN8 + nt) * 512 + ks * 256 + lane * 8);
                unsigned bh[2] = {bv.x, bv.y};
                #pragma unroll
                for (int mt = 0; mt < 4; ++mt) {
                    MMA_FP16(acc[mt][nt], ah[mt], bh);
                }
            }
        }
        __syncthreads();
    }

    // -------- direct epilogue -> g_Cf (fp16) for halves on/above diagonal --------
    #pragma unroll
    for (int mt = 0; mt < 4; ++mt) {
        const int roff = wM + mt * 16 + g;
        const int h = roff >> 7;
        if (h == 1 && bj == 2 * BI) continue;
        const int gi0 = iBase + roff;
        const float* adj0 = adj_v + (size_t)gi0 * NN_NODES;
        const float* adj1 = adj0 + 8u * NN_NODES;
        __half* d0 = g_Cf + (size_t)gi0 * NN_NODES;
        __half* d1 = d0 + 8u * NN_NODES;
        #pragma unroll
        for (int nt = 0; nt < 8; ++nt) {
            int gj = jBase + wN + nt * 8 + t * 2;
            float2 a0 = *(const float2*)(adj0 + gj);
            float2 a1 = *(const float2*)(adj1 + gj);
            float o00 = (gi0 == gj)         ? a0.x : 0.5f * a0.x * (acc[mt][nt][0] + 1.0f);
            float o01 = (gi0 == gj + 1)     ? a0.y : 0.5f * a0.y * (acc[mt][nt][1] + 1.0f);
            float o10 = (gi0 + 8 == gj)     ? a1.x : 0.5f * a1.x * (acc[mt][nt][2] + 1.0f);
            float o11 = (gi0 + 8 == gj + 1) ? a1.y : 0.5f * a1.y * (acc[mt][nt][3] + 1.0f);
            *(unsigned*)(d0 + gj) = packf2h(o00, o01);
            *(unsigned*)(d1 + gj) = packf2h(o10, o11);
        }
    }

    // -------- mirrored epilogue per row-half h with 2*BI+h < bj --------
    float* TS = (float*)sm;
    #pragma unroll
    for (int h = 0; h < 2; ++h) {
        if (2 * BI + h >= bj) continue;
        __syncthreads();
        if ((wM >> 7) == h) {
            const int ibase_loc = wM & 127;
            #pragma unroll
            for (int mt = 0; mt < 4; ++mt) {
                int ii = ibase_loc + mt * 16 + g;
                #pragma unroll
                for (int nt = 0; nt < 8; ++nt) {
                    int jj = wN + nt * 8 + t * 2;
                    TS[(jj)     * TS_LDC + ii]     = acc[mt][nt][0];
                    TS[(jj + 1) * TS_LDC + ii]     = acc[mt][nt][1];
                    TS[(jj)     * TS_LDC + ii + 8] = acc[mt][nt][2];
                    TS[(jj + 1) * TS_LDC + ii + 8] = acc[mt][nt][3];
                }
            }
        }
        __syncthreads();

        const int jj  = tid >> 1;
        const int iiB = (tid & 1) * 64;
        const int gj  = jBase + jj;
        const int giB = iBase + h * 128 + iiB;
        const float* adjRow = adj_v + (size_t)gj * NN_NODES + giB;
        __half* dst = g_Cf + (size_t)gj * NN_NODES + giB;
        const float* tsRow = TS + jj * TS_LDC + iiB;
        #pragma unroll
        for (int q = 0; q < 16; ++q) {
            float4 a = *(const float4*)(adjRow + q * 4);
            float4 s4 = *(const float4*)(tsRow + q * 4);
            uint2 o;
            o.x = packf2h(0.5f * a.x * (s4.x + 1.0f), 0.5f * a.y * (s4.y + 1.0f));
            o.y = packf2h(0.5f * a.z * (s4.z + 1.0f), 0.5f * a.w * (s4.w + 1.0f));
            *(uint2*)(dst + q * 4) = o;
        }
    }
}

// ---------------- K3: ret = A_comb @ HW + bias (fp16 single product) ----------------
#define G3_ROWB 72u
#define G3_TILE (128u * G3_ROWB)          // 9216
#define G3_STAGE (2u * G3_TILE)           // 18432
#define SMEM_GO (2u * G3_STAGE)           // 36864
#define OFF3_A(s)  ((unsigned)(s) * G3_STAGE)
#define OFF3_BH(s) (OFF3_A(s) + G3_TILE)

__global__ __launch_bounds__(256) void gemm_out_mma_kernel(
    const float* __restrict__ bias, float* __restrict__ out) {
    extern __shared__ char sm[];
    const unsigned sb = smem_u32(sm);
    const int tid  = threadIdx.x;
    const int warp = tid >> 5;
    const int lane = tid & 31;
    const int g = lane >> 2, t = lane & 3;
    const int iBase = blockIdx.y * 128;
    const int jBase = blockIdx.x * 128;
    const int wM = (warp >> 1) * 32;
    const int wN = (warp & 1) * 64;

    float acc[2][8][4];
    #pragma unroll
    for (int mt = 0; mt < 2; ++mt)
        #pragma unroll
        for (int nt = 0; nt < 8; ++nt)
            #pragma unroll
            for (int q = 0; q < 4; ++q) acc[mt][nt][q] = 0.0f;

    auto fill = [&](int chunk, int stg) {
        const unsigned kb = (unsigned)chunk * 32u;
        #pragma unroll
        for (int i = 0; i < 4; ++i) {
            int c = tid + i * 256;
            int row = c >> 3, sub = c & 7;
            unsigned so = (unsigned)row * G3_ROWB + (unsigned)sub * 8u;
            size_t ga = (size_t)(iBase + row) * NN_NODES + kb + sub * 4;
            size_t gb = (size_t)(jBase + row) * NN_NODES + kb + sub * 4;
            CP_ASYNC8(sb + OFF3_A(stg)  + so, (const char*)(g_Cf + ga));
            CP_ASYNC8(sb + OFF3_BH(stg) + so, (const char*)(g_HWth + gb));
        }
        CP_COMMIT();
    };

    fill(0, 0);
    const int NCH = NN_NODES / 32;

    for (int c = 0; c < NCH; ++c) {
        const int s = c & 1;
        if (c + 1 < NCH) { fill(c + 1, s ^ 1); CP_WAIT(1); }
        else             { CP_WAIT(0); }
        __syncthreads();

        const char* pA  = sm + OFF3_A(s);
        const char* pBH = sm + OFF3_BH(s);

        #pragma unroll
        for (int ks = 0; ks < 2; ++ks) {
            unsigned ah[2][4], bh[8][2];
            const unsigned colb = (unsigned)(ks * 32 + t * 4);
            #pragma unroll
            for (int mt = 0; mt < 2; ++mt) {
                unsigned o0 = (unsigned)(wM + mt * 16 + g) * G3_ROWB + colb;
                unsigned o1 = o0 + 8u * G3_ROWB;
                ah[mt][0] = *(const unsigned*)(pA + o0);
                ah[mt][1] = *(const unsigned*)(pA + o1);
                ah[mt][2] = *(const unsigned*)(pA + o0 + 16u);
                ah[mt][3] = *(const unsigned*)(pA + o1 + 16u);
            }
            #pragma unroll
            for (int nt = 0; nt < 8; ++nt) {
                unsigned ob = (unsigned)(wN + nt * 8 + g) * G3_ROWB + colb;
                bh[nt][0] = *(const unsigned*)(pBH + ob);
                bh[nt][1] = *(const unsigned*)(pBH + ob + 16u);
            }
            #pragma unroll
            for (int mt = 0; mt < 2; ++mt)
                #pragma unroll
                for (int nt = 0; nt < 8; ++nt) {
                    MMA_FP16(acc[mt][nt], ah[mt], bh[nt]);
                }
        }
        __syncthreads();
    }

    #pragma unroll
    for (int mt = 0; mt < 2; ++mt) {
        int gi0 = iBase + wM + mt * 16 + g;
        float* d0 = out + (size_t)gi0 * DIM_OUT;
        float* d1 = d0 + 8u * DIM_OUT;
        #pragma unroll
        for (int nt = 0; nt < 8; ++nt) {
            int gj = jBase + wN + nt * 8 + t * 2;
            float2 bs = *(const float2*)(bias + gj);
            *(float2*)(d0 + gj) = make_float2(acc[mt][nt][0] + bs.x, acc[mt][nt][1] + bs.y);
            *(float2*)(d1 + gj) = make_float2(acc[mt][nt][2] + bs.x, acc[mt][nt][3] + bs.y);
        }
    }
}

// ---------------- SIMT GEMM for HW = H_v @ W ----------------
__global__ __launch_bounds__(256, 2) void gemm_hw_kernel(
    const float* __restrict__ A, const float* __restrict__ B) {
    __shared__ __align__(16) float As[2][8][128];
    __shared__ __align__(16) float Bs[2][8][128];

    const int Nn = DIM_OUT, K = DIM_V;
    const int tid = threadIdx.x;
    const int iBase = blockIdx.y * 128;
    const int jBase = blockIdx.x * 128;

    const int lrow = tid >> 1;
    const int kq   = (tid & 1) * 4;
    const float* Aptr = A + (size_t)(iBase + lrow) * K + kq;
    const int bk = tid >> 5;
    const int bn = (tid & 31) * 4;
    const float* Bptr = B + (size_t)bk * Nn + jBase + bn;

    unsigned long long acc[8][4];
    #pragma unroll
    for (int r = 0; r < 8; ++r)
        #pragma unroll
        for (int c = 0; c < 4; ++c) acc[r][c] = 0ull;

    {
        float4 a = *(const float4*)Aptr;
        float4 b = *(const float4*)Bptr;
        As[0][kq + 0][lrow] = a.x; As[0][kq + 1][lrow] = a.y;
        As[0][kq + 2][lrow] = a.z; As[0][kq + 3][lrow] = a.w;
        *(float4*)&Bs[0][bk][bn] = b;
    }
    __syncthreads();

    const int tx = (tid & 15) * 8;
    const int ty = (tid >> 4) * 8;
    int buf = 0;
    const int KT = K / 8;

    for (int kt = 0; kt < KT; ++kt) {
        float4 aN, bN;
        if (kt + 1 < KT) {
            aN = *(const float4*)(Aptr + (size_t)(kt + 1) * 8);
            bN = *(const float4*)(Bptr + (size_t)(kt + 1) * 8 * Nn);
        }
        #pragma unroll
        for (int kk = 0; kk < 8; ++kk) {
            float4 a0 = *(const float4*)&As[buf][kk][ty];
            float4 a1 = *(const float4*)&As[buf][kk][ty + 4];
            ulonglong2 b0 = *(const ulonglong2*)&Bs[buf][kk][tx];
            ulonglong2 b1 = *(const ulonglong2*)&Bs[buf][kk][tx + 4];
            float av[8] = {a0.x, a0.y, a0.z, a0.w, a1.x, a1.y, a1.z, a1.w};
            unsigned long long bv[4] = {b0.x, b0.y, b1.x, b1.y};
            #pragma unroll
            for (int r = 0; r < 8; ++r) {
                unsigned long long aa = pack2(av[r], av[r]);
                #pragma unroll
                for (int c = 0; c < 4; ++c) ffma2(acc[r][c], aa, bv[c]);
            }
        }
        if (kt + 1 < KT) {
            int nb = buf ^ 1;
            As[nb][kq + 0][lrow] = aN.x; As[nb][kq + 1][lrow] = aN.y;
            As[nb][kq + 2][lrow] = aN.z; As[nb][kq + 3][lrow] = aN.w;
            *(float4*)&Bs[nb][bk][bn] = bN;
            __syncthreads();
            buf = nb;
        }
    }

    #pragma unroll
    for (int r = 0; r < 8; ++r) {
        int gi = iBase + ty + r;
        float* dst = g_HW + (size_t)gi * Nn;
        #pragma unroll
        for (int c = 0; c < 4; ++c) {
            int gj = jBase + tx + c * 2;
            float2 v = unpack2(acc[r][c]);
            *(float2*)&dst[gj] = v;
        }
    }
}

// -------- transpose: HW [4096,512] -> HW^T fp16 [512,4096] --------
__global__ void hw_transpose_split_kernel() {
    __shared__ float tile[32][33];
    const int tx = threadIdx.x, ty = threadIdx.y;
    const int nb = blockIdx.x * 32;
    const int kb = blockIdx.y * 32;
    #pragma unroll
    for (int i = 0; i < 4; ++i) {
        int k = kb + ty + i * 8;
        tile[ty + i * 8][tx] = g_HW[(size_t)k * DIM_OUT + nb + tx];
    }
    __syncthreads();
    #pragma unroll
    for (int i = 0; i < 4; ++i) {
        int n = nb + ty + i * 8;
        int k = kb + tx;
        g_HWth[(size_t)n * NN_NODES + k] = __float2half_rn(tile[tx][ty + i * 8]);
    }
}

extern "C" void kernel_launch(void* const* d_in, const int* in_sizes, int n_in,
                              void* d_out, int out_size) {
    const float* H_v    = (const float*)d_in[0];
    const float* H_e    = (const float*)d_in[1];
    const float* adj_v  = (const float*)d_in[3];
    const float* T      = (const float*)d_in[4];
    const float* weight = (const float*)d_in[5];
    const float* p      = (const float*)d_in[6];
    const float* bias   = (const float*)d_in[7];
    float* out = (float*)d_out;
    (void)in_sizes; (void)n_in;

    cudaFuncSetAttribute(gemm1_mma_kernel,
                         cudaFuncAttributeMaxDynamicSharedMemorySize, SMEM_G1);
    cudaFuncSetAttribute(gemm_out_mma_kernel,
                         cudaFuncAttributeMaxDynamicSharedMemorySize, SMEM_GO);

    // K0: edge scaling vector
    escale_kernel<<<NN_EDGES / 8, dim3(32, 8)>>>(H_e, p);

    // K-split: fragment-permuted fp16 operand prep (depends on K0)
    split_kernel<<<(NN_NODES * NN_EDGES) / (256 * 4), 256>>>(T);

    // K1: HW = H_v @ W
    gemm_hw_kernel<<<dim3(DIM_OUT / 128, NN_NODES / 128), 256>>>(H_v, weight);

    // K2 (4th launch — ncu profiling slot): dominant GEMM, fp16 single-product,
    // permuted frags, 256x128 tiles, triangular, fused fp16 A_comb epilogue
    gemm1_mma_kernel<<<272, 256, SMEM_G1>>>(adj_v);

    // HW transpose -> fp16 (indep of gemm1)
    hw_transpose_split_kernel<<<dim3(DIM_OUT / 32, NN_NODES / 32), dim3(32, 8)>>>();

    // K3: ret = A_comb @ HW + bias (fp16 single product)
    gemm_out_mma_kernel<<<dim3(DIM_OUT / 128, NN_NODES / 128), 256, SMEM_GO>>>(bias, out);

    const size_t ret_elems = (size_t)NN_NODES * DIM_OUT;
    const size_t he_elems  = (size_t)NN_EDGES * DIM_E;
    if ((size_t)out_size >= ret_elems + he_elems) {
        cudaMemcpyAsync(out + ret_elems, H_e, he_elems * sizeof(float),
                        cudaMemcpyDeviceToDevice);
    }
}

// round 16
// speedup vs baseline: 5.4610x; 1.0798x over previous
#include <cuda_runtime.h>
#include <cuda_bf16.h>
#include <cuda_fp16.h>

// Problem constants
#define NN_NODES 4096
#define NN_EDGES 8192
#define DIM_V    512
#define DIM_OUT  512
#define DIM_E    128
#define KBLKS    (NN_EDGES / 16)   // 512 col-blocks of 16

// ---------------- scratch (device globals; no allocation allowed) ----------------
__device__ float g_e_scale[NN_EDGES];
__device__ float g_HW[(size_t)NN_NODES * DIM_OUT];                //  8 MB fp32
// fragment-permuted fp16 operands for gemm1 (mma.m16n8k16 order)
__device__ __half g_Ah[(size_t)NN_NODES * NN_EDGES];              // 64 MB
__device__ __half g_Bh[(size_t)NN_NODES * NN_EDGES];              // 64 MB
__device__ __half g_Cf[(size_t)NN_NODES * NN_NODES];              // 32 MB (A_comb fp16)
__device__ __half g_HWth[(size_t)DIM_OUT * NN_NODES];             //  4 MB (HW^T fp16)
__device__ __half g_Hvh[(size_t)NN_NODES * DIM_V];                //  4 MB (H_v hi)
__device__ __half g_Hvl[(size_t)NN_NODES * DIM_V];                //  4 MB (H_v lo)
__device__ __half g_WT[(size_t)DIM_OUT * DIM_V];                  // 0.5 MB (W^T fp16)

// ---------------- PTX helpers (non-'a' features only) ----------------
__device__ __forceinline__ unsigned smem_u32(const void* p) {
    unsigned a;
    asm("{ .reg .u64 t; cvta.to.shared.u64 t, %1; cvt.u32.u64 %0, t; }" : "=r"(a) : "l"(p));
    return a;
}
#define CP_ASYNC8(dst, src) \
    asm volatile("cp.async.ca.shared.global [%0], [%1], 8;" :: "r"(dst), "l"(src) : "memory")
#define CP_ASYNC16(dst, src) \
    asm volatile("cp.async.cg.shared.global [%0], [%1], 16;" :: "r"(dst), "l"(src) : "memory")
#define CP_COMMIT() asm volatile("cp.async.commit_group;" ::: "memory")
#define CP_WAIT(n)  asm volatile("cp.async.wait_group %0;" :: "n"(n) : "memory")

#define MMA_FP16(acc, A, B) \
    asm volatile("mma.sync.aligned.m16n8k16.row.col.f32.f16.f16.f32 " \
                 "{%0,%1,%2,%3},{%4,%5,%6,%7},{%8,%9},{%0,%1,%2,%3};" \
                 : "+f"((acc)[0]), "+f"((acc)[1]), "+f"((acc)[2]), "+f"((acc)[3]) \
                 : "r"((A)[0]), "r"((A)[1]), "r"((A)[2]), "r"((A)[3]), \
                   "r"((B)[0]), "r"((B)[1]))

__device__ __forceinline__ unsigned packh2(__half x, __half y) {
    return (unsigned)__half_as_ushort(x) | ((unsigned)__half_as_ushort(y) << 16);
}
__device__ __forceinline__ unsigned packf2h(float x, float y) {
    return packh2(__float2half_rn(x), __float2half_rn(y));
}

// ---------------- K0: e_scale[e] = dot(H_e[e,:], p) ----------------
__global__ void escale_kernel(const float* __restrict__ He,
                              const float* __restrict__ p) {
    int row  = blockIdx.x * 8 + threadIdx.y;
    int lane = threadIdx.x;
    float4 h  = ((const float4*)(He + (size_t)row * DIM_E))[lane];
    float4 pv = ((const float4*)p)[lane];
    float v = h.x * pv.x + h.y * pv.y + h.z * pv.z + h.w * pv.w;
    #pragma unroll
    for (int o = 16; o; o >>= 1) v += __shfl_xor_sync(0xffffffffu, v, o);
    if (lane == 0) g_e_scale[row] = v;
}

// ------- K-split v2: coalesced fragment-permuted fp16 operands for gemm1 -------
// CTA loads a 16x256 T tile; each warp writes whole permuted blocks:
// A-block (512B) = one uint4 per lane; B-block (256B) = one uint2 per lane.
#define TSM_LD 260
__global__ __launch_bounds__(256) void split_kernel(const float* __restrict__ T) {
    __shared__ __align__(16) float tile[16][TSM_LD];
    __shared__ __align__(16) float esc[256];
    const int tid = threadIdx.x;
    const int C = blockIdx.x;      // col group of 256
    const int R = blockIdx.y;      // row group of 16
    const int colBase = C * 256;
    const int rowBase = R * 16;

    if (tid < 64)
        *(float4*)(esc + tid * 4) = *(const float4*)(g_e_scale + colBase + tid * 4);
    #pragma unroll
    for (int i = 0; i < 4; ++i) {
        int idx = tid + i * 256;
        int rr = idx >> 6;
        int cc = (idx & 63) * 4;
        *(float4*)&tile[rr][cc] =
            *(const float4*)(T + (size_t)(rowBase + rr) * NN_EDGES + colBase + cc);
    }
    __syncthreads();

    const int warp = tid >> 5, lane = tid & 31;
    const int g = lane >> 2, t = lane & 3;

    // A blocks: 16 per CTA, 2 per warp
    #pragma unroll
    for (int j = 0; j < 2; ++j) {
        int cb = warp * 2 + j;
        int c = cb * 16 + t * 2;
        float e0 = esc[c], e1 = esc[c + 1], e8 = esc[c + 8], e9 = esc[c + 9];
        uint4 u;
        u.x = packf2h(tile[g][c] * e0,         tile[g][c + 1] * e1);
        u.y = packf2h(tile[g + 8][c] * e0,     tile[g + 8][c + 1] * e1);
        u.z = packf2h(tile[g][c + 8] * e8,     tile[g][c + 9] * e9);
        u.w = packf2h(tile[g + 8][c + 8] * e8, tile[g + 8][c + 9] * e9);
        size_t base = ((size_t)R * KBLKS + (C * 16 + cb)) * 512;
        *(uint4*)((char*)g_Ah + base + lane * 16) = u;
    }
    // B blocks: 32 per CTA, 4 per warp
    #pragma unroll
    for (int j = 0; j < 4; ++j) {
        int blk = warp * 4 + j;
        int cb = blk >> 1, nb = blk & 1;
        int c = cb * 16 + t * 2;
        int rr = nb * 8 + g;
        uint2 u;
        u.x = packf2h(tile[rr][c],     tile[rr][c + 1]);
        u.y = packf2h(tile[rr][c + 8], tile[rr][c + 9]);
        size_t base = ((size_t)(R * 2 + nb) * KBLKS + (C * 16 + cb)) * 256;
        *(uint2*)((char*)g_Bh + base + lane * 8) = u;
    }
}

// ------- H_v -> fp16 hi/lo -------
__global__ __launch_bounds__(256) void hv_split_kernel(const float* __restrict__ Hv) {
    size_t i = ((size_t)blockIdx.x * 256 + threadIdx.x) * 4;
    float4 v = *(const float4*)(Hv + i);
    float x[4] = {v.x, v.y, v.z, v.w};
    unsigned long long hh = 0, ll = 0;
    #pragma unroll
    for (int k = 0; k < 4; ++k) {
        __half h = __float2half_rn(x[k]);
        __half l = __float2half_rn(x[k] - __half2float(h));
        hh |= (unsigned long long)__half_as_ushort(h) << (16 * k);
        ll |= (unsigned long long)__half_as_ushort(l) << (16 * k);
    }
    *(unsigned long long*)(g_Hvh + i) = hh;
    *(unsigned long long*)(g_Hvl + i) = ll;
}

// ------- W [512,512] -> W^T fp16 [n][k] -------
__global__ void wt_kernel(const float* __restrict__ W) {
    __shared__ float tile[32][33];
    const int tx = threadIdx.x, ty = threadIdx.y;
    const int nb = blockIdx.x * 32;
    const int kb = blockIdx.y * 32;
    #pragma unroll
    for (int i = 0; i < 4; ++i)
        tile[ty + i * 8][tx] = W[(size_t)(kb + ty + i * 8) * DIM_OUT + nb + tx];
    __syncthreads();
    #pragma unroll
    for (int i = 0; i < 4; ++i)
        g_WT[(size_t)(nb + ty + i * 8) * DIM_V + kb + tx] =
            __float2half_rn(tile[tx][ty + i * 8]);
}

// ========== K2: GEMM1 fp16 single product, permuted frags, 256x128 tiles ==========
#define A_TILE_B 16384u
#define B_TILE_B 8192u
#define STAGEB2 (A_TILE_B + B_TILE_B)    // 24576
#define SMEM_G1 73728u                   // >= 2 stages (49152) and TS (67584)
#define OFF2_A(s) ((unsigned)(s) * STAGEB2)
#define OFF2_B(s) (OFF2_A(s) + A_TILE_B)
#define NCH_G1 (NN_EDGES / 32)           // 256
#define TS_LDC 132

__global__ __launch_bounds__(256) void gemm1_mma_kernel(const float* __restrict__ adj_v) {
    extern __shared__ char sm[];
    const unsigned sb = smem_u32(sm);
    const int tid  = threadIdx.x;
    const int warp = tid >> 5;
    const int lane = tid & 31;
    const int g = lane >> 2, t = lane & 3;
    const int wM = (warp >> 1) * 64;
    const int wN = (warp & 1) * 64;
    const int wM16 = (warp >> 1) * 4;
    const int wN8  = (warp & 1) * 8;

    int r = (int)blockIdx.x, BI = 0;
    while (r >= 32 - 2 * BI) { r -= 32 - 2 * BI; ++BI; }
    const int bj = 2 * BI + r;
    const int iBase = BI * 256;
    const int jBase = bj * 128;
    const int iBase16 = BI * 16;
    const int jBase8  = bj * 16;

    float acc[4][8][4];
    #pragma unroll
    for (int mt = 0; mt < 4; ++mt)
        #pragma unroll
        for (int nt = 0; nt < 8; ++nt)
            #pragma unroll
            for (int q = 0; q < 4; ++q) acc[mt][nt][q] = 0.0f;

    auto fill = [&](int chunk, int stg) {
        const int kb16 = chunk * 2;
        #pragma unroll
        for (int i = 0; i < 4; ++i) {
            int c = tid + i * 256;
            int rb = c >> 6, seg = c & 63;
            const char* src = (const char*)g_Ah
                + ((size_t)(iBase16 + rb) * KBLKS + kb16) * 512 + seg * 16;
            CP_ASYNC16(sb + OFF2_A(stg) + rb * 1024u + seg * 16u, src);
        }
        #pragma unroll
        for (int i = 0; i < 2; ++i) {
            int c = tid + i * 256;
            int nb = c >> 5, seg = c & 31;
            const char* src = (const char*)g_Bh
                + ((size_t)(jBase8 + nb) * KBLKS + kb16) * 256 + seg * 16;
            CP_ASYNC16(sb + OFF2_B(stg) + nb * 512u + seg * 16u, src);
        }
        CP_COMMIT();
    };

    fill(0, 0);

    for (int c = 0; c < NCH_G1; ++c) {
        const int s = c & 1;
        if (c + 1 < NCH_G1) { fill(c + 1, s ^ 1); CP_WAIT(1); }
        else                { CP_WAIT(0); }
        __syncthreads();

        const char* pA = sm + OFF2_A(s);
        const char* pB = sm + OFF2_B(s);

        #pragma unroll
        for (int ks = 0; ks < 2; ++ks) {
            unsigned ah[4][4];
            #pragma unroll
            for (int mt = 0; mt < 4; ++mt) {
                uint4 v = *(const uint4*)(pA + (wM16 + mt) * 1024 + ks * 512 + lane * 16);
                ah[mt][0] = v.x; ah[mt][1] = v.y; ah[mt][2] = v.z; ah[mt][3] = v.w;
            }
            #pragma unroll
            for (int nt = 0; nt < 8; ++nt) {
                uint2 bv = *(const uint2*)(pB + (wN8 + nt) * 512 + ks * 256 + lane * 8);
                unsigned bh[2] = {bv.x, bv.y};
                #pragma unroll
                for (int mt = 0; mt < 4; ++mt) {
                    MMA_FP16(acc[mt][nt], ah[mt], bh);
                }
            }
        }
        __syncthreads();
    }

    // -------- direct epilogue -> g_Cf (fp16) for halves on/above diagonal --------
    #pragma unroll
    for (int mt = 0; mt < 4; ++mt) {
        const int roff = wM + mt * 16 + g;
        const int h = roff >> 7;
        if (h == 1 && bj == 2 * BI) continue;
        const int gi0 = iBase + roff;
        const float* adj0 = adj_v + (size_t)gi0 * NN_NODES;
        const float* adj1 = adj0 + 8u * NN_NODES;
        __half* d0 = g_Cf + (size_t)gi0 * NN_NODES;
        __half* d1 = d0 + 8u * NN_NODES;
        #pragma unroll
        for (int nt = 0; nt < 8; ++nt) {
            int gj = jBase + wN + nt * 8 + t * 2;
            float2 a0 = *(const float2*)(adj0 + gj);
            float2 a1 = *(const float2*)(adj1 + gj);
            float o00 = (gi0 == gj)         ? a0.x : 0.5f * a0.x * (acc[mt][nt][0] + 1.0f);
            float o01 = (gi0 == gj + 1)     ? a0.y : 0.5f * a0.y * (acc[mt][nt][1] + 1.0f);
            float o10 = (gi0 + 8 == gj)     ? a1.x : 0.5f * a1.x * (acc[mt][nt][2] + 1.0f);
            float o11 = (gi0 + 8 == gj + 1) ? a1.y : 0.5f * a1.y * (acc[mt][nt][3] + 1.0f);
            *(unsigned*)(d0 + gj) = packf2h(o00, o01);
            *(unsigned*)(d1 + gj) = packf2h(o10, o11);
        }
    }

    // -------- mirrored epilogue per row-half h with 2*BI+h < bj --------
    float* TS = (float*)sm;
    #pragma unroll
    for (int h = 0; h < 2; ++h) {
        if (2 * BI + h >= bj) continue;
        __syncthreads();
        if ((wM >> 7) == h) {
            const int ibase_loc = wM & 127;
            #pragma unroll
            for (int mt = 0; mt < 4; ++mt) {
                int ii = ibase_loc + mt * 16 + g;
                #pragma unroll
                for (int nt = 0; nt < 8; ++nt) {
                    int jj = wN + nt * 8 + t * 2;
                    TS[(jj)     * TS_LDC + ii]     = acc[mt][nt][0];
                    TS[(jj + 1) * TS_LDC + ii]     = acc[mt][nt][1];
                    TS[(jj)     * TS_LDC + ii + 8] = acc[mt][nt][2];
                    TS[(jj + 1) * TS_LDC + ii + 8] = acc[mt][nt][3];
                }
            }
        }
        __syncthreads();

        const int jj  = tid >> 1;
        const int iiB = (tid & 1) * 64;
        const int gj  = jBase + jj;
        const int giB = iBase + h * 128 + iiB;
        const float* adjRow = adj_v + (size_t)gj * NN_NODES + giB;
        __half* dst = g_Cf + (size_t)gj * NN_NODES + giB;
        const float* tsRow = TS + jj * TS_LDC + iiB;
        #pragma unroll
        for (int q = 0; q < 16; ++q) {
            float4 a = *(const float4*)(adjRow + q * 4);
            float4 s4 = *(const float4*)(tsRow + q * 4);
            uint2 o;
            o.x = packf2h(0.5f * a.x * (s4.x + 1.0f), 0.5f * a.y * (s4.y + 1.0f));
            o.y = packf2h(0.5f * a.z * (s4.z + 1.0f), 0.5f * a.w * (s4.w + 1.0f));
            *(uint2*)(dst + q * 4) = o;
        }
    }
}

// ---------------- shared 72B-row tile geometry ----------------
#define G3_ROWB 72u
#define G3_TILE (128u * G3_ROWB)          // 9216

// ---------------- gemm_hw (tensorized): HW = H_v @ W, 2-product ----------------
#define GH_STAGE (3u * G3_TILE)           // 27648
#define SMEM_GH (2u * GH_STAGE)           // 55296
#define OFFH_A(s)  ((unsigned)(s) * GH_STAGE)
#define OFFH_L(s)  (OFFH_A(s) + G3_TILE)
#define OFFH_B(s)  (OFFH_A(s) + 2u * G3_TILE)

__global__ __launch_bounds__(256) void gemm_hw_mma_kernel() {
    extern __shared__ char sm[];
    const unsigned sb = smem_u32(sm);
    const int tid  = threadIdx.x;
    const int warp = tid >> 5;
    const int lane = tid & 31;
    const int g = lane >> 2, t = lane & 3;
    const int iBase = blockIdx.y * 128;   // M over 4096
    const int jBase = blockIdx.x * 128;   // N over 512
    const int wM = (warp >> 1) * 32;
    const int wN = (warp & 1) * 64;

    float acc[2][8][4];
    #pragma unroll
    for (int mt = 0; mt < 2; ++mt)
        #pragma unroll
        for (int nt = 0; nt < 8; ++nt)
            #pragma unroll
            for (int q = 0; q < 4; ++q) acc[mt][nt][q] = 0.0f;

    auto fill = [&](int chunk, int stg) {
        const unsigned kb = (unsigned)chunk * 32u;
        #pragma unroll
        for (int i = 0; i < 4; ++i) {
            int c = tid + i * 256;
            int row = c >> 3, sub = c & 7;
            unsigned so = (unsigned)row * G3_ROWB + (unsigned)sub * 8u;
            size_t ga = (size_t)(iBase + row) * DIM_V + kb + sub * 4;
            size_t gb = (size_t)(jBase + row) * DIM_V + kb + sub * 4;
            CP_ASYNC8(sb + OFFH_A(stg) + so, (const char*)(g_Hvh + ga));
            CP_ASYNC8(sb + OFFH_L(stg) + so, (const char*)(g_Hvl + ga));
            CP_ASYNC8(sb + OFFH_B(stg) + so, (const char*)(g_WT + gb));
        }
        CP_COMMIT();
    };

    fill(0, 0);
    const int NCH = DIM_V / 32;   // 16

    for (int c = 0; c < NCH; ++c) {
        const int s = c & 1;
        if (c + 1 < NCH) { fill(c + 1, s ^ 1); CP_WAIT(1); }
        else             { CP_WAIT(0); }
        __syncthreads();

        const char* pA = sm + OFFH_A(s);
        const char* pL = sm + OFFH_L(s);
        const char* pB = sm + OFFH_B(s);

        #pragma unroll
        for (int ks = 0; ks < 2; ++ks) {
            unsigned ah[2][4], al[2][4], bh[8][2];
            const unsigned colb = (unsigned)(ks * 32 + t * 4);
            #pragma unroll
            for (int mt = 0; mt < 2; ++mt) {
                unsigned o0 = (unsigned)(wM + mt * 16 + g) * G3_ROWB + colb;
                unsigned o1 = o0 + 8u * G3_ROWB;
                ah[mt][0] = *(const unsigned*)(pA + o0);
                ah[mt][1] = *(const unsigned*)(pA + o1);
                ah[mt][2] = *(const unsigned*)(pA + o0 + 16u);
                ah[mt][3] = *(const unsigned*)(pA + o1 + 16u);
                al[mt][0] = *(const unsigned*)(pL + o0);
                al[mt][1] = *(const unsigned*)(pL + o1);
                al[mt][2] = *(const unsigned*)(pL + o0 + 16u);
                al[mt][3] = *(const unsigned*)(pL + o1 + 16u);
            }
            #pragma unroll
            for (int nt = 0; nt < 8; ++nt) {
                unsigned ob = (unsigned)(wN + nt * 8 + g) * G3_ROWB + colb;
                bh[nt][0] = *(const unsigned*)(pB + ob);
                bh[nt][1] = *(const unsigned*)(pB + ob + 16u);
            }
            #pragma unroll
            for (int mt = 0; mt < 2; ++mt)
                #pragma unroll
                for (int nt = 0; nt < 8; ++nt) {
                    MMA_FP16(acc[mt][nt], ah[mt], bh[nt]);
                    MMA_FP16(acc[mt][nt], al[mt], bh[nt]);
                }
        }
        __syncthreads();
    }

    #pragma unroll
    for (int mt = 0; mt < 2; ++mt) {
        int gi0 = iBase + wM + mt * 16 + g;
        float* d0 = g_HW + (size_t)gi0 * DIM_OUT;
        float* d1 = d0 + 8u * DIM_OUT;
        #pragma unroll
        for (int nt = 0; nt < 8; ++nt) {
            int gj = jBase + wN + nt * 8 + t * 2;
            *(float2*)(d0 + gj) = make_float2(acc[mt][nt][0], acc[mt][nt][1]);
            *(float2*)(d1 + gj) = make_float2(acc[mt][nt][2], acc[mt][nt][3]);
        }
    }
}

// ---------------- K3: ret = A_comb @ HW + bias (fp16 single product) ----------------
#define G3_STAGE (2u * G3_TILE)           // 18432
#define SMEM_GO (2u * G3_STAGE)           // 36864
#define OFF3_A(s)  ((unsigned)(s) * G3_STAGE)
#define OFF3_BH(s) (OFF3_A(s) + G3_TILE)

__global__ __launch_bounds__(256) void gemm_out_mma_kernel(
    const float* __restrict__ bias, float* __restrict__ out) {
    extern __shared__ char sm[];
    const unsigned sb = smem_u32(sm);
    const int tid  = threadIdx.x;
    const int warp = tid >> 5;
    const int lane = tid & 31;
    const int g = lane >> 2, t = lane & 3;
    const int iBase = blockIdx.y * 128;
    const int jBase = blockIdx.x * 128;
    const int wM = (warp >> 1) * 32;
    const int wN = (warp & 1) * 64;

    float acc[2][8][4];
    #pragma unroll
    for (int mt = 0; mt < 2; ++mt)
        #pragma unroll
        for (int nt = 0; nt < 8; ++nt)
            #pragma unroll
            for (int q = 0; q < 4; ++q) acc[mt][nt][q] = 0.0f;

    auto fill = [&](int chunk, int stg) {
        const unsigned kb = (unsigned)chunk * 32u;
        #pragma unroll
        for (int i = 0; i < 4; ++i) {
            int c = tid + i * 256;
            int row = c >> 3, sub = c & 7;
            unsigned so = (unsigned)row * G3_ROWB + (unsigned)sub * 8u;
            size_t ga = (size_t)(iBase + row) * NN_NODES + kb + sub * 4;
            size_t gb = (size_t)(jBase + row) * NN_NODES + kb + sub * 4;
            CP_ASYNC8(sb + OFF3_A(stg)  + so, (const char*)(g_Cf + ga));
            CP_ASYNC8(sb + OFF3_BH(stg) + so, (const char*)(g_HWth + gb));
        }
        CP_COMMIT();
    };

    fill(0, 0);
    const int NCH = NN_NODES / 32;

    for (int c = 0; c < NCH; ++c) {
        const int s = c & 1;
        if (c + 1 < NCH) { fill(c + 1, s ^ 1); CP_WAIT(1); }
        else             { CP_WAIT(0); }
        __syncthreads();

        const char* pA  = sm + OFF3_A(s);
        const char* pBH = sm + OFF3_BH(s);

        #pragma unroll
        for (int ks = 0; ks < 2; ++ks) {
            unsigned ah[2][4], bh[8][2];
            const unsigned colb = (unsigned)(ks * 32 + t * 4);
            #pragma unroll
            for (int mt = 0; mt < 2; ++mt) {
                unsigned o0 = (unsigned)(wM + mt * 16 + g) * G3_ROWB + colb;
                unsigned o1 = o0 + 8u * G3_ROWB;
                ah[mt][0] = *(const unsigned*)(pA + o0);
                ah[mt][1] = *(const unsigned*)(pA + o1);
                ah[mt][2] = *(const unsigned*)(pA + o0 + 16u);
                ah[mt][3] = *(const unsigned*)(pA + o1 + 16u);
            }
            #pragma unroll
            for (int nt = 0; nt < 8; ++nt) {
                unsigned ob = (unsigned)(wN + nt * 8 + g) * G3_ROWB + colb;
                bh[nt][0] = *(const unsigned*)(pBH + ob);
                bh[nt][1] = *(const unsigned*)(pBH + ob + 16u);
            }
            #pragma unroll
            for (int mt = 0; mt < 2; ++mt)
                #pragma unroll
                for (int nt = 0; nt < 8; ++nt) {
                    MMA_FP16(acc[mt][nt], ah[mt], bh[nt]);
                }
        }
        __syncthreads();
    }

    #pragma unroll
    for (int mt = 0; mt < 2; ++mt) {
        int gi0 = iBase + wM + mt * 16 + g;
        float* d0 = out + (size_t)gi0 * DIM_OUT;
        float* d1 = d0 + 8u * DIM_OUT;
        #pragma unroll
        for (int nt = 0; nt < 8; ++nt) {
            int gj = jBase + wN + nt * 8 + t * 2;
            float2 bs = *(const float2*)(bias + gj);
            *(float2*)(d0 + gj) = make_float2(acc[mt][nt][0] + bs.x, acc[mt][nt][1] + bs.y);
            *(float2*)(d1 + gj) = make_float2(acc[mt][nt][2] + bs.x, acc[mt][nt][3] + bs.y);
        }
    }
}

// -------- transpose: HW [4096,512] -> HW^T fp16 [512,4096] --------
__global__ void hw_transpose_split_kernel() {
    __shared__ float tile[32][33];
    const int tx = threadIdx.x, ty = threadIdx.y;
    const int nb = blockIdx.x * 32;
    const int kb = blockIdx.y * 32;
    #pragma unroll
    for (int i = 0; i < 4; ++i) {
        int k = kb + ty + i * 8;
        tile[ty + i * 8][tx] = g_HW[(size_t)k * DIM_OUT + nb + tx];
    }
    __syncthreads();
    #pragma unroll
    for (int i = 0; i < 4; ++i) {
        int n = nb + ty + i * 8;
        int k = kb + tx;
        g_HWth[(size_t)n * NN_NODES + k] = __float2half_rn(tile[tx][ty + i * 8]);
    }
}

extern "C" void kernel_launch(void* const* d_in, const int* in_sizes, int n_in,
                              void* d_out, int out_size) {
    const float* H_v    = (const float*)d_in[0];
    const float* H_e    = (const float*)d_in[1];
    const float* adj_v  = (const float*)d_in[3];
    const float* T      = (const float*)d_in[4];
    const float* weight = (const float*)d_in[5];
    const float* p      = (const float*)d_in[6];
    const float* bias   = (const float*)d_in[7];
    float* out = (float*)d_out;
    (void)in_sizes; (void)n_in;

    cudaFuncSetAttribute(gemm1_mma_kernel,
                         cudaFuncAttributeMaxDynamicSharedMemorySize, SMEM_G1);
    cudaFuncSetAttribute(gemm_out_mma_kernel,
                         cudaFuncAttributeMaxDynamicSharedMemorySize, SMEM_GO);
    cudaFuncSetAttribute(gemm_hw_mma_kernel,
                         cudaFuncAttributeMaxDynamicSharedMemorySize, SMEM_GH);

    // K0: edge scaling vector
    escale_kernel<<<NN_EDGES / 8, dim3(32, 8)>>>(H_e, p);

    // K-split v2: coalesced fragment-permuted fp16 operand prep (depends on K0)
    split_kernel<<<dim3(NN_EDGES / 256, NN_NODES / 16), 256>>>(T);

    // H_v -> fp16 hi/lo (independent)
    hv_split_kernel<<<(NN_NODES * DIM_V) / (256 * 4), 256>>>(H_v);

    // K2 (4th launch — ncu profiling slot): dominant GEMM
    gemm1_mma_kernel<<<272, 256, SMEM_G1>>>(adj_v);

    // W^T fp16, then HW = H_v @ W on tensor cores, then HW^T fp16
    wt_kernel<<<dim3(DIM_OUT / 32, DIM_V / 32), dim3(32, 8)>>>(weight);
    gemm_hw_mma_kernel<<<dim3(DIM_OUT / 128, NN_NODES / 128), 256, SMEM_GH>>>();
    hw_transpose_split_kernel<<<dim3(DIM_OUT / 32, NN_NODES / 32), dim3(32, 8)>>>();

    // K3: ret = A_comb @ HW + bias (fp16 single product)
    gemm_out_mma_kernel<<<dim3(DIM_OUT / 128, NN_NODES / 128), 256, SMEM_GO>>>(bias, out);

    const size_t ret_elems = (size_t)NN_NODES * DIM_OUT;
    const size_t he_elems  = (size_t)NN_EDGES * DIM_E;
    if ((size_t)out_size >= ret_elems + he_elems) {
        cudaMemcpyAsync(out + ret_elems, H_e, he_elems * sizeof(float),
                        cudaMemcpyDeviceToDevice);
    }
}